// round 1
// baseline (speedup 1.0000x reference)
#include <cuda_runtime.h>
#include <math.h>

// Problem constants
#define Hh   768
#define Lc   2
#define Vc   32000
#define Bc   128
#define Tc   64
#define Sc   32
#define G4   (4*Hh)   // 3072

// ---------------- scratch (device globals; no allocations allowed) ----------
__device__ __align__(128) float g_xs[Tc*Bc*Hh];     // gathered target embeddings [t][b][h]
__device__ __align__(128) float g_G0[(size_t)Tc*Bc*G4]; // precomputed layer0 input gates (+biases)
__device__ __align__(128) float g_h0[2][Bc*Hh];     // layer0 hidden ping-pong
__device__ __align__(128) float g_h1[2][Bc*Hh];     // layer1 hidden ping-pong
__device__ __align__(128) float g_c0[Bc*Hh];
__device__ __align__(128) float g_c1[Bc*Hh];
__device__ __align__(128) float g_ys[Tc*Bc*Hh];     // layer1 outputs [t][b][h]

// ---------------- f32x2 packed math helpers (sm_103a FFMA2 path) ------------
__device__ __forceinline__ unsigned long long pack2(float x, float y) {
    unsigned long long r;
    unsigned lo = __float_as_uint(x), hi = __float_as_uint(y);
    asm("mov.b64 %0, {%1, %2};" : "=l"(r) : "r"(lo), "r"(hi));
    return r;
}
__device__ __forceinline__ float2 unpack2(unsigned long long v) {
    unsigned lo, hi;
    asm("mov.b64 {%0, %1}, %2;" : "=r"(lo), "=r"(hi) : "l"(v));
    return make_float2(__uint_as_float(lo), __uint_as_float(hi));
}
__device__ __forceinline__ void fma2(unsigned long long& c, unsigned long long a, unsigned long long b) {
    asm("fma.rn.f32x2 %0, %1, %2, %3;" : "=l"(c) : "l"(a), "l"(b), "l"(c));
}

// ---------------- init: gather embeddings, init h/c ------------------------
__global__ void init_kernel(const int* __restrict__ src, const int* __restrict__ trg,
                            const float* __restrict__ bert, const float* __restrict__ emb) {
    int idx = blockIdx.x * blockDim.x + threadIdx.x;
    if (idx < Tc*Bc*Hh) {
        int h = idx % Hh;
        int m = idx / Hh;          // m = t*Bc + b
        int b = m % Bc;
        int t = m / Bc;
        g_xs[idx] = emb[(size_t)trg[b*Tc + t] * Hh + h];
    }
    if (idx < Bc*Hh) {
        int b = idx / Hh, h = idx % Hh;
        float v = bert[(size_t)src[b*Sc] * Hh + h];
        g_h0[0][idx] = v;
        g_h1[0][idx] = v;
        g_c0[idx] = 0.f;
        g_c1[idx] = 0.f;
    }
}

// ---------------- generic NT GEMM: C = A @ W^T (+bias), 128x128x16 tile -----
// MODE 0: A = g_xs [8192 x 768], W = W_ih[0] [3072 x 768], bias1+bias2, C = g_G0 row-major
// MODE 1: A = g_ys [8192 x 768], W = W_out [32000 x 768], bias1,        C = out[b][t][v]
template<int MODE>
__global__ __launch_bounds__(256) void gemm_nt(const float* __restrict__ W,
                                               const float* __restrict__ bias1,
                                               const float* __restrict__ bias2,
                                               float* __restrict__ Cout) {
    const float* __restrict__ A = (MODE == 0) ? g_xs : g_ys;
    const int m0 = blockIdx.y * 128;
    const int n0 = blockIdx.x * 128;
    __shared__ __align__(16) float As[16][128];
    __shared__ __align__(16) float Bs[16][128];
    const int tid = threadIdx.x;
    const int tm0 = (tid >> 4) * 8;     // 8 rows per thread (4 packed pairs)
    const int tn0 = (tid & 15) * 8;     // 8 cols per thread

    unsigned long long acc2[4][8];
    #pragma unroll
    for (int i = 0; i < 4; i++)
        #pragma unroll
        for (int j = 0; j < 8; j++) acc2[i][j] = 0ull;

    for (int kt = 0; kt < Hh/16; ++kt) {
        #pragma unroll
        for (int q = 0; q < 2; ++q) {
            int ff  = tid + q*256;
            int row = ff >> 2;
            int c4  = (ff & 3) * 4;
            float4 av = *reinterpret_cast<const float4*>(&A[(size_t)(m0+row)*Hh + kt*16 + c4]);
            float4 bv = *reinterpret_cast<const float4*>(&W[(size_t)(n0+row)*Hh + kt*16 + c4]);
            As[c4+0][row]=av.x; As[c4+1][row]=av.y; As[c4+2][row]=av.z; As[c4+3][row]=av.w;
            Bs[c4+0][row]=bv.x; Bs[c4+1][row]=bv.y; Bs[c4+2][row]=bv.z; Bs[c4+3][row]=bv.w;
        }
        __syncthreads();
        #pragma unroll
        for (int k = 0; k < 16; ++k) {
            unsigned long long a2[4];
            const unsigned long long* ap = reinterpret_cast<const unsigned long long*>(&As[k][tm0]);
            #pragma unroll
            for (int i = 0; i < 4; i++) a2[i] = ap[i];
            float4 bv0 = *reinterpret_cast<const float4*>(&Bs[k][tn0]);
            float4 bv1 = *reinterpret_cast<const float4*>(&Bs[k][tn0+4]);
            unsigned long long b2[8];
            b2[0]=pack2(bv0.x,bv0.x); b2[1]=pack2(bv0.y,bv0.y);
            b2[2]=pack2(bv0.z,bv0.z); b2[3]=pack2(bv0.w,bv0.w);
            b2[4]=pack2(bv1.x,bv1.x); b2[5]=pack2(bv1.y,bv1.y);
            b2[6]=pack2(bv1.z,bv1.z); b2[7]=pack2(bv1.w,bv1.w);
            #pragma unroll
            for (int i = 0; i < 4; i++)
                #pragma unroll
                for (int j = 0; j < 8; j++) fma2(acc2[i][j], a2[i], b2[j]);
        }
        __syncthreads();
    }

    float bias[8];
    #pragma unroll
    for (int j = 0; j < 8; j++) {
        float bb = bias1[n0 + tn0 + j];
        if (MODE == 0) bb += bias2[n0 + tn0 + j];
        bias[j] = bb;
    }

    #pragma unroll
    for (int i = 0; i < 4; i++) {
        float lo[8], hi[8];
        #pragma unroll
        for (int j = 0; j < 8; j++) {
            float2 u = unpack2(acc2[i][j]);
            lo[j] = u.x + bias[j];
            hi[j] = u.y + bias[j];
        }
        const int mlo = m0 + tm0 + 2*i;
        const int mhi = mlo + 1;
        if (MODE == 0) {
            float* dlo = &g_G0[(size_t)mlo * G4 + n0 + tn0];
            float* dhi = &g_G0[(size_t)mhi * G4 + n0 + tn0];
            *reinterpret_cast<float4*>(dlo)     = make_float4(lo[0],lo[1],lo[2],lo[3]);
            *reinterpret_cast<float4*>(dlo + 4) = make_float4(lo[4],lo[5],lo[6],lo[7]);
            *reinterpret_cast<float4*>(dhi)     = make_float4(hi[0],hi[1],hi[2],hi[3]);
            *reinterpret_cast<float4*>(dhi + 4) = make_float4(hi[4],hi[5],hi[6],hi[7]);
        } else {
            // m = t*Bc + b ; out[b][t][v]
            int blo = mlo & (Bc-1), tlo = mlo >> 7;
            int bhi = mhi & (Bc-1), thi = mhi >> 7;
            float* dlo = &Cout[((size_t)blo * Tc + tlo) * Vc + n0 + tn0];
            float* dhi = &Cout[((size_t)bhi * Tc + thi) * Vc + n0 + tn0];
            *reinterpret_cast<float4*>(dlo)     = make_float4(lo[0],lo[1],lo[2],lo[3]);
            *reinterpret_cast<float4*>(dlo + 4) = make_float4(lo[4],lo[5],lo[6],lo[7]);
            *reinterpret_cast<float4*>(dhi)     = make_float4(hi[0],hi[1],hi[2],hi[3]);
            *reinterpret_cast<float4*>(dhi + 4) = make_float4(hi[4],hi[5],hi[6],hi[7]);
        }
    }
}

// ---------------- per-timestep, per-layer LSTM step -------------------------
// Tile: all 128 batch rows x (4 gates x 8 h-columns), K = 768. grid = 96 CTAs.
// LAYER 0: gates = g_G0[t] + h0_prev @ Whh0^T                  (1 GEMM)
// LAYER 1: gates = h0_new @ Wih1^T + h1_prev @ Whh1^T + biases (2 GEMMs)
template<int LAYER>
__global__ __launch_bounds__(256) void lstm_step(int t,
                                                 const float* __restrict__ Wih_l,
                                                 const float* __restrict__ Whh_l,
                                                 const float* __restrict__ bih_l,
                                                 const float* __restrict__ bhh_l) {
    const int rd = t & 1, wr = rd ^ 1;
    const int h0c = blockIdx.x * 8;
    __shared__ __align__(16) float As[16][128];
    __shared__ __align__(16) float Ws[16][32];
    __shared__ float gsh[128][33];
    const int tid = threadIdx.x;
    const int tm0 = (tid >> 4) * 8;
    const int tn0 = (tid & 15) * 2;

    unsigned long long acc2[4][2];
    acc2[0][0]=0ull; acc2[0][1]=0ull; acc2[1][0]=0ull; acc2[1][1]=0ull;
    acc2[2][0]=0ull; acc2[2][1]=0ull; acc2[3][0]=0ull; acc2[3][1]=0ull;

    const int NMAT = (LAYER == 0) ? 1 : 2;
    for (int mm = 0; mm < NMAT; ++mm) {
        const float* Ap = (LAYER == 0) ? g_h0[rd] : (mm == 0 ? g_h0[wr] : g_h1[rd]);
        const float* Wp = (LAYER == 0) ? Whh_l   : (mm == 0 ? Wih_l    : Whh_l);
        for (int kt = 0; kt < Hh/16; ++kt) {
            __syncthreads();
            #pragma unroll
            for (int q = 0; q < 2; ++q) {
                int ff  = tid + q*256;
                int row = ff >> 2;
                int c4  = (ff & 3) * 4;
                float4 av = *reinterpret_cast<const float4*>(&Ap[(size_t)row*Hh + kt*16 + c4]);
                As[c4+0][row]=av.x; As[c4+1][row]=av.y; As[c4+2][row]=av.z; As[c4+3][row]=av.w;
            }
            if (tid < 128) {
                int row = tid >> 2;                 // 0..31 tile column
                int c4  = (tid & 3) * 4;
                int wrow = (row >> 3) * Hh + h0c + (row & 7);  // gate*H + h
                float4 wv = *reinterpret_cast<const float4*>(&Wp[(size_t)wrow*Hh + kt*16 + c4]);
                Ws[c4+0][row]=wv.x; Ws[c4+1][row]=wv.y; Ws[c4+2][row]=wv.z; Ws[c4+3][row]=wv.w;
            }
            __syncthreads();
            #pragma unroll
            for (int k = 0; k < 16; ++k) {
                unsigned long long a2[4];
                const unsigned long long* ap = reinterpret_cast<const unsigned long long*>(&As[k][tm0]);
                #pragma unroll
                for (int i = 0; i < 4; i++) a2[i] = ap[i];
                float b0 = Ws[k][tn0], b1 = Ws[k][tn0+1];
                unsigned long long bb0 = pack2(b0, b0);
                unsigned long long bb1 = pack2(b1, b1);
                #pragma unroll
                for (int i = 0; i < 4; i++) {
                    fma2(acc2[i][0], a2[i], bb0);
                    fma2(acc2[i][1], a2[i], bb1);
                }
            }
        }
    }
    __syncthreads();
    #pragma unroll
    for (int i = 0; i < 4; i++) {
        float2 u0 = unpack2(acc2[i][0]);
        float2 u1 = unpack2(acc2[i][1]);
        gsh[tm0+2*i  ][tn0  ] = u0.x;
        gsh[tm0+2*i+1][tn0  ] = u0.y;
        gsh[tm0+2*i  ][tn0+1] = u1.x;
        gsh[tm0+2*i+1][tn0+1] = u1.y;
    }
    __syncthreads();

    float* cbuf = (LAYER == 0) ? g_c0 : g_c1;
    float* hbuf = (LAYER == 0) ? g_h0[wr] : g_h1[wr];
    for (int e = tid; e < 1024; e += 256) {
        int b = e >> 3, j = e & 7;
        float gi = gsh[b][j], gf = gsh[b][8+j], gg = gsh[b][16+j], go = gsh[b][24+j];
        if (LAYER == 0) {
            size_t base = (size_t)(t*Bc + b) * G4 + h0c + j;
            gi += g_G0[base];
            gf += g_G0[base +   Hh];
            gg += g_G0[base + 2*Hh];
            go += g_G0[base + 3*Hh];
        } else {
            gi += bih_l[       h0c+j] + bhh_l[       h0c+j];
            gf += bih_l[  Hh + h0c+j] + bhh_l[  Hh + h0c+j];
            gg += bih_l[2*Hh + h0c+j] + bhh_l[2*Hh + h0c+j];
            go += bih_l[3*Hh + h0c+j] + bhh_l[3*Hh + h0c+j];
        }
        int ci = b*Hh + h0c + j;
        float si = 1.f / (1.f + expf(-gi));
        float sf = 1.f / (1.f + expf(-gf));
        float so = 1.f / (1.f + expf(-go));
        float cn = sf * cbuf[ci] + si * tanhf(gg);
        float hn = so * tanhf(cn);
        cbuf[ci] = cn;
        hbuf[ci] = hn;
        if (LAYER == 1) g_ys[(size_t)(t*Bc + b) * Hh + h0c + j] = hn;
    }
}

// ---------------- launch ----------------------------------------------------
extern "C" void kernel_launch(void* const* d_in, const int* in_sizes, int n_in,
                              void* d_out, int out_size) {
    const int*   src   = (const int*)  d_in[0];
    const int*   trg   = (const int*)  d_in[1];
    const float* bert  = (const float*)d_in[2];
    const float* emb   = (const float*)d_in[3];
    const float* W_ih  = (const float*)d_in[4];
    const float* W_hh  = (const float*)d_in[5];
    const float* b_ih  = (const float*)d_in[6];
    const float* b_hh  = (const float*)d_in[7];
    const float* W_out = (const float*)d_in[8];
    const float* b_out = (const float*)d_in[9];
    float* out = (float*)d_out;

    // 1. gather embeddings + init h/c
    init_kernel<<<(Tc*Bc*Hh + 255)/256, 256>>>(src, trg, bert, emb);

    // 2. hoisted layer-0 input GEMM: g_G0 = g_xs @ W_ih[0]^T + (b_ih[0]+b_hh[0])
    gemm_nt<0><<<dim3(G4/128, (Tc*Bc)/128), 256>>>(W_ih, b_ih, b_hh, nullptr);

    // 3. recurrence: 64 timesteps x 2 layers
    const float* Wih1 = W_ih + (size_t)G4 * Hh;
    const float* Whh1 = W_hh + (size_t)G4 * Hh;
    const float* bih1 = b_ih + G4;
    const float* bhh1 = b_hh + G4;
    for (int t = 0; t < Tc; ++t) {
        lstm_step<0><<<Hh/8, 256>>>(t, nullptr, W_hh, nullptr, nullptr);
        lstm_step<1><<<Hh/8, 256>>>(t, Wih1, Whh1, bih1, bhh1);
    }

    // 4. output projection: out[b][t][v] = ys[t][b][:] . W_out[v][:] + b_out[v]
    gemm_nt<1><<<dim3(Vc/128, (Tc*Bc)/128), 256>>>(W_out, b_out, nullptr, out);
}

// round 2
// speedup vs baseline: 1.1063x; 1.1063x over previous
#include <cuda_runtime.h>
#include <math.h>

// Problem constants
#define Hh   768
#define Lc   2
#define Vc   32000
#define Bc   128
#define Tc   64
#define Sc   32
#define G4   (4*Hh)   // 3072

// ---------------- scratch (device globals; no allocations allowed) ----------
__device__ __align__(128) float g_xs[Tc*Bc*Hh];         // gathered target embeddings [t][b][h]
__device__ __align__(128) float g_G0[(size_t)Tc*Bc*G4]; // precomputed layer0 input gates (+biases)
__device__ __align__(128) float g_h0[2][Bc*Hh];         // layer0 hidden ping-pong
__device__ __align__(128) float g_h1[2][Bc*Hh];         // layer1 hidden ping-pong
__device__ __align__(128) float g_c0[Bc*Hh];
__device__ __align__(128) float g_c1[Bc*Hh];
__device__ __align__(128) float g_p1[2][Bc*G4];         // layer1 input-gate partials (pipeline)
__device__ __align__(128) float g_ys[Tc*Bc*Hh];         // layer1 outputs [t][b][h]

// ---------------- f32x2 packed math helpers (sm_103a FFMA2 path) ------------
__device__ __forceinline__ unsigned long long pack2(float x, float y) {
    unsigned long long r;
    unsigned lo = __float_as_uint(x), hi = __float_as_uint(y);
    asm("mov.b64 %0, {%1, %2};" : "=l"(r) : "r"(lo), "r"(hi));
    return r;
}
__device__ __forceinline__ float2 unpack2(unsigned long long v) {
    unsigned lo, hi;
    asm("mov.b64 {%0, %1}, %2;" : "=r"(lo), "=r"(hi) : "l"(v));
    return make_float2(__uint_as_float(lo), __uint_as_float(hi));
}
__device__ __forceinline__ void fma2(unsigned long long& c, unsigned long long a, unsigned long long b) {
    asm("fma.rn.f32x2 %0, %1, %2, %3;" : "=l"(c) : "l"(a), "l"(b), "l"(c));
}

// ---------------- init: gather embeddings, init h/c ------------------------
__global__ void init_kernel(const int* __restrict__ src, const int* __restrict__ trg,
                            const float* __restrict__ bert, const float* __restrict__ emb) {
    int idx = blockIdx.x * blockDim.x + threadIdx.x;
    if (idx < Tc*Bc*Hh) {
        int h = idx % Hh;
        int m = idx / Hh;          // m = t*Bc + b
        int b = m % Bc;
        int t = m / Bc;
        g_xs[idx] = emb[(size_t)trg[b*Tc + t] * Hh + h];
    }
    if (idx < Bc*Hh) {
        int b = idx / Hh, h = idx % Hh;
        float v = bert[(size_t)src[b*Sc] * Hh + h];
        g_h0[0][idx] = v;
        g_h1[0][idx] = v;
        g_c0[idx] = 0.f;
        g_c1[idx] = 0.f;
    }
}

// ---------------- generic NT GEMM: C = A @ W^T (+bias), 128x128x16 tile -----
// MODE 0: A = g_xs [8192 x 768], W = W_ih[0] [3072 x 768], bias1+bias2, C = g_G0 row-major
// MODE 1: A = g_ys [8192 x 768], W = W_out [32000 x 768], bias1,        C = out[b][t][v]
template<int MODE>
__global__ __launch_bounds__(256) void gemm_nt(const float* __restrict__ W,
                                               const float* __restrict__ bias1,
                                               const float* __restrict__ bias2,
                                               float* __restrict__ Cout) {
    const float* __restrict__ A = (MODE == 0) ? g_xs : g_ys;
    const int m0 = blockIdx.y * 128;
    const int n0 = blockIdx.x * 128;
    __shared__ __align__(16) float As[16][128];
    __shared__ __align__(16) float Bs[16][128];
    const int tid = threadIdx.x;
    const int tm0 = (tid >> 4) * 8;     // 8 rows per thread (4 packed pairs)
    const int tn0 = (tid & 15) * 8;     // 8 cols per thread

    unsigned long long acc2[4][8];
    #pragma unroll
    for (int i = 0; i < 4; i++)
        #pragma unroll
        for (int j = 0; j < 8; j++) acc2[i][j] = 0ull;

    for (int kt = 0; kt < Hh/16; ++kt) {
        #pragma unroll
        for (int q = 0; q < 2; ++q) {
            int ff  = tid + q*256;
            int row = ff >> 2;
            int c4  = (ff & 3) * 4;
            float4 av = *reinterpret_cast<const float4*>(&A[(size_t)(m0+row)*Hh + kt*16 + c4]);
            float4 bv = *reinterpret_cast<const float4*>(&W[(size_t)(n0+row)*Hh + kt*16 + c4]);
            As[c4+0][row]=av.x; As[c4+1][row]=av.y; As[c4+2][row]=av.z; As[c4+3][row]=av.w;
            Bs[c4+0][row]=bv.x; Bs[c4+1][row]=bv.y; Bs[c4+2][row]=bv.z; Bs[c4+3][row]=bv.w;
        }
        __syncthreads();
        #pragma unroll
        for (int k = 0; k < 16; ++k) {
            unsigned long long a2[4];
            const unsigned long long* ap = reinterpret_cast<const unsigned long long*>(&As[k][tm0]);
            #pragma unroll
            for (int i = 0; i < 4; i++) a2[i] = ap[i];
            float4 bv0 = *reinterpret_cast<const float4*>(&Bs[k][tn0]);
            float4 bv1 = *reinterpret_cast<const float4*>(&Bs[k][tn0+4]);
            unsigned long long b2[8];
            b2[0]=pack2(bv0.x,bv0.x); b2[1]=pack2(bv0.y,bv0.y);
            b2[2]=pack2(bv0.z,bv0.z); b2[3]=pack2(bv0.w,bv0.w);
            b2[4]=pack2(bv1.x,bv1.x); b2[5]=pack2(bv1.y,bv1.y);
            b2[6]=pack2(bv1.z,bv1.z); b2[7]=pack2(bv1.w,bv1.w);
            #pragma unroll
            for (int i = 0; i < 4; i++)
                #pragma unroll
                for (int j = 0; j < 8; j++) fma2(acc2[i][j], a2[i], b2[j]);
        }
        __syncthreads();
    }

    float bias[8];
    #pragma unroll
    for (int j = 0; j < 8; j++) {
        float bb = bias1[n0 + tn0 + j];
        if (MODE == 0) bb += bias2[n0 + tn0 + j];
        bias[j] = bb;
    }

    #pragma unroll
    for (int i = 0; i < 4; i++) {
        float lo[8], hi[8];
        #pragma unroll
        for (int j = 0; j < 8; j++) {
            float2 u = unpack2(acc2[i][j]);
            lo[j] = u.x + bias[j];
            hi[j] = u.y + bias[j];
        }
        const int mlo = m0 + tm0 + 2*i;
        const int mhi = mlo + 1;
        if (MODE == 0) {
            float* dlo = &g_G0[(size_t)mlo * G4 + n0 + tn0];
            float* dhi = &g_G0[(size_t)mhi * G4 + n0 + tn0];
            *reinterpret_cast<float4*>(dlo)     = make_float4(lo[0],lo[1],lo[2],lo[3]);
            *reinterpret_cast<float4*>(dlo + 4) = make_float4(lo[4],lo[5],lo[6],lo[7]);
            *reinterpret_cast<float4*>(dhi)     = make_float4(hi[0],hi[1],hi[2],hi[3]);
            *reinterpret_cast<float4*>(dhi + 4) = make_float4(hi[4],hi[5],hi[6],hi[7]);
        } else {
            // m = t*Bc + b ; out[b][t][v]
            int blo = mlo & (Bc-1), tlo = mlo >> 7;
            int bhi = mhi & (Bc-1), thi = mhi >> 7;
            float* dlo = &Cout[((size_t)blo * Tc + tlo) * Vc + n0 + tn0];
            float* dhi = &Cout[((size_t)bhi * Tc + thi) * Vc + n0 + tn0];
            *reinterpret_cast<float4*>(dlo)     = make_float4(lo[0],lo[1],lo[2],lo[3]);
            *reinterpret_cast<float4*>(dlo + 4) = make_float4(lo[4],lo[5],lo[6],lo[7]);
            *reinterpret_cast<float4*>(dhi)     = make_float4(hi[0],hi[1],hi[2],hi[3]);
            *reinterpret_cast<float4*>(dhi + 4) = make_float4(hi[4],hi[5],hi[6],hi[7]);
        }
    }
}

// ---------------- pipelined recurrence step --------------------------------
// One launch per pipeline slot s = 0..65, 144 CTAs:
//  Role A (CTA 0..95, 8 h-cols each): shares A = h0[s&1]:
//    G1: layer0 step s gates (32 cols = 4 gates x 8 h) + g_G0 -> epi0 -> h0[(s+1)&1], c0   (s<64)
//    G2: p1(s-1) = h0_new(s-1) @ Wih1^T (same A!) -> g_p1[(s-1)&1]                          (s>=1)
//  Role B (CTA 96..143, 16 h-cols each): layer1 step u = s-2 (s>=2):
//    G3: h1[u&1] @ Whh1^T (64 cols = 4 gates x 16 h) + g_p1[u&1] + biases -> epi1 ->
//        h1[(u+1)&1], c1, g_ys[u]
__global__ __launch_bounds__(256) void step_kernel(int s,
                                                   const float* __restrict__ Whh0,
                                                   const float* __restrict__ Wih1,
                                                   const float* __restrict__ Whh1,
                                                   const float* __restrict__ bih1,
                                                   const float* __restrict__ bhh1) {
    __shared__ union {
        struct { float As[16][128]; float Wd[16][64][2]; } ld;   // 16.0 KB
        float gsh[128][65];                                      // 32.5 KB
    } sm;

    const int tid = threadIdx.x;
    const int bx  = blockIdx.x;
    const bool roleA = (bx < 96);

    const float* Aptr;
    int hgroup;
    if (roleA) {
        if (s >= 65) return;
        hgroup = bx * 8;
        Aptr = g_h0[s & 1];
    } else {
        if (s < 2) return;
        hgroup = (bx - 96) * 16;
        Aptr = g_h1[s & 1];      // u = s-2; u&1 == s&1
    }

    const int tm0 = (tid & 15) * 8;   // 8 m-rows (4 f32x2 pairs)
    const int tn0 = (tid >> 4) * 4;   // 4 n-cols

    unsigned long long acc[4][4];
    #pragma unroll
    for (int i = 0; i < 4; i++)
        #pragma unroll
        for (int j = 0; j < 4; j++) acc[i][j] = 0ull;

    // precompute this thread's W row pointer (each thread loads 1 float4/ktile)
    const int wr = tid >> 2;          // 0..63 tile column
    const int wc4 = (tid & 3) * 4;
    const float* wrow;
    if (roleA) {
        if (wr < 32) wrow = &Whh0[(size_t)((wr>>3)*Hh + hgroup + (wr&7)) * Hh];
        else {
            int q = wr - 32;
            wrow = &Wih1[(size_t)((q>>3)*Hh + hgroup + (q&7)) * Hh];
        }
    } else {
        wrow = &Whh1[(size_t)((wr>>4)*Hh + hgroup + (wr&15)) * Hh];
    }

    for (int kt = 0; kt < Hh/16; ++kt) {
        __syncthreads();
        // A tile: 128 rows x 16 k
        #pragma unroll
        for (int q = 0; q < 2; ++q) {
            int ff  = tid + q*256;
            int row = ff >> 2;
            int c4  = (ff & 3) * 4;
            float4 av = *reinterpret_cast<const float4*>(&Aptr[(size_t)row*Hh + kt*16 + c4]);
            sm.ld.As[c4+0][row]=av.x; sm.ld.As[c4+1][row]=av.y;
            sm.ld.As[c4+2][row]=av.z; sm.ld.As[c4+3][row]=av.w;
        }
        // W tile: 64 cols x 16 k, stored duplicated for f32x2
        {
            float4 wv = *reinterpret_cast<const float4*>(&wrow[kt*16 + wc4]);
            *reinterpret_cast<unsigned long long*>(&sm.ld.Wd[wc4+0][wr][0]) = pack2(wv.x, wv.x);
            *reinterpret_cast<unsigned long long*>(&sm.ld.Wd[wc4+1][wr][0]) = pack2(wv.y, wv.y);
            *reinterpret_cast<unsigned long long*>(&sm.ld.Wd[wc4+2][wr][0]) = pack2(wv.z, wv.z);
            *reinterpret_cast<unsigned long long*>(&sm.ld.Wd[wc4+3][wr][0]) = pack2(wv.w, wv.w);
        }
        __syncthreads();
        #pragma unroll
        for (int k = 0; k < 16; ++k) {
            unsigned long long a2[4];
            const unsigned long long* ap = reinterpret_cast<const unsigned long long*>(&sm.ld.As[k][tm0]);
            a2[0]=ap[0]; a2[1]=ap[1]; a2[2]=ap[2]; a2[3]=ap[3];
            const unsigned long long* bp = reinterpret_cast<const unsigned long long*>(&sm.ld.Wd[k][tn0][0]);
            unsigned long long b0=bp[0], b1=bp[1], b2=bp[2], b3=bp[3];
            #pragma unroll
            for (int i = 0; i < 4; i++) {
                fma2(acc[i][0], a2[i], b0);
                fma2(acc[i][1], a2[i], b1);
                fma2(acc[i][2], a2[i], b2);
                fma2(acc[i][3], a2[i], b3);
            }
        }
    }
    __syncthreads();   // done with As/Wd; gsh aliasing is now safe

    if (roleA) {
        if (tn0 >= 32) {
            // G2: store p1 partial straight to gmem
            if (s >= 1) {
                float* pbuf = g_p1[(s-1) & 1];
                int q0 = tn0 - 32;
                int gate = q0 >> 3;
                int j0 = q0 & 7;           // 0 or 4 -> float4 aligned
                #pragma unroll
                for (int i = 0; i < 4; i++) {
                    float2 u0 = unpack2(acc[i][0]);
                    float2 u1 = unpack2(acc[i][1]);
                    float2 u2 = unpack2(acc[i][2]);
                    float2 u3 = unpack2(acc[i][3]);
                    int blo = tm0 + 2*i, bhi = blo + 1;
                    float* d0 = &pbuf[(size_t)blo*G4 + gate*Hh + hgroup + j0];
                    float* d1 = &pbuf[(size_t)bhi*G4 + gate*Hh + hgroup + j0];
                    *reinterpret_cast<float4*>(d0) = make_float4(u0.x,u1.x,u2.x,u3.x);
                    *reinterpret_cast<float4*>(d1) = make_float4(u0.y,u1.y,u2.y,u3.y);
                }
            }
        } else {
            // G1: stage layer0 gates to smem for regrouping
            #pragma unroll
            for (int i = 0; i < 4; i++) {
                float2 u0 = unpack2(acc[i][0]);
                float2 u1 = unpack2(acc[i][1]);
                float2 u2 = unpack2(acc[i][2]);
                float2 u3 = unpack2(acc[i][3]);
                int blo = tm0 + 2*i, bhi = blo + 1;
                sm.gsh[blo][tn0+0]=u0.x; sm.gsh[bhi][tn0+0]=u0.y;
                sm.gsh[blo][tn0+1]=u1.x; sm.gsh[bhi][tn0+1]=u1.y;
                sm.gsh[blo][tn0+2]=u2.x; sm.gsh[bhi][tn0+2]=u2.y;
                sm.gsh[blo][tn0+3]=u3.x; sm.gsh[bhi][tn0+3]=u3.y;
            }
        }
        __syncthreads();
        if (s < 64) {
            // layer0 epilogue for 128 b x 8 h
            float* hout = g_h0[(s+1) & 1];
            for (int e = tid; e < Bc*8; e += 256) {
                int b = e >> 3, j = e & 7;
                size_t gbase = ((size_t)(s*Bc + b))*G4 + hgroup + j;
                float gi = sm.gsh[b][j]      + g_G0[gbase];
                float gf = sm.gsh[b][8+j]    + g_G0[gbase +   Hh];
                float gg = sm.gsh[b][16+j]   + g_G0[gbase + 2*Hh];
                float go = sm.gsh[b][24+j]   + g_G0[gbase + 3*Hh];
                int ci = b*Hh + hgroup + j;
                float si = 1.f/(1.f+expf(-gi));
                float sf = 1.f/(1.f+expf(-gf));
                float so = 1.f/(1.f+expf(-go));
                float cn = sf * g_c0[ci] + si * tanhf(gg);
                float hn = so * tanhf(cn);
                g_c0[ci] = cn;
                hout[ci] = hn;
            }
        }
    } else {
        // role B: stage all 64 cols (4 gates x 16 h)
        #pragma unroll
        for (int i = 0; i < 4; i++) {
            float2 u0 = unpack2(acc[i][0]);
            float2 u1 = unpack2(acc[i][1]);
            float2 u2 = unpack2(acc[i][2]);
            float2 u3 = unpack2(acc[i][3]);
            int blo = tm0 + 2*i, bhi = blo + 1;
            sm.gsh[blo][tn0+0]=u0.x; sm.gsh[bhi][tn0+0]=u0.y;
            sm.gsh[blo][tn0+1]=u1.x; sm.gsh[bhi][tn0+1]=u1.y;
            sm.gsh[blo][tn0+2]=u2.x; sm.gsh[bhi][tn0+2]=u2.y;
            sm.gsh[blo][tn0+3]=u3.x; sm.gsh[bhi][tn0+3]=u3.y;
        }
        __syncthreads();
        const int u = s - 2;
        const float* pbuf = g_p1[u & 1];
        float* hout = g_h1[(u+1) & 1];
        for (int e = tid; e < Bc*16; e += 256) {
            int b = e >> 4, jj = e & 15;
            int col = hgroup + jj;
            const float* pb = pbuf + (size_t)b*G4;
            float gi = sm.gsh[b][jj]      + pb[col]        + bih1[col]        + bhh1[col];
            float gf = sm.gsh[b][16+jj]   + pb[Hh+col]     + bih1[Hh+col]     + bhh1[Hh+col];
            float gg = sm.gsh[b][32+jj]   + pb[2*Hh+col]   + bih1[2*Hh+col]   + bhh1[2*Hh+col];
            float go = sm.gsh[b][48+jj]   + pb[3*Hh+col]   + bih1[3*Hh+col]   + bhh1[3*Hh+col];
            int ci = b*Hh + col;
            float si = 1.f/(1.f+expf(-gi));
            float sf = 1.f/(1.f+expf(-gf));
            float so = 1.f/(1.f+expf(-go));
            float cn = sf * g_c1[ci] + si * tanhf(gg);
            float hn = so * tanhf(cn);
            g_c1[ci] = cn;
            hout[ci] = hn;
            g_ys[((size_t)u*Bc + b)*Hh + col] = hn;
        }
    }
}

// ---------------- launch ----------------------------------------------------
extern "C" void kernel_launch(void* const* d_in, const int* in_sizes, int n_in,
                              void* d_out, int out_size) {
    const int*   src   = (const int*)  d_in[0];
    const int*   trg   = (const int*)  d_in[1];
    const float* bert  = (const float*)d_in[2];
    const float* emb   = (const float*)d_in[3];
    const float* W_ih  = (const float*)d_in[4];
    const float* W_hh  = (const float*)d_in[5];
    const float* b_ih  = (const float*)d_in[6];
    const float* b_hh  = (const float*)d_in[7];
    const float* W_out = (const float*)d_in[8];
    const float* b_out = (const float*)d_in[9];
    float* out = (float*)d_out;

    // 1. gather embeddings + init h/c
    init_kernel<<<(Tc*Bc*Hh + 255)/256, 256>>>(src, trg, bert, emb);

    // 2. hoisted layer-0 input GEMM: g_G0 = g_xs @ W_ih[0]^T + (b_ih[0]+b_hh[0])
    gemm_nt<0><<<dim3(G4/128, (Tc*Bc)/128), 256>>>(W_ih, b_ih, b_hh, nullptr);

    // 3. pipelined recurrence: 66 launches cover 64 steps x 2 layers
    const float* Whh0 = W_hh;
    const float* Wih1 = W_ih + (size_t)G4 * Hh;
    const float* Whh1 = W_hh + (size_t)G4 * Hh;
    const float* bih1 = b_ih + G4;
    const float* bhh1 = b_hh + G4;
    for (int s = 0; s <= 65; ++s)
        step_kernel<<<144, 256>>>(s, Whh0, Wih1, Whh1, bih1, bhh1);

    // 4. output projection: out[b][t][v] = ys[t][b][:] . W_out[v][:] + b_out[v]
    gemm_nt<1><<<dim3(Vc/128, (Tc*Bc)/128), 256>>>(W_out, b_out, nullptr, out);
}

// round 4
// speedup vs baseline: 1.6388x; 1.4813x over previous
#include <cuda_runtime.h>
#include <cuda_bf16.h>
#include <math.h>
#include <stdint.h>

// Problem constants
#define Hh   768
#define Lc   2
#define Vc   32000
#define Bc   128
#define Tc   64
#define Sc   32
#define G4   (4*Hh)   // 3072

// ---------------- scratch (device globals; no allocations allowed) ----------
__device__ __align__(128) float g_xs[Tc*Bc*Hh];         // gathered target embeddings [t][b][h]
__device__ __align__(128) float g_G0[(size_t)Tc*Bc*G4]; // precomputed layer0 input gates (+biases)
__device__ __align__(128) float g_h0[2][Bc*Hh];         // layer0 hidden ping-pong
__device__ __align__(128) float g_h1[2][Bc*Hh];         // layer1 hidden ping-pong
__device__ __align__(128) float g_c0[Bc*Hh];
__device__ __align__(128) float g_c1[Bc*Hh];
__device__ __align__(128) float g_p1[2][Bc*G4];         // layer1 input-gate partials (pipeline)
__device__ __align__(128) float g_ys[Tc*Bc*Hh];         // layer1 outputs [t][b][h]
// bf16 2-way-split buffers for tensor-core projection
__device__ __align__(128) __nv_bfloat16 g_ysh[Tc*Bc*Hh];
__device__ __align__(128) __nv_bfloat16 g_ysl[Tc*Bc*Hh];
__device__ __align__(128) __nv_bfloat16 g_Wh[(size_t)Vc*Hh];
__device__ __align__(128) __nv_bfloat16 g_Wl[(size_t)Vc*Hh];

// ---------------- f32x2 packed math helpers (sm_103a FFMA2 path) ------------
__device__ __forceinline__ unsigned long long pack2(float x, float y) {
    unsigned long long r;
    unsigned lo = __float_as_uint(x), hi = __float_as_uint(y);
    asm("mov.b64 %0, {%1, %2};" : "=l"(r) : "r"(lo), "r"(hi));
    return r;
}
__device__ __forceinline__ float2 unpack2(unsigned long long v) {
    unsigned lo, hi;
    asm("mov.b64 {%0, %1}, %2;" : "=r"(lo), "=r"(hi) : "l"(v));
    return make_float2(__uint_as_float(lo), __uint_as_float(hi));
}
__device__ __forceinline__ void fma2(unsigned long long& c, unsigned long long a, unsigned long long b) {
    asm("fma.rn.f32x2 %0, %1, %2, %3;" : "=l"(c) : "l"(a), "l"(b), "l"(c));
}

// ---------------- mma.sync helpers (plain sm_103-target ISA) ----------------
__device__ __forceinline__ uint32_t smem_u32(const void* p) {
    uint32_t a;
    asm("{ .reg .u64 t; cvta.to.shared.u64 t, %1; cvt.u32.u64 %0, t; }" : "=r"(a) : "l"(p));
    return a;
}
#define LDSM4(r, a) \
    asm volatile("ldmatrix.sync.aligned.m8n8.x4.shared.b16 {%0,%1,%2,%3}, [%4];" \
        : "=r"((r)[0]), "=r"((r)[1]), "=r"((r)[2]), "=r"((r)[3]) : "r"(a))

__device__ __forceinline__ void mma_bf16(float* c, const uint32_t* a, const uint32_t* b) {
    asm volatile("mma.sync.aligned.m16n8k16.row.col.f32.bf16.bf16.f32 "
        "{%0,%1,%2,%3}, {%4,%5,%6,%7}, {%8,%9}, {%0,%1,%2,%3};"
        : "+f"(c[0]), "+f"(c[1]), "+f"(c[2]), "+f"(c[3])
        : "r"(a[0]), "r"(a[1]), "r"(a[2]), "r"(a[3]), "r"(b[0]), "r"(b[1]));
}
__device__ __forceinline__ void cp16(uint32_t dst, const void* src) {
    asm volatile("cp.async.cg.shared.global [%0], [%1], 16;" :: "r"(dst), "l"(src));
}

// ---------------- init: gather embeddings, init h/c ------------------------
__global__ void init_kernel(const int* __restrict__ src, const int* __restrict__ trg,
                            const float* __restrict__ bert, const float* __restrict__ emb) {
    int idx = blockIdx.x * blockDim.x + threadIdx.x;
    if (idx < Tc*Bc*Hh) {
        int h = idx % Hh;
        int m = idx / Hh;          // m = t*Bc + b
        int b = m % Bc;
        int t = m / Bc;
        g_xs[idx] = emb[(size_t)trg[b*Tc + t] * Hh + h];
    }
    if (idx < Bc*Hh) {
        int b = idx / Hh, h = idx % Hh;
        float v = bert[(size_t)src[b*Sc] * Hh + h];
        g_h0[0][idx] = v;
        g_h1[0][idx] = v;
        g_c0[idx] = 0.f;
        g_c1[idx] = 0.f;
    }
}

// ---------------- bf16 2-way split ------------------------------------------
__global__ void split_bf16(const float* __restrict__ x, __nv_bfloat16* __restrict__ hi,
                           __nv_bfloat16* __restrict__ lo, int n) {
    int i = blockIdx.x * 256 + threadIdx.x;
    if (i < n) {
        float v = x[i];
        __nv_bfloat16 h = __float2bfloat16_rz(v);
        float r = v - __bfloat162float(h);
        hi[i] = h;
        lo[i] = __float2bfloat16_rz(r);
    }
}

// ---------------- fp32 NT GEMM (hoisted layer0 input GEMM) ------------------
__global__ __launch_bounds__(256) void gemm_nt(const float* __restrict__ W,
                                               const float* __restrict__ bias1,
                                               const float* __restrict__ bias2) {
    const float* __restrict__ A = g_xs;
    const int m0 = blockIdx.y * 128;
    const int n0 = blockIdx.x * 128;
    __shared__ __align__(16) float As[16][128];
    __shared__ __align__(16) float Bs[16][128];
    const int tid = threadIdx.x;
    const int tm0 = (tid >> 4) * 8;
    const int tn0 = (tid & 15) * 8;

    unsigned long long acc2[4][8];
    #pragma unroll
    for (int i = 0; i < 4; i++)
        #pragma unroll
        for (int j = 0; j < 8; j++) acc2[i][j] = 0ull;

    for (int kt = 0; kt < Hh/16; ++kt) {
        #pragma unroll
        for (int q = 0; q < 2; ++q) {
            int ff  = tid + q*256;
            int row = ff >> 2;
            int c4  = (ff & 3) * 4;
            float4 av = *reinterpret_cast<const float4*>(&A[(size_t)(m0+row)*Hh + kt*16 + c4]);
            float4 bv = *reinterpret_cast<const float4*>(&W[(size_t)(n0+row)*Hh + kt*16 + c4]);
            As[c4+0][row]=av.x; As[c4+1][row]=av.y; As[c4+2][row]=av.z; As[c4+3][row]=av.w;
            Bs[c4+0][row]=bv.x; Bs[c4+1][row]=bv.y; Bs[c4+2][row]=bv.z; Bs[c4+3][row]=bv.w;
        }
        __syncthreads();
        #pragma unroll
        for (int k = 0; k < 16; ++k) {
            unsigned long long a2[4];
            const unsigned long long* ap = reinterpret_cast<const unsigned long long*>(&As[k][tm0]);
            #pragma unroll
            for (int i = 0; i < 4; i++) a2[i] = ap[i];
            float4 bv0 = *reinterpret_cast<const float4*>(&Bs[k][tn0]);
            float4 bv1 = *reinterpret_cast<const float4*>(&Bs[k][tn0+4]);
            unsigned long long b2[8];
            b2[0]=pack2(bv0.x,bv0.x); b2[1]=pack2(bv0.y,bv0.y);
            b2[2]=pack2(bv0.z,bv0.z); b2[3]=pack2(bv0.w,bv0.w);
            b2[4]=pack2(bv1.x,bv1.x); b2[5]=pack2(bv1.y,bv1.y);
            b2[6]=pack2(bv1.z,bv1.z); b2[7]=pack2(bv1.w,bv1.w);
            #pragma unroll
            for (int i = 0; i < 4; i++)
                #pragma unroll
                for (int j = 0; j < 8; j++) fma2(acc2[i][j], a2[i], b2[j]);
        }
        __syncthreads();
    }

    float bias[8];
    #pragma unroll
    for (int j = 0; j < 8; j++)
        bias[j] = bias1[n0 + tn0 + j] + bias2[n0 + tn0 + j];

    #pragma unroll
    for (int i = 0; i < 4; i++) {
        float lo[8], hi[8];
        #pragma unroll
        for (int j = 0; j < 8; j++) {
            float2 u = unpack2(acc2[i][j]);
            lo[j] = u.x + bias[j];
            hi[j] = u.y + bias[j];
        }
        const int mlo = m0 + tm0 + 2*i;
        const int mhi = mlo + 1;
        float* dlo = &g_G0[(size_t)mlo * G4 + n0 + tn0];
        float* dhi = &g_G0[(size_t)mhi * G4 + n0 + tn0];
        *reinterpret_cast<float4*>(dlo)     = make_float4(lo[0],lo[1],lo[2],lo[3]);
        *reinterpret_cast<float4*>(dlo + 4) = make_float4(lo[4],lo[5],lo[6],lo[7]);
        *reinterpret_cast<float4*>(dhi)     = make_float4(hi[0],hi[1],hi[2],hi[3]);
        *reinterpret_cast<float4*>(dhi + 4) = make_float4(hi[4],hi[5],hi[6],hi[7]);
    }
}

// ---------------- pipelined recurrence step (unchanged, passing) -------------
__global__ __launch_bounds__(256) void step_kernel(int s,
                                                   const float* __restrict__ Whh0,
                                                   const float* __restrict__ Wih1,
                                                   const float* __restrict__ Whh1,
                                                   const float* __restrict__ bih1,
                                                   const float* __restrict__ bhh1) {
    __shared__ union {
        struct { float As[16][128]; float Wd[16][64][2]; } ld;
        float gsh[128][65];
    } sm;

    const int tid = threadIdx.x;
    const int bx  = blockIdx.x;
    const bool roleA = (bx < 96);

    const float* Aptr;
    int hgroup;
    if (roleA) {
        if (s >= 65) return;
        hgroup = bx * 8;
        Aptr = g_h0[s & 1];
    } else {
        if (s < 2) return;
        hgroup = (bx - 96) * 16;
        Aptr = g_h1[s & 1];
    }

    const int tm0 = (tid & 15) * 8;
    const int tn0 = (tid >> 4) * 4;

    unsigned long long acc[4][4];
    #pragma unroll
    for (int i = 0; i < 4; i++)
        #pragma unroll
        for (int j = 0; j < 4; j++) acc[i][j] = 0ull;

    const int wr = tid >> 2;
    const int wc4 = (tid & 3) * 4;
    const float* wrow;
    if (roleA) {
        if (wr < 32) wrow = &Whh0[(size_t)((wr>>3)*Hh + hgroup + (wr&7)) * Hh];
        else {
            int q = wr - 32;
            wrow = &Wih1[(size_t)((q>>3)*Hh + hgroup + (q&7)) * Hh];
        }
    } else {
        wrow = &Whh1[(size_t)((wr>>4)*Hh + hgroup + (wr&15)) * Hh];
    }

    for (int kt = 0; kt < Hh/16; ++kt) {
        __syncthreads();
        #pragma unroll
        for (int q = 0; q < 2; ++q) {
            int ff  = tid + q*256;
            int row = ff >> 2;
            int c4  = (ff & 3) * 4;
            float4 av = *reinterpret_cast<const float4*>(&Aptr[(size_t)row*Hh + kt*16 + c4]);
            sm.ld.As[c4+0][row]=av.x; sm.ld.As[c4+1][row]=av.y;
            sm.ld.As[c4+2][row]=av.z; sm.ld.As[c4+3][row]=av.w;
        }
        {
            float4 wv = *reinterpret_cast<const float4*>(&wrow[kt*16 + wc4]);
            *reinterpret_cast<unsigned long long*>(&sm.ld.Wd[wc4+0][wr][0]) = pack2(wv.x, wv.x);
            *reinterpret_cast<unsigned long long*>(&sm.ld.Wd[wc4+1][wr][0]) = pack2(wv.y, wv.y);
            *reinterpret_cast<unsigned long long*>(&sm.ld.Wd[wc4+2][wr][0]) = pack2(wv.z, wv.z);
            *reinterpret_cast<unsigned long long*>(&sm.ld.Wd[wc4+3][wr][0]) = pack2(wv.w, wv.w);
        }
        __syncthreads();
        #pragma unroll
        for (int k = 0; k < 16; ++k) {
            unsigned long long a2[4];
            const unsigned long long* ap = reinterpret_cast<const unsigned long long*>(&sm.ld.As[k][tm0]);
            a2[0]=ap[0]; a2[1]=ap[1]; a2[2]=ap[2]; a2[3]=ap[3];
            const unsigned long long* bp = reinterpret_cast<const unsigned long long*>(&sm.ld.Wd[k][tn0][0]);
            unsigned long long b0=bp[0], b1=bp[1], b2=bp[2], b3=bp[3];
            #pragma unroll
            for (int i = 0; i < 4; i++) {
                fma2(acc[i][0], a2[i], b0);
                fma2(acc[i][1], a2[i], b1);
                fma2(acc[i][2], a2[i], b2);
                fma2(acc[i][3], a2[i], b3);
            }
        }
    }
    __syncthreads();

    if (roleA) {
        if (tn0 >= 32) {
            if (s >= 1) {
                float* pbuf = g_p1[(s-1) & 1];
                int q0 = tn0 - 32;
                int gate = q0 >> 3;
                int j0 = q0 & 7;
                #pragma unroll
                for (int i = 0; i < 4; i++) {
                    float2 u0 = unpack2(acc[i][0]);
                    float2 u1 = unpack2(acc[i][1]);
                    float2 u2 = unpack2(acc[i][2]);
                    float2 u3 = unpack2(acc[i][3]);
                    int blo = tm0 + 2*i, bhi = blo + 1;
                    float* d0 = &pbuf[(size_t)blo*G4 + gate*Hh + hgroup + j0];
                    float* d1 = &pbuf[(size_t)bhi*G4 + gate*Hh + hgroup + j0];
                    *reinterpret_cast<float4*>(d0) = make_float4(u0.x,u1.x,u2.x,u3.x);
                    *reinterpret_cast<float4*>(d1) = make_float4(u0.y,u1.y,u2.y,u3.y);
                }
            }
        } else {
            #pragma unroll
            for (int i = 0; i < 4; i++) {
                float2 u0 = unpack2(acc[i][0]);
                float2 u1 = unpack2(acc[i][1]);
                float2 u2 = unpack2(acc[i][2]);
                float2 u3 = unpack2(acc[i][3]);
                int blo = tm0 + 2*i, bhi = blo + 1;
                sm.gsh[blo][tn0+0]=u0.x; sm.gsh[bhi][tn0+0]=u0.y;
                sm.gsh[blo][tn0+1]=u1.x; sm.gsh[bhi][tn0+1]=u1.y;
                sm.gsh[blo][tn0+2]=u2.x; sm.gsh[bhi][tn0+2]=u2.y;
                sm.gsh[blo][tn0+3]=u3.x; sm.gsh[bhi][tn0+3]=u3.y;
            }
        }
        __syncthreads();
        if (s < 64) {
            float* hout = g_h0[(s+1) & 1];
            for (int e = tid; e < Bc*8; e += 256) {
                int b = e >> 3, j = e & 7;
                size_t gbase = ((size_t)(s*Bc + b))*G4 + hgroup + j;
                float gi = sm.gsh[b][j]      + g_G0[gbase];
                float gf = sm.gsh[b][8+j]    + g_G0[gbase +   Hh];
                float gg = sm.gsh[b][16+j]   + g_G0[gbase + 2*Hh];
                float go = sm.gsh[b][24+j]   + g_G0[gbase + 3*Hh];
                int ci = b*Hh + hgroup + j;
                float si = 1.f/(1.f+expf(-gi));
                float sf = 1.f/(1.f+expf(-gf));
                float so = 1.f/(1.f+expf(-go));
                float cn = sf * g_c0[ci] + si * tanhf(gg);
                float hn = so * tanhf(cn);
                g_c0[ci] = cn;
                hout[ci] = hn;
            }
        }
    } else {
        #pragma unroll
        for (int i = 0; i < 4; i++) {
            float2 u0 = unpack2(acc[i][0]);
            float2 u1 = unpack2(acc[i][1]);
            float2 u2 = unpack2(acc[i][2]);
            float2 u3 = unpack2(acc[i][3]);
            int blo = tm0 + 2*i, bhi = blo + 1;
            sm.gsh[blo][tn0+0]=u0.x; sm.gsh[bhi][tn0+0]=u0.y;
            sm.gsh[blo][tn0+1]=u1.x; sm.gsh[bhi][tn0+1]=u1.y;
            sm.gsh[blo][tn0+2]=u2.x; sm.gsh[bhi][tn0+2]=u2.y;
            sm.gsh[blo][tn0+3]=u3.x; sm.gsh[bhi][tn0+3]=u3.y;
        }
        __syncthreads();
        const int u = s - 2;
        const float* pbuf = g_p1[u & 1];
        float* hout = g_h1[(u+1) & 1];
        for (int e = tid; e < Bc*16; e += 256) {
            int b = e >> 4, jj = e & 15;
            int col = hgroup + jj;
            const float* pb = pbuf + (size_t)b*G4;
            float gi = sm.gsh[b][jj]      + pb[col]        + bih1[col]        + bhh1[col];
            float gf = sm.gsh[b][16+jj]   + pb[Hh+col]     + bih1[Hh+col]     + bhh1[Hh+col];
            float gg = sm.gsh[b][32+jj]   + pb[2*Hh+col]   + bih1[2*Hh+col]   + bhh1[2*Hh+col];
            float go = sm.gsh[b][48+jj]   + pb[3*Hh+col]   + bih1[3*Hh+col]   + bhh1[3*Hh+col];
            int ci = b*Hh + col;
            float si = 1.f/(1.f+expf(-gi));
            float sf = 1.f/(1.f+expf(-gf));
            float so = 1.f/(1.f+expf(-go));
            float cn = sf * g_c1[ci] + si * tanhf(gg);
            float hn = so * tanhf(cn);
            g_c1[ci] = cn;
            hout[ci] = hn;
            g_ys[((size_t)u*Bc + b)*Hh + col] = hn;
        }
    }
}

// ---------------- mma.sync bf16x2 output projection --------------------------
// out[b][t][v] = ys @ W_out^T + b_out computed as AhBh + AhBl + AlBh (fp32 acc).
// CTA 128x128, 256 threads (2x4 warps, warp tile 64x32), K-chunk 32,
// double-buffered cp.async, xor-swizzled smem, ldmatrix + mma.m16n8k16.bf16.
#define PSTAGE   32768     // Ah 8K | Al 8K | Bh 8K | Bl 8K
#define PROJ_SMEM (2*PSTAGE)

__global__ void __launch_bounds__(256) proj_mma(const float* __restrict__ b_out,
                                                float* __restrict__ out) {
    extern __shared__ char dsm[];
    const uint32_t base = smem_u32(dsm);
    const int tid  = threadIdx.x;
    const int t    = blockIdx.x;          // m-tile == timestep (tile_M = Bc = 128)
    const int m0   = t * 128;
    const int n0   = blockIdx.y * 128;
    const int lane = tid & 31;
    const int warp = tid >> 5;
    const int wm   = warp >> 2;           // 0..1  (m 64 each)
    const int wn   = warp & 3;            // 0..3  (n 32 each)
    const int lr   = lane & 15;
    const int lk   = lane >> 4;

    float acc[4][4][4];
    #pragma unroll
    for (int i = 0; i < 4; i++)
        #pragma unroll
        for (int j = 0; j < 4; j++)
            #pragma unroll
            for (int r = 0; r < 4; r++) acc[i][j][r] = 0.f;

    auto load_stage = [&](int buf, int k0) {
        const uint32_t sb = base + buf*PSTAGE;
        #pragma unroll
        for (int i = 0; i < 8; i++) {
            int id  = tid + i*256;        // 0..2047
            int arr = id >> 9;            // constant per i pair
            int w   = id & 511;
            int row = w >> 2, ch = w & 3;
            uint32_t dst = sb + arr*8192 + row*64 + ((ch ^ (row & 3)) << 4);
            const __nv_bfloat16* src;
            if      (arr == 0) src = &g_ysh[(size_t)(m0 + row)*Hh + k0 + ch*8];
            else if (arr == 1) src = &g_ysl[(size_t)(m0 + row)*Hh + k0 + ch*8];
            else if (arr == 2) src = &g_Wh [(size_t)(n0 + row)*Hh + k0 + ch*8];
            else               src = &g_Wl [(size_t)(n0 + row)*Hh + k0 + ch*8];
            cp16(dst, src);
        }
        asm volatile("cp.async.commit_group;" ::: "memory");
    };

    load_stage(0, 0);

    for (int s = 0; s < Hh/32; ++s) {
        if (s + 1 < Hh/32) {
            load_stage((s+1) & 1, (s+1)*32);
            asm volatile("cp.async.wait_group 1;" ::: "memory");
        } else {
            asm volatile("cp.async.wait_group 0;" ::: "memory");
        }
        __syncthreads();

        const uint32_t sb = base + (s & 1)*PSTAGE;
        #pragma unroll
        for (int kk8 = 0; kk8 < 4; kk8 += 2) {     // two k16 steps per chunk
            uint32_t ah[4][4], al[4][4];
            #pragma unroll
            for (int mt = 0; mt < 4; mt++) {
                int row = wm*64 + mt*16 + lr;
                uint32_t off = row*64 + ((((kk8 + lk) ^ (row & 3))) << 4);
                LDSM4(ah[mt], sb + off);
                LDSM4(al[mt], sb + 8192 + off);
            }
            uint32_t bh[4][2], bl[4][2];
            #pragma unroll
            for (int np = 0; np < 2; np++) {
                int row = wn*32 + np*16 + lr;
                uint32_t off = row*64 + ((((kk8 + lk) ^ (row & 3))) << 4);
                uint32_t r[4];
                LDSM4(r, sb + 16384 + off);
                bh[np*2][0]=r[0]; bh[np*2+1][0]=r[1]; bh[np*2][1]=r[2]; bh[np*2+1][1]=r[3];
                LDSM4(r, sb + 24576 + off);
                bl[np*2][0]=r[0]; bl[np*2+1][0]=r[1]; bl[np*2][1]=r[2]; bl[np*2+1][1]=r[3];
            }
            #pragma unroll
            for (int mt = 0; mt < 4; mt++)
                #pragma unroll
                for (int nt = 0; nt < 4; nt++) {
                    mma_bf16(acc[mt][nt], ah[mt], bh[nt]);
                    mma_bf16(acc[mt][nt], ah[mt], bl[nt]);
                    mma_bf16(acc[mt][nt], al[mt], bh[nt]);
                }
        }
        __syncthreads();
    }

    // epilogue: frag -> gmem with bias, rows are batch b (tile m == timestep t)
    #pragma unroll
    for (int nt = 0; nt < 4; nt++) {
        int col = n0 + wn*32 + nt*8 + (lane & 3)*2;
        float bb0 = b_out[col], bb1 = b_out[col + 1];
        #pragma unroll
        for (int mt = 0; mt < 4; mt++) {
            int r0 = wm*64 + mt*16 + (lane >> 2);
            float2* p0 = reinterpret_cast<float2*>(&out[((size_t)r0*Tc + t)*Vc + col]);
            *p0 = make_float2(acc[mt][nt][0] + bb0, acc[mt][nt][1] + bb1);
            float2* p1 = reinterpret_cast<float2*>(&out[((size_t)(r0+8)*Tc + t)*Vc + col]);
            *p1 = make_float2(acc[mt][nt][2] + bb0, acc[mt][nt][3] + bb1);
        }
    }
}

// ---------------- launch ----------------------------------------------------
extern "C" void kernel_launch(void* const* d_in, const int* in_sizes, int n_in,
                              void* d_out, int out_size) {
    const int*   src   = (const int*)  d_in[0];
    const int*   trg   = (const int*)  d_in[1];
    const float* bert  = (const float*)d_in[2];
    const float* emb   = (const float*)d_in[3];
    const float* W_ih  = (const float*)d_in[4];
    const float* W_hh  = (const float*)d_in[5];
    const float* b_ih  = (const float*)d_in[6];
    const float* b_hh  = (const float*)d_in[7];
    const float* W_out = (const float*)d_in[8];
    const float* b_out = (const float*)d_in[9];
    float* out = (float*)d_out;

    cudaFuncSetAttribute(proj_mma, cudaFuncAttributeMaxDynamicSharedMemorySize, PROJ_SMEM);

    // 1. gather embeddings + init h/c
    init_kernel<<<(Tc*Bc*Hh + 255)/256, 256>>>(src, trg, bert, emb);

    // 1b. split W_out into bf16 hi/lo (independent of recurrence)
    __nv_bfloat16 *wh, *wl, *ysh, *ysl;
    cudaGetSymbolAddress((void**)&wh,  g_Wh);
    cudaGetSymbolAddress((void**)&wl,  g_Wl);
    cudaGetSymbolAddress((void**)&ysh, g_ysh);
    cudaGetSymbolAddress((void**)&ysl, g_ysl);
    split_bf16<<<(Vc*Hh + 255)/256, 256>>>(W_out, wh, wl, Vc*Hh);

    // 2. hoisted layer-0 input GEMM: g_G0 = g_xs @ W_ih[0]^T + (b_ih[0]+b_hh[0])
    gemm_nt<<<dim3(G4/128, (Tc*Bc)/128), 256>>>(W_ih, b_ih, b_hh);

    // 3. pipelined recurrence: 66 launches cover 64 steps x 2 layers
    const float* Whh0 = W_hh;
    const float* Wih1 = W_ih + (size_t)G4 * Hh;
    const float* Whh1 = W_hh + (size_t)G4 * Hh;
    const float* bih1 = b_ih + G4;
    const float* bhh1 = b_hh + G4;
    for (int s = 0; s <= 65; ++s)
        step_kernel<<<144, 256>>>(s, Whh0, Wih1, Whh1, bih1, bhh1);

    // 3b. split ys into bf16 hi/lo
    {
        float* ysp;
        cudaGetSymbolAddress((void**)&ysp, g_ys);
        split_bf16<<<(Tc*Bc*Hh + 255)/256, 256>>>(ysp, ysh, ysl, Tc*Bc*Hh);
    }

    // 4. output projection on tensor cores (bf16x2 split, 3 MMAs)
    proj_mma<<<dim3(Tc, Vc/128), 256, PROJ_SMEM>>>(b_out, out);
}

// round 5
// speedup vs baseline: 2.6907x; 1.6419x over previous
#include <cuda_runtime.h>
#include <cuda_bf16.h>
#include <math.h>
#include <stdint.h>

// Problem constants
#define Hh   768
#define Lc   2
#define Vc   32000
#define Bc   128
#define Tc   64
#define Sc   32
#define G4   (4*Hh)   // 3072

// ---------------- scratch (device globals; no allocations allowed) ----------
__device__ __align__(128) float g_xs[Tc*Bc*Hh];         // gathered target embeddings [t][b][h]
__device__ __align__(128) float g_G0[(size_t)Tc*Bc*G4]; // precomputed layer0 input gates (+biases), gate-major
__device__ __align__(128) float g_c0[Bc*Hh];
__device__ __align__(128) float g_c1[Bc*Hh];
__device__ __align__(128) float g_p1[2][Bc*G4];         // layer1 input-gate partials (permuted cols)
__device__ __align__(128) float g_bp1[G4];              // permuted (b_ih[1]+b_hh[1])
// h-state as bf16 hi/lo, ping-pong
__device__ __align__(128) __nv_bfloat16 g_h0b[2][2][Bc*Hh];
__device__ __align__(128) __nv_bfloat16 g_h1b[2][2][Bc*Hh];
// recurrence weights: [mat 0=Whh0,1=Wih1,2=Whh1][hi/lo], permuted rows p = h*4+gate
__device__ __align__(128) __nv_bfloat16 g_Wr[3][2][(size_t)G4*Hh];
// bf16 2-way-split buffers for tensor-core projection
__device__ __align__(128) __nv_bfloat16 g_ysh[Tc*Bc*Hh];
__device__ __align__(128) __nv_bfloat16 g_ysl[Tc*Bc*Hh];
__device__ __align__(128) __nv_bfloat16 g_Wh[(size_t)Vc*Hh];
__device__ __align__(128) __nv_bfloat16 g_Wl[(size_t)Vc*Hh];

// ---------------- f32x2 packed math helpers ---------------------------------
__device__ __forceinline__ unsigned long long pack2(float x, float y) {
    unsigned long long r;
    unsigned lo = __float_as_uint(x), hi = __float_as_uint(y);
    asm("mov.b64 %0, {%1, %2};" : "=l"(r) : "r"(lo), "r"(hi));
    return r;
}
__device__ __forceinline__ float2 unpack2(unsigned long long v) {
    unsigned lo, hi;
    asm("mov.b64 {%0, %1}, %2;" : "=r"(lo), "=r"(hi) : "l"(v));
    return make_float2(__uint_as_float(lo), __uint_as_float(hi));
}
__device__ __forceinline__ void fma2(unsigned long long& c, unsigned long long a, unsigned long long b) {
    asm("fma.rn.f32x2 %0, %1, %2, %3;" : "=l"(c) : "l"(a), "l"(b), "l"(c));
}

// ---------------- mma.sync helpers ------------------------------------------
__device__ __forceinline__ uint32_t smem_u32(const void* p) {
    uint32_t a;
    asm("{ .reg .u64 t; cvta.to.shared.u64 t, %1; cvt.u32.u64 %0, t; }" : "=r"(a) : "l"(p));
    return a;
}
#define LDSM4(r, a) \
    asm volatile("ldmatrix.sync.aligned.m8n8.x4.shared.b16 {%0,%1,%2,%3}, [%4];" \
        : "=r"((r)[0]), "=r"((r)[1]), "=r"((r)[2]), "=r"((r)[3]) : "r"(a))

__device__ __forceinline__ void mma_bf16(float* c, const uint32_t* a, const uint32_t* b) {
    asm volatile("mma.sync.aligned.m16n8k16.row.col.f32.bf16.bf16.f32 "
        "{%0,%1,%2,%3}, {%4,%5,%6,%7}, {%8,%9}, {%0,%1,%2,%3};"
        : "+f"(c[0]), "+f"(c[1]), "+f"(c[2]), "+f"(c[3])
        : "r"(a[0]), "r"(a[1]), "r"(a[2]), "r"(a[3]), "r"(b[0]), "r"(b[1]));
}
__device__ __forceinline__ void cp16(uint32_t dst, const void* src) {
    asm volatile("cp.async.cg.shared.global [%0], [%1], 16;" :: "r"(dst), "l"(src));
}
__device__ __forceinline__ void bf_split(float v, __nv_bfloat16& h, __nv_bfloat16& l) {
    h = __float2bfloat16_rz(v);
    l = __float2bfloat16_rz(v - __bfloat162float(h));
}

// ---------------- init: gather embeddings, init h/c ------------------------
__global__ void init_kernel(const int* __restrict__ src, const int* __restrict__ trg,
                            const float* __restrict__ bert, const float* __restrict__ emb) {
    int idx = blockIdx.x * blockDim.x + threadIdx.x;
    if (idx < Tc*Bc*Hh) {
        int h = idx % Hh;
        int m = idx / Hh;          // m = t*Bc + b
        int b = m % Bc;
        int t = m / Bc;
        g_xs[idx] = emb[(size_t)trg[b*Tc + t] * Hh + h];
    }
    if (idx < Bc*Hh) {
        int b = idx / Hh;
        float v = bert[(size_t)src[b*Sc] * Hh + (idx % Hh)];
        __nv_bfloat16 h, l;
        bf_split(v, h, l);
        g_h0b[0][0][idx] = h; g_h0b[0][1][idx] = l;
        g_h1b[0][0][idx] = h; g_h1b[0][1][idx] = l;
        g_c0[idx] = 0.f;
        g_c1[idx] = 0.f;
    }
}

// ---------------- bf16 2-way split (W_out) ----------------------------------
__global__ void split_bf16(const float* __restrict__ x, __nv_bfloat16* __restrict__ hi,
                           __nv_bfloat16* __restrict__ lo, int n) {
    int i = blockIdx.x * 256 + threadIdx.x;
    if (i < n) {
        __nv_bfloat16 h, l;
        bf_split(x[i], h, l);
        hi[i] = h;
        lo[i] = l;
    }
}

// ---------------- recurrence weight split + permute --------------------------
// permuted row p = h*4 + gate  (gate order i,f,g,o), so a 64-col tile holds
// complete gate quadruples for 16 h's.
__global__ void wsplit(const float* __restrict__ Whh0, const float* __restrict__ Wih1,
                       const float* __restrict__ Whh1,
                       const float* __restrict__ bih1, const float* __restrict__ bhh1) {
    int i = blockIdx.x * 256 + threadIdx.x;
    const int per = G4 * Hh;
    if (i < 3*per) {
        int mat = i / per;
        int rem = i % per;
        int r = rem / Hh, k = rem % Hh;
        const float* srcp = (mat == 0) ? Whh0 : (mat == 1 ? Wih1 : Whh1);
        float v = srcp[(size_t)r*Hh + k];
        int p = (r % Hh)*4 + (r / Hh);
        __nv_bfloat16 h, l;
        bf_split(v, h, l);
        g_Wr[mat][0][(size_t)p*Hh + k] = h;
        g_Wr[mat][1][(size_t)p*Hh + k] = l;
    }
    if (i < G4) {
        int p = (i % Hh)*4 + (i / Hh);
        g_bp1[p] = bih1[i] + bhh1[i];
    }
}

// ---------------- fp32 NT GEMM (hoisted layer0 input GEMM) ------------------
__global__ __launch_bounds__(256) void gemm_nt(const float* __restrict__ W,
                                               const float* __restrict__ bias1,
                                               const float* __restrict__ bias2) {
    const float* __restrict__ A = g_xs;
    const int m0 = blockIdx.y * 128;
    const int n0 = blockIdx.x * 128;
    __shared__ __align__(16) float As[16][128];
    __shared__ __align__(16) float Bs[16][128];
    const int tid = threadIdx.x;
    const int tm0 = (tid >> 4) * 8;
    const int tn0 = (tid & 15) * 8;

    unsigned long long acc2[4][8];
    #pragma unroll
    for (int i = 0; i < 4; i++)
        #pragma unroll
        for (int j = 0; j < 8; j++) acc2[i][j] = 0ull;

    for (int kt = 0; kt < Hh/16; ++kt) {
        #pragma unroll
        for (int q = 0; q < 2; ++q) {
            int ff  = tid + q*256;
            int row = ff >> 2;
            int c4  = (ff & 3) * 4;
            float4 av = *reinterpret_cast<const float4*>(&A[(size_t)(m0+row)*Hh + kt*16 + c4]);
            float4 bv = *reinterpret_cast<const float4*>(&W[(size_t)(n0+row)*Hh + kt*16 + c4]);
            As[c4+0][row]=av.x; As[c4+1][row]=av.y; As[c4+2][row]=av.z; As[c4+3][row]=av.w;
            Bs[c4+0][row]=bv.x; Bs[c4+1][row]=bv.y; Bs[c4+2][row]=bv.z; Bs[c4+3][row]=bv.w;
        }
        __syncthreads();
        #pragma unroll
        for (int k = 0; k < 16; ++k) {
            unsigned long long a2[4];
            const unsigned long long* ap = reinterpret_cast<const unsigned long long*>(&As[k][tm0]);
            #pragma unroll
            for (int i = 0; i < 4; i++) a2[i] = ap[i];
            float4 bv0 = *reinterpret_cast<const float4*>(&Bs[k][tn0]);
            float4 bv1 = *reinterpret_cast<const float4*>(&Bs[k][tn0+4]);
            unsigned long long b2[8];
            b2[0]=pack2(bv0.x,bv0.x); b2[1]=pack2(bv0.y,bv0.y);
            b2[2]=pack2(bv0.z,bv0.z); b2[3]=pack2(bv0.w,bv0.w);
            b2[4]=pack2(bv1.x,bv1.x); b2[5]=pack2(bv1.y,bv1.y);
            b2[6]=pack2(bv1.z,bv1.z); b2[7]=pack2(bv1.w,bv1.w);
            #pragma unroll
            for (int i = 0; i < 4; i++)
                #pragma unroll
                for (int j = 0; j < 8; j++) fma2(acc2[i][j], a2[i], b2[j]);
        }
        __syncthreads();
    }

    float bias[8];
    #pragma unroll
    for (int j = 0; j < 8; j++)
        bias[j] = bias1[n0 + tn0 + j] + bias2[n0 + tn0 + j];

    #pragma unroll
    for (int i = 0; i < 4; i++) {
        float lo[8], hi[8];
        #pragma unroll
        for (int j = 0; j < 8; j++) {
            float2 u = unpack2(acc2[i][j]);
            lo[j] = u.x + bias[j];
            hi[j] = u.y + bias[j];
        }
        const int mlo = m0 + tm0 + 2*i;
        const int mhi = mlo + 1;
        float* dlo = &g_G0[(size_t)mlo * G4 + n0 + tn0];
        float* dhi = &g_G0[(size_t)mhi * G4 + n0 + tn0];
        *reinterpret_cast<float4*>(dlo)     = make_float4(lo[0],lo[1],lo[2],lo[3]);
        *reinterpret_cast<float4*>(dlo + 4) = make_float4(lo[4],lo[5],lo[6],lo[7]);
        *reinterpret_cast<float4*>(dhi)     = make_float4(hi[0],hi[1],hi[2],hi[3]);
        *reinterpret_cast<float4*>(dhi + 4) = make_float4(hi[4],hi[5],hi[6],hi[7]);
    }
}

// ---------------- mma-based pipelined recurrence step ------------------------
// 66 launches, 144 CTAs each; CTA = 128x64x768 bf16x2-split GEMM + epilogue.
//   bx  0..47 : layer0 gates  (B = permWhh0, A = h0b[s&1])      active s in [0,63]
//   bx 48..95 : layer1 input  (B = permWih1, A = h0b[s&1])      active s in [1,64] -> g_p1[(s-1)&1]
//   bx 96..143: layer1 gates  (B = permWhh1, A = h1b[s&1])      active s in [2,65], u = s-2
#define SSTAGE 24576   // Ah 8K | Al 8K | Bh 4K | Bl 4K
#define STEP_SMEM (2*SSTAGE)

__global__ __launch_bounds__(256) void step_mma(int s) {
    extern __shared__ char dsm[];
    const uint32_t base = smem_u32(dsm);
    const int tid  = threadIdx.x;
    const int bx   = blockIdx.x;
    const int lane = tid & 31;
    const int warp = tid >> 5;
    const int wm   = warp >> 2;        // 0..1 (m 64 each)
    const int wn   = warp & 3;         // 0..3 (n 16 each)
    const int lr   = lane & 15;
    const int lk   = lane >> 4;

    int role, nb;
    const __nv_bfloat16 *Bh, *Bl, *Ah, *Al;
    if (bx < 48) {
        if (s >= 64) return;
        role = 0; nb = bx;
        Bh = g_Wr[0][0]; Bl = g_Wr[0][1];
        Ah = g_h0b[s & 1][0]; Al = g_h0b[s & 1][1];
    } else if (bx < 96) {
        if (s < 1 || s > 64) return;
        role = 1; nb = bx - 48;
        Bh = g_Wr[1][0]; Bl = g_Wr[1][1];
        Ah = g_h0b[s & 1][0]; Al = g_h0b[s & 1][1];
    } else {
        if (s < 2) return;
        role = 2; nb = bx - 96;
        Bh = g_Wr[2][0]; Bl = g_Wr[2][1];
        Ah = g_h1b[s & 1][0]; Al = g_h1b[s & 1][1];
    }
    const int n0 = nb * 64;

    float acc[4][2][4];
    #pragma unroll
    for (int i = 0; i < 4; i++)
        #pragma unroll
        for (int j = 0; j < 2; j++)
            #pragma unroll
            for (int r = 0; r < 4; r++) acc[i][j][r] = 0.f;

    auto load_stage = [&](int buf, int k0) {
        const uint32_t sb = base + buf*SSTAGE;
        #pragma unroll
        for (int q = 0; q < 2; ++q) {           // A: 128 rows x 32k, hi+lo
            int id  = tid + q*256;
            int row = id >> 2, ch = id & 3;
            uint32_t off = row*64 + ((ch ^ (row & 3)) << 4);
            cp16(sb + off,        &Ah[row*Hh + k0 + ch*8]);
            cp16(sb + 8192 + off, &Al[row*Hh + k0 + ch*8]);
        }
        {                                        // B: 64 rows x 32k, hi+lo
            int row = tid >> 2, ch = tid & 3;
            uint32_t off = row*64 + ((ch ^ (row & 3)) << 4);
            cp16(sb + 16384 + off, &Bh[(size_t)(n0 + row)*Hh + k0 + ch*8]);
            cp16(sb + 20480 + off, &Bl[(size_t)(n0 + row)*Hh + k0 + ch*8]);
        }
        asm volatile("cp.async.commit_group;" ::: "memory");
    };

    load_stage(0, 0);

    for (int st = 0; st < Hh/32; ++st) {
        if (st + 1 < Hh/32) {
            load_stage((st+1) & 1, (st+1)*32);
            asm volatile("cp.async.wait_group 1;" ::: "memory");
        } else {
            asm volatile("cp.async.wait_group 0;" ::: "memory");
        }
        __syncthreads();

        const uint32_t sb = base + (st & 1)*SSTAGE;
        #pragma unroll
        for (int kk8 = 0; kk8 < 4; kk8 += 2) {
            uint32_t ah[4][4], al[4][4];
            #pragma unroll
            for (int mt = 0; mt < 4; mt++) {
                int row = wm*64 + mt*16 + lr;
                uint32_t off = row*64 + ((((kk8 + lk) ^ (row & 3))) << 4);
                LDSM4(ah[mt], sb + off);
                LDSM4(al[mt], sb + 8192 + off);
            }
            uint32_t bh[2][2], bl[2][2];
            {
                int row = wn*16 + lr;
                uint32_t off = row*64 + ((((kk8 + lk) ^ (row & 3))) << 4);
                uint32_t r[4];
                LDSM4(r, sb + 16384 + off);
                bh[0][0]=r[0]; bh[1][0]=r[1]; bh[0][1]=r[2]; bh[1][1]=r[3];
                LDSM4(r, sb + 20480 + off);
                bl[0][0]=r[0]; bl[1][0]=r[1]; bl[0][1]=r[2]; bl[1][1]=r[3];
            }
            #pragma unroll
            for (int mt = 0; mt < 4; mt++)
                #pragma unroll
                for (int nt = 0; nt < 2; nt++) {
                    mma_bf16(acc[mt][nt], ah[mt], bh[nt]);
                    mma_bf16(acc[mt][nt], ah[mt], bl[nt]);
                    mma_bf16(acc[mt][nt], al[mt], bh[nt]);
                }
        }
        __syncthreads();
    }

    if (role == 1) {
        // store layer1 input partial, permuted layout, straight from frags
        float* pbuf = g_p1[(s-1) & 1];
        #pragma unroll
        for (int mt = 0; mt < 4; mt++)
            #pragma unroll
            for (int nt = 0; nt < 2; nt++) {
                int r0  = wm*64 + mt*16 + (lane >> 2);
                int col = n0 + wn*16 + nt*8 + (lane & 3)*2;
                *reinterpret_cast<float2*>(&pbuf[(size_t)r0*G4 + col]) =
                    make_float2(acc[mt][nt][0], acc[mt][nt][1]);
                *reinterpret_cast<float2*>(&pbuf[(size_t)(r0+8)*G4 + col]) =
                    make_float2(acc[mt][nt][2], acc[mt][nt][3]);
            }
        return;
    }

    // stage gates to smem: gsh[128][68]
    float* gsh = reinterpret_cast<float*>(dsm);
    #pragma unroll
    for (int mt = 0; mt < 4; mt++)
        #pragma unroll
        for (int nt = 0; nt < 2; nt++) {
            int r0 = wm*64 + mt*16 + (lane >> 2);
            int c  = wn*16 + nt*8 + (lane & 3)*2;
            *reinterpret_cast<float2*>(&gsh[r0*68 + c]) =
                make_float2(acc[mt][nt][0], acc[mt][nt][1]);
            *reinterpret_cast<float2*>(&gsh[(r0+8)*68 + c]) =
                make_float2(acc[mt][nt][2], acc[mt][nt][3]);
        }
    __syncthreads();

    const int hg = nb * 16;
    if (role == 0) {
        __nv_bfloat16* Ho = g_h0b[(s & 1) ^ 1][0];
        __nv_bfloat16* Lo = g_h0b[(s & 1) ^ 1][1];
        for (int e = tid; e < Bc*16; e += 256) {
            int b = e >> 4, hl = e & 15;
            float4 g = *reinterpret_cast<const float4*>(&gsh[b*68 + hl*4]);
            int h = hg + hl;
            size_t gb = ((size_t)(s*Bc + b))*G4 + h;     // gate-major G0
            float gi = g.x + g_G0[gb];
            float gf = g.y + g_G0[gb +   Hh];
            float gg = g.z + g_G0[gb + 2*Hh];
            float go = g.w + g_G0[gb + 3*Hh];
            int ci = b*Hh + h;
            float si = 1.f/(1.f+expf(-gi));
            float sf = 1.f/(1.f+expf(-gf));
            float so = 1.f/(1.f+expf(-go));
            float cn = sf * g_c0[ci] + si * tanhf(gg);
            float hn = so * tanhf(cn);
            g_c0[ci] = cn;
            __nv_bfloat16 hh, ll;
            bf_split(hn, hh, ll);
            Ho[ci] = hh; Lo[ci] = ll;
        }
    } else {
        const int u = s - 2;
        const float* pbuf = g_p1[u & 1];
        __nv_bfloat16* Ho = g_h1b[(s & 1) ^ 1][0];
        __nv_bfloat16* Lo = g_h1b[(s & 1) ^ 1][1];
        for (int e = tid; e < Bc*16; e += 256) {
            int b = e >> 4, hl = e & 15;
            float4 g = *reinterpret_cast<const float4*>(&gsh[b*68 + hl*4]);
            int h = hg + hl;
            float4 p  = *reinterpret_cast<const float4*>(&pbuf[(size_t)b*G4 + h*4]);
            float4 bb = *reinterpret_cast<const float4*>(&g_bp1[h*4]);
            float gi = g.x + p.x + bb.x;
            float gf = g.y + p.y + bb.y;
            float gg = g.z + p.z + bb.z;
            float go = g.w + p.w + bb.w;
            int ci = b*Hh + h;
            float si = 1.f/(1.f+expf(-gi));
            float sf = 1.f/(1.f+expf(-gf));
            float so = 1.f/(1.f+expf(-go));
            float cn = sf * g_c1[ci] + si * tanhf(gg);
            float hn = so * tanhf(cn);
            g_c1[ci] = cn;
            __nv_bfloat16 hh, ll;
            bf_split(hn, hh, ll);
            Ho[ci] = hh; Lo[ci] = ll;
            size_t yo = ((size_t)u*Bc + b)*Hh + h;
            g_ysh[yo] = hh; g_ysl[yo] = ll;
        }
    }
}

// ---------------- mma.sync bf16x2 output projection (unchanged) --------------
#define PSTAGE   32768     // Ah 8K | Al 8K | Bh 8K | Bl 8K
#define PROJ_SMEM (2*PSTAGE)

__global__ void __launch_bounds__(256) proj_mma(const float* __restrict__ b_out,
                                                float* __restrict__ out) {
    extern __shared__ char dsm[];
    const uint32_t base = smem_u32(dsm);
    const int tid  = threadIdx.x;
    const int t    = blockIdx.x;
    const int m0   = t * 128;
    const int n0   = blockIdx.y * 128;
    const int lane = tid & 31;
    const int warp = tid >> 5;
    const int wm   = warp >> 2;
    const int wn   = warp & 3;
    const int lr   = lane & 15;
    const int lk   = lane >> 4;

    float acc[4][4][4];
    #pragma unroll
    for (int i = 0; i < 4; i++)
        #pragma unroll
        for (int j = 0; j < 4; j++)
            #pragma unroll
            for (int r = 0; r < 4; r++) acc[i][j][r] = 0.f;

    auto load_stage = [&](int buf, int k0) {
        const uint32_t sb = base + buf*PSTAGE;
        #pragma unroll
        for (int i = 0; i < 8; i++) {
            int id  = tid + i*256;
            int arr = id >> 9;
            int w   = id & 511;
            int row = w >> 2, ch = w & 3;
            uint32_t dst = sb + arr*8192 + row*64 + ((ch ^ (row & 3)) << 4);
            const __nv_bfloat16* src;
            if      (arr == 0) src = &g_ysh[(size_t)(m0 + row)*Hh + k0 + ch*8];
            else if (arr == 1) src = &g_ysl[(size_t)(m0 + row)*Hh + k0 + ch*8];
            else if (arr == 2) src = &g_Wh [(size_t)(n0 + row)*Hh + k0 + ch*8];
            else               src = &g_Wl [(size_t)(n0 + row)*Hh + k0 + ch*8];
            cp16(dst, src);
        }
        asm volatile("cp.async.commit_group;" ::: "memory");
    };

    load_stage(0, 0);

    for (int s = 0; s < Hh/32; ++s) {
        if (s + 1 < Hh/32) {
            load_stage((s+1) & 1, (s+1)*32);
            asm volatile("cp.async.wait_group 1;" ::: "memory");
        } else {
            asm volatile("cp.async.wait_group 0;" ::: "memory");
        }
        __syncthreads();

        const uint32_t sb = base + (s & 1)*PSTAGE;
        #pragma unroll
        for (int kk8 = 0; kk8 < 4; kk8 += 2) {
            uint32_t ah[4][4], al[4][4];
            #pragma unroll
            for (int mt = 0; mt < 4; mt++) {
                int row = wm*64 + mt*16 + lr;
                uint32_t off = row*64 + ((((kk8 + lk) ^ (row & 3))) << 4);
                LDSM4(ah[mt], sb + off);
                LDSM4(al[mt], sb + 8192 + off);
            }
            uint32_t bh[4][2], bl[4][2];
            #pragma unroll
            for (int np = 0; np < 2; np++) {
                int row = wn*32 + np*16 + lr;
                uint32_t off = row*64 + ((((kk8 + lk) ^ (row & 3))) << 4);
                uint32_t r[4];
                LDSM4(r, sb + 16384 + off);
                bh[np*2][0]=r[0]; bh[np*2+1][0]=r[1]; bh[np*2][1]=r[2]; bh[np*2+1][1]=r[3];
                LDSM4(r, sb + 24576 + off);
                bl[np*2][0]=r[0]; bl[np*2+1][0]=r[1]; bl[np*2][1]=r[2]; bl[np*2+1][1]=r[3];
            }
            #pragma unroll
            for (int mt = 0; mt < 4; mt++)
                #pragma unroll
                for (int nt = 0; nt < 4; nt++) {
                    mma_bf16(acc[mt][nt], ah[mt], bh[nt]);
                    mma_bf16(acc[mt][nt], ah[mt], bl[nt]);
                    mma_bf16(acc[mt][nt], al[mt], bh[nt]);
                }
        }
        __syncthreads();
    }

    #pragma unroll
    for (int nt = 0; nt < 4; nt++) {
        int col = n0 + wn*32 + nt*8 + (lane & 3)*2;
        float bb0 = b_out[col], bb1 = b_out[col + 1];
        #pragma unroll
        for (int mt = 0; mt < 4; mt++) {
            int r0 = wm*64 + mt*16 + (lane >> 2);
            float2* p0 = reinterpret_cast<float2*>(&out[((size_t)r0*Tc + t)*Vc + col]);
            *p0 = make_float2(acc[mt][nt][0] + bb0, acc[mt][nt][1] + bb1);
            float2* p1 = reinterpret_cast<float2*>(&out[((size_t)(r0+8)*Tc + t)*Vc + col]);
            *p1 = make_float2(acc[mt][nt][2] + bb0, acc[mt][nt][3] + bb1);
        }
    }
}

// ---------------- launch ----------------------------------------------------
extern "C" void kernel_launch(void* const* d_in, const int* in_sizes, int n_in,
                              void* d_out, int out_size) {
    const int*   src   = (const int*)  d_in[0];
    const int*   trg   = (const int*)  d_in[1];
    const float* bert  = (const float*)d_in[2];
    const float* emb   = (const float*)d_in[3];
    const float* W_ih  = (const float*)d_in[4];
    const float* W_hh  = (const float*)d_in[5];
    const float* b_ih  = (const float*)d_in[6];
    const float* b_hh  = (const float*)d_in[7];
    const float* W_out = (const float*)d_in[8];
    const float* b_out = (const float*)d_in[9];
    float* out = (float*)d_out;

    cudaFuncSetAttribute(proj_mma, cudaFuncAttributeMaxDynamicSharedMemorySize, PROJ_SMEM);
    cudaFuncSetAttribute(step_mma, cudaFuncAttributeMaxDynamicSharedMemorySize, STEP_SMEM);

    // 1. gather embeddings + init h/c (bf16-split h state)
    init_kernel<<<(Tc*Bc*Hh + 255)/256, 256>>>(src, trg, bert, emb);

    // 1b. split W_out into bf16 hi/lo
    __nv_bfloat16 *wh, *wl;
    cudaGetSymbolAddress((void**)&wh, g_Wh);
    cudaGetSymbolAddress((void**)&wl, g_Wl);
    split_bf16<<<(Vc*Hh + 255)/256, 256>>>(W_out, wh, wl, Vc*Hh);

    // 1c. split + permute recurrence weights, permuted layer1 bias
    const float* Whh0 = W_hh;
    const float* Wih1 = W_ih + (size_t)G4 * Hh;
    const float* Whh1 = W_hh + (size_t)G4 * Hh;
    wsplit<<<(3*G4*Hh + 255)/256, 256>>>(Whh0, Wih1, Whh1, b_ih + G4, b_hh + G4);

    // 2. hoisted layer-0 input GEMM: g_G0 = g_xs @ W_ih[0]^T + (b_ih[0]+b_hh[0])
    gemm_nt<<<dim3(G4/128, (Tc*Bc)/128), 256>>>(W_ih, b_ih, b_hh);

    // 3. pipelined recurrence on tensor cores: 66 launches cover 64 steps x 2 layers
    for (int s = 0; s <= 65; ++s)
        step_mma<<<144, 256, STEP_SMEM>>>(s);

    // 4. output projection on tensor cores (bf16x2 split, 3 MMAs)
    proj_mma<<<dim3(Tc, Vc/128), 256, PROJ_SMEM>>>(b_out, out);
}

// round 6
// speedup vs baseline: 3.1904x; 1.1857x over previous
#include <cuda_runtime.h>
#include <cuda_bf16.h>
#include <math.h>
#include <stdint.h>

// Problem constants
#define Hh   768
#define Lc   2
#define Vc   32000
#define Bc   128
#define Tc   64
#define Sc   32
#define G4   (4*Hh)   // 3072

// ---------------- scratch (device globals; no allocations allowed) ----------
__device__ __align__(128) float g_G0[(size_t)Tc*Bc*G4]; // layer0 input gates (+biases), gate-major
__device__ __align__(128) float g_c0[Bc*Hh];
__device__ __align__(128) float g_c1[Bc*Hh];
__device__ __align__(128) float g_p1[2][Bc*G4];         // layer1 input-gate partials (permuted cols)
__device__ __align__(128) float g_bp1[G4];              // permuted (b_ih[1]+b_hh[1])
__device__ __align__(128) float g_b0[G4];               // b_ih[0]+b_hh[0] (gate-major)
// xs as bf16 hi/lo (written directly by init gather)
__device__ __align__(128) __nv_bfloat16 g_xsh[Tc*Bc*Hh];
__device__ __align__(128) __nv_bfloat16 g_xsl[Tc*Bc*Hh];
// h-state as bf16 hi/lo, ping-pong
__device__ __align__(128) __nv_bfloat16 g_h0b[2][2][Bc*Hh];
__device__ __align__(128) __nv_bfloat16 g_h1b[2][2][Bc*Hh];
// recurrence weights: [mat 0=Whh0,1=Wih1,2=Whh1][hi/lo], permuted rows p = h*4+gate
__device__ __align__(128) __nv_bfloat16 g_Wr[3][2][(size_t)G4*Hh];
// W_ih[0] split (gate-major rows, unpermuted)
__device__ __align__(128) __nv_bfloat16 g_Wi0[2][(size_t)G4*Hh];
// bf16 2-way-split buffers for tensor-core projection
__device__ __align__(128) __nv_bfloat16 g_ysh[Tc*Bc*Hh];
__device__ __align__(128) __nv_bfloat16 g_ysl[Tc*Bc*Hh];
__device__ __align__(128) __nv_bfloat16 g_Wh[(size_t)Vc*Hh];
__device__ __align__(128) __nv_bfloat16 g_Wl[(size_t)Vc*Hh];

// ---------------- mma.sync helpers ------------------------------------------
__device__ __forceinline__ uint32_t smem_u32(const void* p) {
    uint32_t a;
    asm("{ .reg .u64 t; cvta.to.shared.u64 t, %1; cvt.u32.u64 %0, t; }" : "=r"(a) : "l"(p));
    return a;
}
#define LDSM4(r, a) \
    asm volatile("ldmatrix.sync.aligned.m8n8.x4.shared.b16 {%0,%1,%2,%3}, [%4];" \
        : "=r"((r)[0]), "=r"((r)[1]), "=r"((r)[2]), "=r"((r)[3]) : "r"(a))

__device__ __forceinline__ void mma_bf16(float* c, const uint32_t* a, const uint32_t* b) {
    asm volatile("mma.sync.aligned.m16n8k16.row.col.f32.bf16.bf16.f32 "
        "{%0,%1,%2,%3}, {%4,%5,%6,%7}, {%8,%9}, {%0,%1,%2,%3};"
        : "+f"(c[0]), "+f"(c[1]), "+f"(c[2]), "+f"(c[3])
        : "r"(a[0]), "r"(a[1]), "r"(a[2]), "r"(a[3]), "r"(b[0]), "r"(b[1]));
}
__device__ __forceinline__ void cp16(uint32_t dst, const void* src) {
    asm volatile("cp.async.cg.shared.global [%0], [%1], 16;" :: "r"(dst), "l"(src));
}
__device__ __forceinline__ void bf_split(float v, __nv_bfloat16& h, __nv_bfloat16& l) {
    h = __float2bfloat16_rz(v);
    l = __float2bfloat16_rz(v - __bfloat162float(h));
}

// ---------------- init: gather embeddings (split), init h/c -----------------
__global__ void init_kernel(const int* __restrict__ src, const int* __restrict__ trg,
                            const float* __restrict__ bert, const float* __restrict__ emb) {
    int idx = blockIdx.x * blockDim.x + threadIdx.x;
    if (idx < Tc*Bc*Hh) {
        int h = idx % Hh;
        int m = idx / Hh;          // m = t*Bc + b
        int b = m % Bc;
        int t = m / Bc;
        float v = emb[(size_t)trg[b*Tc + t] * Hh + h];
        __nv_bfloat16 hh, ll;
        bf_split(v, hh, ll);
        g_xsh[idx] = hh; g_xsl[idx] = ll;
    }
    if (idx < Bc*Hh) {
        int b = idx / Hh;
        float v = bert[(size_t)src[b*Sc] * Hh + (idx % Hh)];
        __nv_bfloat16 h, l;
        bf_split(v, h, l);
        g_h0b[0][0][idx] = h; g_h0b[0][1][idx] = l;
        g_h1b[0][0][idx] = h; g_h1b[0][1][idx] = l;
        g_c0[idx] = 0.f;
        g_c1[idx] = 0.f;
    }
}

// ---------------- bf16 2-way split (W_out) ----------------------------------
__global__ void split_bf16(const float* __restrict__ x, __nv_bfloat16* __restrict__ hi,
                           __nv_bfloat16* __restrict__ lo, int n) {
    int i = blockIdx.x * 256 + threadIdx.x;
    if (i < n) {
        __nv_bfloat16 h, l;
        bf_split(x[i], h, l);
        hi[i] = h;
        lo[i] = l;
    }
}

// ---------------- weight split(+permute) -------------------------------------
// mats 0..2: recurrence (permuted rows p = h*4+gate); mat 3: W_ih[0] (unpermuted)
__global__ void wsplit(const float* __restrict__ Whh0, const float* __restrict__ Wih1,
                       const float* __restrict__ Whh1, const float* __restrict__ Wih0,
                       const float* __restrict__ bih0, const float* __restrict__ bhh0,
                       const float* __restrict__ bih1, const float* __restrict__ bhh1) {
    int i = blockIdx.x * 256 + threadIdx.x;
    const int per = G4 * Hh;
    if (i < 4*per) {
        int mat = i / per;
        int rem = i % per;
        int r = rem / Hh, k = rem % Hh;
        __nv_bfloat16 h, l;
        if (mat < 3) {
            const float* srcp = (mat == 0) ? Whh0 : (mat == 1 ? Wih1 : Whh1);
            bf_split(srcp[(size_t)r*Hh + k], h, l);
            int p = (r % Hh)*4 + (r / Hh);
            g_Wr[mat][0][(size_t)p*Hh + k] = h;
            g_Wr[mat][1][(size_t)p*Hh + k] = l;
        } else {
            bf_split(Wih0[(size_t)r*Hh + k], h, l);
            g_Wi0[0][(size_t)r*Hh + k] = h;
            g_Wi0[1][(size_t)r*Hh + k] = l;
        }
    }
    if (i < G4) {
        int p = (i % Hh)*4 + (i / Hh);
        g_bp1[p] = bih1[i] + bhh1[i];
        g_b0[i]  = bih0[i] + bhh0[i];
    }
}

// ---------------- mma hoisted layer0 input GEMM ------------------------------
// g_G0[m][n] = xs[m] . W_ih0[n] + b0[n]; M=8192, N=3072, K=768.
// Same datapath as proj_mma (validated): CTA 128x128, warp 64x32, K-chunk 32.
#define GSTAGE   32768
#define GMMA_SMEM (2*GSTAGE)

__global__ void __launch_bounds__(256) gemm_mma() {
    extern __shared__ char dsm[];
    const uint32_t base = smem_u32(dsm);
    const int tid  = threadIdx.x;
    const int m0   = blockIdx.y * 128;
    const int n0   = blockIdx.x * 128;
    const int lane = tid & 31;
    const int warp = tid >> 5;
    const int wm   = warp >> 2;
    const int wn   = warp & 3;
    const int lr   = lane & 15;
    const int lk   = lane >> 4;

    float acc[4][4][4];
    #pragma unroll
    for (int i = 0; i < 4; i++)
        #pragma unroll
        for (int j = 0; j < 4; j++)
            #pragma unroll
            for (int r = 0; r < 4; r++) acc[i][j][r] = 0.f;

    auto load_stage = [&](int buf, int k0) {
        const uint32_t sb = base + buf*GSTAGE;
        #pragma unroll
        for (int i = 0; i < 8; i++) {
            int id  = tid + i*256;
            int arr = id >> 9;
            int w   = id & 511;
            int row = w >> 2, ch = w & 3;
            uint32_t dst = sb + arr*8192 + row*64 + ((ch ^ (row & 3)) << 4);
            const __nv_bfloat16* src;
            if      (arr == 0) src = &g_xsh[(size_t)(m0 + row)*Hh + k0 + ch*8];
            else if (arr == 1) src = &g_xsl[(size_t)(m0 + row)*Hh + k0 + ch*8];
            else if (arr == 2) src = &g_Wi0[0][(size_t)(n0 + row)*Hh + k0 + ch*8];
            else               src = &g_Wi0[1][(size_t)(n0 + row)*Hh + k0 + ch*8];
            cp16(dst, src);
        }
        asm volatile("cp.async.commit_group;" ::: "memory");
    };

    load_stage(0, 0);

    for (int s = 0; s < Hh/32; ++s) {
        if (s + 1 < Hh/32) {
            load_stage((s+1) & 1, (s+1)*32);
            asm volatile("cp.async.wait_group 1;" ::: "memory");
        } else {
            asm volatile("cp.async.wait_group 0;" ::: "memory");
        }
        __syncthreads();

        const uint32_t sb = base + (s & 1)*GSTAGE;
        #pragma unroll
        for (int kk8 = 0; kk8 < 4; kk8 += 2) {
            uint32_t ah[4][4], al[4][4];
            #pragma unroll
            for (int mt = 0; mt < 4; mt++) {
                int row = wm*64 + mt*16 + lr;
                uint32_t off = row*64 + ((((kk8 + lk) ^ (row & 3))) << 4);
                LDSM4(ah[mt], sb + off);
                LDSM4(al[mt], sb + 8192 + off);
            }
            uint32_t bh[4][2], bl[4][2];
            #pragma unroll
            for (int np = 0; np < 2; np++) {
                int row = wn*32 + np*16 + lr;
                uint32_t off = row*64 + ((((kk8 + lk) ^ (row & 3))) << 4);
                uint32_t r[4];
                LDSM4(r, sb + 16384 + off);
                bh[np*2][0]=r[0]; bh[np*2+1][0]=r[1]; bh[np*2][1]=r[2]; bh[np*2+1][1]=r[3];
                LDSM4(r, sb + 24576 + off);
                bl[np*2][0]=r[0]; bl[np*2+1][0]=r[1]; bl[np*2][1]=r[2]; bl[np*2+1][1]=r[3];
            }
            #pragma unroll
            for (int mt = 0; mt < 4; mt++)
                #pragma unroll
                for (int nt = 0; nt < 4; nt++) {
                    mma_bf16(acc[mt][nt], ah[mt], bh[nt]);
                    mma_bf16(acc[mt][nt], ah[mt], bl[nt]);
                    mma_bf16(acc[mt][nt], al[mt], bh[nt]);
                }
        }
        __syncthreads();
    }

    #pragma unroll
    for (int nt = 0; nt < 4; nt++) {
        int col = n0 + wn*32 + nt*8 + (lane & 3)*2;
        float bb0 = g_b0[col], bb1 = g_b0[col + 1];
        #pragma unroll
        for (int mt = 0; mt < 4; mt++) {
            int r0 = m0 + wm*64 + mt*16 + (lane >> 2);
            *reinterpret_cast<float2*>(&g_G0[(size_t)r0*G4 + col]) =
                make_float2(acc[mt][nt][0] + bb0, acc[mt][nt][1] + bb1);
            *reinterpret_cast<float2*>(&g_G0[(size_t)(r0+8)*G4 + col]) =
                make_float2(acc[mt][nt][2] + bb0, acc[mt][nt][3] + bb1);
        }
    }
}

// ---------------- mma-based pipelined recurrence step ------------------------
// 66 launches, 144 CTAs each; CTA = 128x64x768 bf16x2-split GEMM + epilogue.
// K-chunk 64 (12 iterations), full SW128 swizzle (128B rows).
//   bx  0..47 : layer0 gates  (B = permWhh0, A = h0b[s&1])      active s in [0,63]
//   bx 48..95 : layer1 input  (B = permWih1, A = h0b[s&1])      active s in [1,64] -> g_p1[(s-1)&1]
//   bx 96..143: layer1 gates  (B = permWhh1, A = h1b[s&1])      active s in [2,65], u = s-2
#define SSTAGE 49152   // Ah 16K | Al 16K | Bh 8K | Bl 8K
#define STEP_SMEM (2*SSTAGE)

__global__ __launch_bounds__(256) void step_mma(int s) {
    extern __shared__ char dsm[];
    const uint32_t base = smem_u32(dsm);
    const int tid  = threadIdx.x;
    const int bx   = blockIdx.x;
    const int lane = tid & 31;
    const int warp = tid >> 5;
    const int wm   = warp >> 2;        // 0..1 (m 64 each)
    const int wn   = warp & 3;         // 0..3 (n 16 each)
    const int lr   = lane & 15;
    const int lk   = lane >> 4;

    int role, nb;
    const __nv_bfloat16 *Bh, *Bl, *Ah, *Al;
    if (bx < 48) {
        if (s >= 64) return;
        role = 0; nb = bx;
        Bh = g_Wr[0][0]; Bl = g_Wr[0][1];
        Ah = g_h0b[s & 1][0]; Al = g_h0b[s & 1][1];
    } else if (bx < 96) {
        if (s < 1 || s > 64) return;
        role = 1; nb = bx - 48;
        Bh = g_Wr[1][0]; Bl = g_Wr[1][1];
        Ah = g_h0b[s & 1][0]; Al = g_h0b[s & 1][1];
    } else {
        if (s < 2) return;
        role = 2; nb = bx - 96;
        Bh = g_Wr[2][0]; Bl = g_Wr[2][1];
        Ah = g_h1b[s & 1][0]; Al = g_h1b[s & 1][1];
    }
    const int n0 = nb * 64;

    float acc[4][2][4];
    #pragma unroll
    for (int i = 0; i < 4; i++)
        #pragma unroll
        for (int j = 0; j < 2; j++)
            #pragma unroll
            for (int r = 0; r < 4; r++) acc[i][j][r] = 0.f;

    // k-chunk 64: 128B rows, swizzle ch ^ (row&7)
    auto load_stage = [&](int buf, int k0) {
        const uint32_t sb = base + buf*SSTAGE;
        #pragma unroll
        for (int q = 0; q < 4; ++q) {            // A: 128 rows x 8 ch, hi+lo
            int id  = tid + q*256;
            int row = id >> 3, ch = id & 7;
            uint32_t off = row*128 + ((ch ^ (row & 7)) << 4);
            cp16(sb + off,         &Ah[row*Hh + k0 + ch*8]);
            cp16(sb + 16384 + off, &Al[row*Hh + k0 + ch*8]);
        }
        #pragma unroll
        for (int q = 0; q < 2; ++q) {            // B: 64 rows x 8 ch, hi+lo
            int id  = tid + q*256;
            int row = id >> 3, ch = id & 7;
            uint32_t off = row*128 + ((ch ^ (row & 7)) << 4);
            cp16(sb + 32768 + off, &Bh[(size_t)(n0 + row)*Hh + k0 + ch*8]);
            cp16(sb + 40960 + off, &Bl[(size_t)(n0 + row)*Hh + k0 + ch*8]);
        }
        asm volatile("cp.async.commit_group;" ::: "memory");
    };

    load_stage(0, 0);

    for (int st = 0; st < Hh/64; ++st) {
        if (st + 1 < Hh/64) {
            load_stage((st+1) & 1, (st+1)*64);
            asm volatile("cp.async.wait_group 1;" ::: "memory");
        } else {
            asm volatile("cp.async.wait_group 0;" ::: "memory");
        }
        __syncthreads();

        const uint32_t sb = base + (st & 1)*SSTAGE;
        #pragma unroll
        for (int kk8 = 0; kk8 < 8; kk8 += 2) {   // 4 k16 steps per chunk
            uint32_t ah[4][4], al[4][4];
            #pragma unroll
            for (int mt = 0; mt < 4; mt++) {
                int row = wm*64 + mt*16 + lr;
                uint32_t off = row*128 + ((((kk8 + lk) ^ (row & 7))) << 4);
                LDSM4(ah[mt], sb + off);
                LDSM4(al[mt], sb + 16384 + off);
            }
            uint32_t bh[2][2], bl[2][2];
            {
                int row = wn*16 + lr;
                uint32_t off = row*128 + ((((kk8 + lk) ^ (row & 7))) << 4);
                uint32_t r[4];
                LDSM4(r, sb + 32768 + off);
                bh[0][0]=r[0]; bh[1][0]=r[1]; bh[0][1]=r[2]; bh[1][1]=r[3];
                LDSM4(r, sb + 40960 + off);
                bl[0][0]=r[0]; bl[1][0]=r[1]; bl[0][1]=r[2]; bl[1][1]=r[3];
            }
            #pragma unroll
            for (int mt = 0; mt < 4; mt++)
                #pragma unroll
                for (int nt = 0; nt < 2; nt++) {
                    mma_bf16(acc[mt][nt], ah[mt], bh[nt]);
                    mma_bf16(acc[mt][nt], ah[mt], bl[nt]);
                    mma_bf16(acc[mt][nt], al[mt], bh[nt]);
                }
        }
        __syncthreads();
    }

    if (role == 1) {
        float* pbuf = g_p1[(s-1) & 1];
        #pragma unroll
        for (int mt = 0; mt < 4; mt++)
            #pragma unroll
            for (int nt = 0; nt < 2; nt++) {
                int r0  = wm*64 + mt*16 + (lane >> 2);
                int col = n0 + wn*16 + nt*8 + (lane & 3)*2;
                *reinterpret_cast<float2*>(&pbuf[(size_t)r0*G4 + col]) =
                    make_float2(acc[mt][nt][0], acc[mt][nt][1]);
                *reinterpret_cast<float2*>(&pbuf[(size_t)(r0+8)*G4 + col]) =
                    make_float2(acc[mt][nt][2], acc[mt][nt][3]);
            }
        return;
    }

    // stage gates to smem: gsh[128][68]
    float* gsh = reinterpret_cast<float*>(dsm);
    #pragma unroll
    for (int mt = 0; mt < 4; mt++)
        #pragma unroll
        for (int nt = 0; nt < 2; nt++) {
            int r0 = wm*64 + mt*16 + (lane >> 2);
            int c  = wn*16 + nt*8 + (lane & 3)*2;
            *reinterpret_cast<float2*>(&gsh[r0*68 + c]) =
                make_float2(acc[mt][nt][0], acc[mt][nt][1]);
            *reinterpret_cast<float2*>(&gsh[(r0+8)*68 + c]) =
                make_float2(acc[mt][nt][2], acc[mt][nt][3]);
        }
    __syncthreads();

    const int hg = nb * 16;
    if (role == 0) {
        __nv_bfloat16* Ho = g_h0b[(s & 1) ^ 1][0];
        __nv_bfloat16* Lo = g_h0b[(s & 1) ^ 1][1];
        for (int e = tid; e < Bc*16; e += 256) {
            int b = e >> 4, hl = e & 15;
            float4 g = *reinterpret_cast<const float4*>(&gsh[b*68 + hl*4]);
            int h = hg + hl;
            size_t gb = ((size_t)(s*Bc + b))*G4 + h;     // gate-major G0
            float gi = g.x + g_G0[gb];
            float gf = g.y + g_G0[gb +   Hh];
            float gg = g.z + g_G0[gb + 2*Hh];
            float go = g.w + g_G0[gb + 3*Hh];
            int ci = b*Hh + h;
            float si = 1.f/(1.f+expf(-gi));
            float sf = 1.f/(1.f+expf(-gf));
            float so = 1.f/(1.f+expf(-go));
            float cn = sf * g_c0[ci] + si * tanhf(gg);
            float hn = so * tanhf(cn);
            g_c0[ci] = cn;
            __nv_bfloat16 hh, ll;
            bf_split(hn, hh, ll);
            Ho[ci] = hh; Lo[ci] = ll;
        }
    } else {
        const int u = s - 2;
        const float* pbuf = g_p1[u & 1];
        __nv_bfloat16* Ho = g_h1b[(s & 1) ^ 1][0];
        __nv_bfloat16* Lo = g_h1b[(s & 1) ^ 1][1];
        for (int e = tid; e < Bc*16; e += 256) {
            int b = e >> 4, hl = e & 15;
            float4 g = *reinterpret_cast<const float4*>(&gsh[b*68 + hl*4]);
            int h = hg + hl;
            float4 p  = *reinterpret_cast<const float4*>(&pbuf[(size_t)b*G4 + h*4]);
            float4 bb = *reinterpret_cast<const float4*>(&g_bp1[h*4]);
            float gi = g.x + p.x + bb.x;
            float gf = g.y + p.y + bb.y;
            float gg = g.z + p.z + bb.z;
            float go = g.w + p.w + bb.w;
            int ci = b*Hh + h;
            float si = 1.f/(1.f+expf(-gi));
            float sf = 1.f/(1.f+expf(-gf));
            float so = 1.f/(1.f+expf(-go));
            float cn = sf * g_c1[ci] + si * tanhf(gg);
            float hn = so * tanhf(cn);
            g_c1[ci] = cn;
            __nv_bfloat16 hh, ll;
            bf_split(hn, hh, ll);
            Ho[ci] = hh; Lo[ci] = ll;
            size_t yo = ((size_t)u*Bc + b)*Hh + h;
            g_ysh[yo] = hh; g_ysl[yo] = ll;
        }
    }
}

// ---------------- mma.sync bf16x2 output projection (unchanged) --------------
#define PSTAGE   32768     // Ah 8K | Al 8K | Bh 8K | Bl 8K
#define PROJ_SMEM (2*PSTAGE)

__global__ void __launch_bounds__(256) proj_mma(const float* __restrict__ b_out,
                                                float* __restrict__ out) {
    extern __shared__ char dsm[];
    const uint32_t base = smem_u32(dsm);
    const int tid  = threadIdx.x;
    const int t    = blockIdx.x;
    const int m0   = t * 128;
    const int n0   = blockIdx.y * 128;
    const int lane = tid & 31;
    const int warp = tid >> 5;
    const int wm   = warp >> 2;
    const int wn   = warp & 3;
    const int lr   = lane & 15;
    const int lk   = lane >> 4;

    float acc[4][4][4];
    #pragma unroll
    for (int i = 0; i < 4; i++)
        #pragma unroll
        for (int j = 0; j < 4; j++)
            #pragma unroll
            for (int r = 0; r < 4; r++) acc[i][j][r] = 0.f;

    auto load_stage = [&](int buf, int k0) {
        const uint32_t sb = base + buf*PSTAGE;
        #pragma unroll
        for (int i = 0; i < 8; i++) {
            int id  = tid + i*256;
            int arr = id >> 9;
            int w   = id & 511;
            int row = w >> 2, ch = w & 3;
            uint32_t dst = sb + arr*8192 + row*64 + ((ch ^ (row & 3)) << 4);
            const __nv_bfloat16* src;
            if      (arr == 0) src = &g_ysh[(size_t)(m0 + row)*Hh + k0 + ch*8];
            else if (arr == 1) src = &g_ysl[(size_t)(m0 + row)*Hh + k0 + ch*8];
            else if (arr == 2) src = &g_Wh [(size_t)(n0 + row)*Hh + k0 + ch*8];
            else               src = &g_Wl [(size_t)(n0 + row)*Hh + k0 + ch*8];
            cp16(dst, src);
        }
        asm volatile("cp.async.commit_group;" ::: "memory");
    };

    load_stage(0, 0);

    for (int s = 0; s < Hh/32; ++s) {
        if (s + 1 < Hh/32) {
            load_stage((s+1) & 1, (s+1)*32);
            asm volatile("cp.async.wait_group 1;" ::: "memory");
        } else {
            asm volatile("cp.async.wait_group 0;" ::: "memory");
        }
        __syncthreads();

        const uint32_t sb = base + (s & 1)*PSTAGE;
        #pragma unroll
        for (int kk8 = 0; kk8 < 4; kk8 += 2) {
            uint32_t ah[4][4], al[4][4];
            #pragma unroll
            for (int mt = 0; mt < 4; mt++) {
                int row = wm*64 + mt*16 + lr;
                uint32_t off = row*64 + ((((kk8 + lk) ^ (row & 3))) << 4);
                LDSM4(ah[mt], sb + off);
                LDSM4(al[mt], sb + 8192 + off);
            }
            uint32_t bh[4][2], bl[4][2];
            #pragma unroll
            for (int np = 0; np < 2; np++) {
                int row = wn*32 + np*16 + lr;
                uint32_t off = row*64 + ((((kk8 + lk) ^ (row & 3))) << 4);
                uint32_t r[4];
                LDSM4(r, sb + 16384 + off);
                bh[np*2][0]=r[0]; bh[np*2+1][0]=r[1]; bh[np*2][1]=r[2]; bh[np*2+1][1]=r[3];
                LDSM4(r, sb + 24576 + off);
                bl[np*2][0]=r[0]; bl[np*2+1][0]=r[1]; bl[np*2][1]=r[2]; bl[np*2+1][1]=r[3];
            }
            #pragma unroll
            for (int mt = 0; mt < 4; mt++)
                #pragma unroll
                for (int nt = 0; nt < 4; nt++) {
                    mma_bf16(acc[mt][nt], ah[mt], bh[nt]);
                    mma_bf16(acc[mt][nt], ah[mt], bl[nt]);
                    mma_bf16(acc[mt][nt], al[mt], bh[nt]);
                }
        }
        __syncthreads();
    }

    #pragma unroll
    for (int nt = 0; nt < 4; nt++) {
        int col = n0 + wn*32 + nt*8 + (lane & 3)*2;
        float bb0 = b_out[col], bb1 = b_out[col + 1];
        #pragma unroll
        for (int mt = 0; mt < 4; mt++) {
            int r0 = wm*64 + mt*16 + (lane >> 2);
            float2* p0 = reinterpret_cast<float2*>(&out[((size_t)r0*Tc + t)*Vc + col]);
            *p0 = make_float2(acc[mt][nt][0] + bb0, acc[mt][nt][1] + bb1);
            float2* p1 = reinterpret_cast<float2*>(&out[((size_t)(r0+8)*Tc + t)*Vc + col]);
            *p1 = make_float2(acc[mt][nt][2] + bb0, acc[mt][nt][3] + bb1);
        }
    }
}

// ---------------- launch ----------------------------------------------------
extern "C" void kernel_launch(void* const* d_in, const int* in_sizes, int n_in,
                              void* d_out, int out_size) {
    const int*   src   = (const int*)  d_in[0];
    const int*   trg   = (const int*)  d_in[1];
    const float* bert  = (const float*)d_in[2];
    const float* emb   = (const float*)d_in[3];
    const float* W_ih  = (const float*)d_in[4];
    const float* W_hh  = (const float*)d_in[5];
    const float* b_ih  = (const float*)d_in[6];
    const float* b_hh  = (const float*)d_in[7];
    const float* W_out = (const float*)d_in[8];
    const float* b_out = (const float*)d_in[9];
    float* out = (float*)d_out;

    cudaFuncSetAttribute(proj_mma, cudaFuncAttributeMaxDynamicSharedMemorySize, PROJ_SMEM);
    cudaFuncSetAttribute(step_mma, cudaFuncAttributeMaxDynamicSharedMemorySize, STEP_SMEM);
    cudaFuncSetAttribute(gemm_mma, cudaFuncAttributeMaxDynamicSharedMemorySize, GMMA_SMEM);

    // 1. gather embeddings (bf16-split xs) + init h/c
    init_kernel<<<(Tc*Bc*Hh + 255)/256, 256>>>(src, trg, bert, emb);

    // 1b. split W_out into bf16 hi/lo
    __nv_bfloat16 *wh, *wl;
    cudaGetSymbolAddress((void**)&wh, g_Wh);
    cudaGetSymbolAddress((void**)&wl, g_Wl);
    split_bf16<<<(Vc*Hh + 255)/256, 256>>>(W_out, wh, wl, Vc*Hh);

    // 1c. split (+permute) all LSTM weights + biases
    const float* Wih0 = W_ih;
    const float* Whh0 = W_hh;
    const float* Wih1 = W_ih + (size_t)G4 * Hh;
    const float* Whh1 = W_hh + (size_t)G4 * Hh;
    wsplit<<<(4*G4*Hh + 255)/256, 256>>>(Whh0, Wih1, Whh1, Wih0,
                                         b_ih, b_hh, b_ih + G4, b_hh + G4);

    // 2. hoisted layer-0 input GEMM on tensor cores
    gemm_mma<<<dim3(G4/128, (Tc*Bc)/128), 256, GMMA_SMEM>>>();

    // 3. pipelined recurrence on tensor cores: 66 launches cover 64 steps x 2 layers
    for (int s = 0; s <= 65; ++s)
        step_mma<<<144, 256, STEP_SMEM>>>(s);

    // 4. output projection on tensor cores (bf16x2 split, 3 MMAs)
    proj_mma<<<dim3(Tc, Vc/128), 256, PROJ_SMEM>>>(b_out, out);
}

// round 7
// speedup vs baseline: 3.2487x; 1.0183x over previous
#include <cuda_runtime.h>
#include <cuda_bf16.h>
#include <math.h>
#include <stdint.h>

// Problem constants
#define Hh   768
#define Lc   2
#define Vc   32000
#define Bc   128
#define Tc   64
#define Sc   32
#define G4   (4*Hh)   // 3072

// ---------------- scratch (device globals; no allocations allowed) ----------
__device__ __align__(128) float g_G0[(size_t)Tc*Bc*G4]; // layer0 input gates (+biases), gate-major
__device__ __align__(128) float g_c0[Bc*Hh];
__device__ __align__(128) float g_c1[Bc*Hh];
__device__ __align__(128) float g_p1[2][Bc*G4];         // layer1 input-gate partials (permuted cols)
__device__ __align__(128) float g_bp1[G4];              // permuted (b_ih[1]+b_hh[1])
__device__ __align__(128) float g_b0[G4];               // b_ih[0]+b_hh[0] (gate-major)
__device__ unsigned g_bar;                              // grid barrier counter
// xs as bf16 hi/lo (written directly by init gather)
__device__ __align__(128) __nv_bfloat16 g_xsh[Tc*Bc*Hh];
__device__ __align__(128) __nv_bfloat16 g_xsl[Tc*Bc*Hh];
// h-state as bf16 hi/lo, ping-pong
__device__ __align__(128) __nv_bfloat16 g_h0b[2][2][Bc*Hh];
__device__ __align__(128) __nv_bfloat16 g_h1b[2][2][Bc*Hh];
// recurrence weights: [mat 0=Whh0,1=Wih1,2=Whh1][hi/lo], permuted rows p = h*4+gate
__device__ __align__(128) __nv_bfloat16 g_Wr[3][2][(size_t)G4*Hh];
// W_ih[0] split (gate-major rows, unpermuted)
__device__ __align__(128) __nv_bfloat16 g_Wi0[2][(size_t)G4*Hh];
// bf16 2-way-split buffers for tensor-core projection
__device__ __align__(128) __nv_bfloat16 g_ysh[Tc*Bc*Hh];
__device__ __align__(128) __nv_bfloat16 g_ysl[Tc*Bc*Hh];
__device__ __align__(128) __nv_bfloat16 g_Wh[(size_t)Vc*Hh];
__device__ __align__(128) __nv_bfloat16 g_Wl[(size_t)Vc*Hh];

// ---------------- mma.sync helpers ------------------------------------------
__device__ __forceinline__ uint32_t smem_u32(const void* p) {
    uint32_t a;
    asm("{ .reg .u64 t; cvta.to.shared.u64 t, %1; cvt.u32.u64 %0, t; }" : "=r"(a) : "l"(p));
    return a;
}
#define LDSM4(r, a) \
    asm volatile("ldmatrix.sync.aligned.m8n8.x4.shared.b16 {%0,%1,%2,%3}, [%4];" \
        : "=r"((r)[0]), "=r"((r)[1]), "=r"((r)[2]), "=r"((r)[3]) : "r"(a))

__device__ __forceinline__ void mma_bf16(float* c, const uint32_t* a, const uint32_t* b) {
    asm volatile("mma.sync.aligned.m16n8k16.row.col.f32.bf16.bf16.f32 "
        "{%0,%1,%2,%3}, {%4,%5,%6,%7}, {%8,%9}, {%0,%1,%2,%3};"
        : "+f"(c[0]), "+f"(c[1]), "+f"(c[2]), "+f"(c[3])
        : "r"(a[0]), "r"(a[1]), "r"(a[2]), "r"(a[3]), "r"(b[0]), "r"(b[1]));
}
__device__ __forceinline__ void cp16(uint32_t dst, const void* src) {       // L2-only (cg)
    asm volatile("cp.async.cg.shared.global [%0], [%1], 16;" :: "r"(dst), "l"(src));
}
__device__ __forceinline__ void cp16ca(uint32_t dst, const void* src) {     // L1-cacheable
    asm volatile("cp.async.ca.shared.global [%0], [%1], 16;" :: "r"(dst), "l"(src));
}
__device__ __forceinline__ void bf_split(float v, __nv_bfloat16& h, __nv_bfloat16& l) {
    h = __float2bfloat16_rz(v);
    l = __float2bfloat16_rz(v - __bfloat162float(h));
}

// ---------------- init: gather embeddings (split), init h/c -----------------
__global__ void init_kernel(const int* __restrict__ src, const int* __restrict__ trg,
                            const float* __restrict__ bert, const float* __restrict__ emb) {
    int idx = blockIdx.x * blockDim.x + threadIdx.x;
    if (idx == 0) g_bar = 0;                       // reset grid barrier each run
    if (idx < Tc*Bc*Hh) {
        int h = idx % Hh;
        int m = idx / Hh;          // m = t*Bc + b
        int b = m % Bc;
        int t = m / Bc;
        float v = emb[(size_t)trg[b*Tc + t] * Hh + h];
        __nv_bfloat16 hh, ll;
        bf_split(v, hh, ll);
        g_xsh[idx] = hh; g_xsl[idx] = ll;
    }
    if (idx < Bc*Hh) {
        int b = idx / Hh;
        float v = bert[(size_t)src[b*Sc] * Hh + (idx % Hh)];
        __nv_bfloat16 h, l;
        bf_split(v, h, l);
        g_h0b[0][0][idx] = h; g_h0b[0][1][idx] = l;
        g_h1b[0][0][idx] = h; g_h1b[0][1][idx] = l;
        g_c0[idx] = 0.f;
        g_c1[idx] = 0.f;
    }
}

// ---------------- bf16 2-way split (W_out) ----------------------------------
__global__ void split_bf16(const float* __restrict__ x, __nv_bfloat16* __restrict__ hi,
                           __nv_bfloat16* __restrict__ lo, int n) {
    int i = blockIdx.x * 256 + threadIdx.x;
    if (i < n) {
        __nv_bfloat16 h, l;
        bf_split(x[i], h, l);
        hi[i] = h;
        lo[i] = l;
    }
}

// ---------------- weight split(+permute) -------------------------------------
__global__ void wsplit(const float* __restrict__ Whh0, const float* __restrict__ Wih1,
                       const float* __restrict__ Whh1, const float* __restrict__ Wih0,
                       const float* __restrict__ bih0, const float* __restrict__ bhh0,
                       const float* __restrict__ bih1, const float* __restrict__ bhh1) {
    int i = blockIdx.x * 256 + threadIdx.x;
    const int per = G4 * Hh;
    if (i < 4*per) {
        int mat = i / per;
        int rem = i % per;
        int r = rem / Hh, k = rem % Hh;
        __nv_bfloat16 h, l;
        if (mat < 3) {
            const float* srcp = (mat == 0) ? Whh0 : (mat == 1 ? Wih1 : Whh1);
            bf_split(srcp[(size_t)r*Hh + k], h, l);
            int p = (r % Hh)*4 + (r / Hh);
            g_Wr[mat][0][(size_t)p*Hh + k] = h;
            g_Wr[mat][1][(size_t)p*Hh + k] = l;
        } else {
            bf_split(Wih0[(size_t)r*Hh + k], h, l);
            g_Wi0[0][(size_t)r*Hh + k] = h;
            g_Wi0[1][(size_t)r*Hh + k] = l;
        }
    }
    if (i < G4) {
        int p = (i % Hh)*4 + (i / Hh);
        g_bp1[p] = bih1[i] + bhh1[i];
        g_b0[i]  = bih0[i] + bhh0[i];
    }
}

// ---------------- mma hoisted layer0 input GEMM (3-stage pipeline) -----------
#define GSTAGE   32768
#define GMMA_SMEM (3*GSTAGE)

__global__ void __launch_bounds__(256) gemm_mma() {
    extern __shared__ char dsm[];
    const uint32_t base = smem_u32(dsm);
    const int tid  = threadIdx.x;
    const int m0   = blockIdx.y * 128;
    const int n0   = blockIdx.x * 128;
    const int lane = tid & 31;
    const int warp = tid >> 5;
    const int wm   = warp >> 2;
    const int wn   = warp & 3;
    const int lr   = lane & 15;
    const int lk   = lane >> 4;
    const int NS   = Hh/32;

    float acc[4][4][4];
    #pragma unroll
    for (int i = 0; i < 4; i++)
        #pragma unroll
        for (int j = 0; j < 4; j++)
            #pragma unroll
            for (int r = 0; r < 4; r++) acc[i][j][r] = 0.f;

    auto load_stage = [&](int buf, int k0) {
        const uint32_t sb = base + buf*GSTAGE;
        #pragma unroll
        for (int i = 0; i < 8; i++) {
            int id  = tid + i*256;
            int arr = id >> 9;
            int w   = id & 511;
            int row = w >> 2, ch = w & 3;
            uint32_t dst = sb + arr*8192 + row*64 + ((ch ^ (row & 3)) << 4);
            const __nv_bfloat16* src;
            if      (arr == 0) src = &g_xsh[(size_t)(m0 + row)*Hh + k0 + ch*8];
            else if (arr == 1) src = &g_xsl[(size_t)(m0 + row)*Hh + k0 + ch*8];
            else if (arr == 2) src = &g_Wi0[0][(size_t)(n0 + row)*Hh + k0 + ch*8];
            else               src = &g_Wi0[1][(size_t)(n0 + row)*Hh + k0 + ch*8];
            cp16(dst, src);
        }
        asm volatile("cp.async.commit_group;" ::: "memory");
    };

    load_stage(0, 0);
    load_stage(1, 32);

    for (int s = 0; s < NS; ++s) {
        if (s + 1 < NS) { asm volatile("cp.async.wait_group 1;" ::: "memory"); }
        else            { asm volatile("cp.async.wait_group 0;" ::: "memory"); }
        __syncthreads();
        if (s + 2 < NS) load_stage((s+2)%3, (s+2)*32);

        const uint32_t sb = base + (s%3)*GSTAGE;
        #pragma unroll
        for (int kk8 = 0; kk8 < 4; kk8 += 2) {
            uint32_t ah[4][4], al[4][4];
            #pragma unroll
            for (int mt = 0; mt < 4; mt++) {
                int row = wm*64 + mt*16 + lr;
                uint32_t off = row*64 + ((((kk8 + lk) ^ (row & 3))) << 4);
                LDSM4(ah[mt], sb + off);
                LDSM4(al[mt], sb + 8192 + off);
            }
            uint32_t bh[4][2], bl[4][2];
            #pragma unroll
            for (int np = 0; np < 2; np++) {
                int row = wn*32 + np*16 + lr;
                uint32_t off = row*64 + ((((kk8 + lk) ^ (row & 3))) << 4);
                uint32_t r[4];
                LDSM4(r, sb + 16384 + off);
                bh[np*2][0]=r[0]; bh[np*2+1][0]=r[1]; bh[np*2][1]=r[2]; bh[np*2+1][1]=r[3];
                LDSM4(r, sb + 24576 + off);
                bl[np*2][0]=r[0]; bl[np*2+1][0]=r[1]; bl[np*2][1]=r[2]; bl[np*2+1][1]=r[3];
            }
            #pragma unroll
            for (int mt = 0; mt < 4; mt++)
                #pragma unroll
                for (int nt = 0; nt < 4; nt++) {
                    mma_bf16(acc[mt][nt], ah[mt], bh[nt]);
                    mma_bf16(acc[mt][nt], ah[mt], bl[nt]);
                    mma_bf16(acc[mt][nt], al[mt], bh[nt]);
                }
        }
    }

    #pragma unroll
    for (int nt = 0; nt < 4; nt++) {
        int col = n0 + wn*32 + nt*8 + (lane & 3)*2;
        float bb0 = g_b0[col], bb1 = g_b0[col + 1];
        #pragma unroll
        for (int mt = 0; mt < 4; mt++) {
            int r0 = m0 + wm*64 + mt*16 + (lane >> 2);
            *reinterpret_cast<float2*>(&g_G0[(size_t)r0*G4 + col]) =
                make_float2(acc[mt][nt][0] + bb0, acc[mt][nt][1] + bb1);
            *reinterpret_cast<float2*>(&g_G0[(size_t)(r0+8)*G4 + col]) =
                make_float2(acc[mt][nt][2] + bb0, acc[mt][nt][3] + bb1);
        }
    }
}

// ---------------- persistent mma recurrence ----------------------------------
// ONE launch, 144 CTAs, 66 pipeline slots separated by a gpu-scope grid barrier.
//   bx  0..47 : layer0 gates  (B = permWhh0, A = h0b[s&1])      active s in [0,63]
//   bx 48..95 : layer1 input  (B = permWih1, A = h0b[s&1])      active s in [1,64] -> g_p1[(s-1)&1]
//   bx 96..143: layer1 gates  (B = permWhh1, A = h1b[s&1])      active s in [2,65], u = s-2
// Cross-CTA data: A via cp.async.cg (L2), p1 epilogue via __ldcg; weights cp.async.ca.
#define SSTAGE 49152   // Ah 16K | Al 16K | Bh 8K | Bl 8K
#define STEP_SMEM (2*SSTAGE)
#define NSLOTS 66
#define GRID_STEP 144

__global__ __launch_bounds__(256) void step_persist() {
    extern __shared__ char dsm[];
    const uint32_t base = smem_u32(dsm);
    const int tid  = threadIdx.x;
    const int bx   = blockIdx.x;
    const int lane = tid & 31;
    const int warp = tid >> 5;
    const int wm   = warp >> 2;        // 0..1 (m 64 each)
    const int wn   = warp & 3;         // 0..3 (n 16 each)
    const int lr   = lane & 15;
    const int lk   = lane >> 4;

    int role, nb;
    const __nv_bfloat16 *Bh, *Bl;
    if (bx < 48)      { role = 0; nb = bx;      Bh = g_Wr[0][0]; Bl = g_Wr[0][1]; }
    else if (bx < 96) { role = 1; nb = bx - 48; Bh = g_Wr[1][0]; Bl = g_Wr[1][1]; }
    else              { role = 2; nb = bx - 96; Bh = g_Wr[2][0]; Bl = g_Wr[2][1]; }
    const int n0 = nb * 64;
    float* gsh = reinterpret_cast<float*>(dsm);

    for (int s = 0; s < NSLOTS; ++s) {
        bool active = (role == 0) ? (s < 64) : (role == 1) ? (s >= 1 && s <= 64) : (s >= 2);
        if (active) {
            const __nv_bfloat16* Ah = (role == 2) ? g_h1b[s & 1][0] : g_h0b[s & 1][0];
            const __nv_bfloat16* Al = (role == 2) ? g_h1b[s & 1][1] : g_h0b[s & 1][1];

            float acc[4][2][4];
            #pragma unroll
            for (int i = 0; i < 4; i++)
                #pragma unroll
                for (int j = 0; j < 2; j++)
                    #pragma unroll
                    for (int r = 0; r < 4; r++) acc[i][j][r] = 0.f;

            auto load_stage = [&](int buf, int k0) {
                const uint32_t sb = base + buf*SSTAGE;
                #pragma unroll
                for (int q = 0; q < 4; ++q) {            // A: cg (cross-CTA, L2-coherent)
                    int id  = tid + q*256;
                    int row = id >> 3, ch = id & 7;
                    uint32_t off = row*128 + ((ch ^ (row & 7)) << 4);
                    cp16(sb + off,         &Ah[row*Hh + k0 + ch*8]);
                    cp16(sb + 16384 + off, &Al[row*Hh + k0 + ch*8]);
                }
                #pragma unroll
                for (int q = 0; q < 2; ++q) {            // B: ca (read-only weights)
                    int id  = tid + q*256;
                    int row = id >> 3, ch = id & 7;
                    uint32_t off = row*128 + ((ch ^ (row & 7)) << 4);
                    cp16ca(sb + 32768 + off, &Bh[(size_t)(n0 + row)*Hh + k0 + ch*8]);
                    cp16ca(sb + 40960 + off, &Bl[(size_t)(n0 + row)*Hh + k0 + ch*8]);
                }
                asm volatile("cp.async.commit_group;" ::: "memory");
            };

            load_stage(0, 0);

            for (int st = 0; st < Hh/64; ++st) {
                if (st + 1 < Hh/64) {
                    load_stage((st+1) & 1, (st+1)*64);
                    asm volatile("cp.async.wait_group 1;" ::: "memory");
                } else {
                    asm volatile("cp.async.wait_group 0;" ::: "memory");
                }
                __syncthreads();

                const uint32_t sb = base + (st & 1)*SSTAGE;
                #pragma unroll
                for (int kk8 = 0; kk8 < 8; kk8 += 2) {
                    uint32_t ah[4][4], al[4][4];
                    #pragma unroll
                    for (int mt = 0; mt < 4; mt++) {
                        int row = wm*64 + mt*16 + lr;
                        uint32_t off = row*128 + ((((kk8 + lk) ^ (row & 7))) << 4);
                        LDSM4(ah[mt], sb + off);
                        LDSM4(al[mt], sb + 16384 + off);
                    }
                    uint32_t bh[2][2], bl[2][2];
                    {
                        int row = wn*16 + lr;
                        uint32_t off = row*128 + ((((kk8 + lk) ^ (row & 7))) << 4);
                        uint32_t r[4];
                        LDSM4(r, sb + 32768 + off);
                        bh[0][0]=r[0]; bh[1][0]=r[1]; bh[0][1]=r[2]; bh[1][1]=r[3];
                        LDSM4(r, sb + 40960 + off);
                        bl[0][0]=r[0]; bl[1][0]=r[1]; bl[0][1]=r[2]; bl[1][1]=r[3];
                    }
                    #pragma unroll
                    for (int mt = 0; mt < 4; mt++)
                        #pragma unroll
                        for (int nt = 0; nt < 2; nt++) {
                            mma_bf16(acc[mt][nt], ah[mt], bh[nt]);
                            mma_bf16(acc[mt][nt], ah[mt], bl[nt]);
                            mma_bf16(acc[mt][nt], al[mt], bh[nt]);
                        }
                }
                __syncthreads();
            }

            if (role == 1) {
                float* pbuf = g_p1[(s-1) & 1];
                #pragma unroll
                for (int mt = 0; mt < 4; mt++)
                    #pragma unroll
                    for (int nt = 0; nt < 2; nt++) {
                        int r0  = wm*64 + mt*16 + (lane >> 2);
                        int col = n0 + wn*16 + nt*8 + (lane & 3)*2;
                        *reinterpret_cast<float2*>(&pbuf[(size_t)r0*G4 + col]) =
                            make_float2(acc[mt][nt][0], acc[mt][nt][1]);
                        *reinterpret_cast<float2*>(&pbuf[(size_t)(r0+8)*G4 + col]) =
                            make_float2(acc[mt][nt][2], acc[mt][nt][3]);
                    }
            } else {
                // stage gates to smem: gsh[128][68]
                #pragma unroll
                for (int mt = 0; mt < 4; mt++)
                    #pragma unroll
                    for (int nt = 0; nt < 2; nt++) {
                        int r0 = wm*64 + mt*16 + (lane >> 2);
                        int c  = wn*16 + nt*8 + (lane & 3)*2;
                        *reinterpret_cast<float2*>(&gsh[r0*68 + c]) =
                            make_float2(acc[mt][nt][0], acc[mt][nt][1]);
                        *reinterpret_cast<float2*>(&gsh[(r0+8)*68 + c]) =
                            make_float2(acc[mt][nt][2], acc[mt][nt][3]);
                    }
                __syncthreads();

                const int hg = nb * 16;
                if (role == 0) {
                    __nv_bfloat16* Ho = g_h0b[(s & 1) ^ 1][0];
                    __nv_bfloat16* Lo = g_h0b[(s & 1) ^ 1][1];
                    for (int e = tid; e < Bc*16; e += 256) {
                        int b = e >> 4, hl = e & 15;
                        float4 g = *reinterpret_cast<const float4*>(&gsh[b*68 + hl*4]);
                        int h = hg + hl;
                        size_t gb = ((size_t)(s*Bc + b))*G4 + h;
                        float gi = g.x + g_G0[gb];
                        float gf = g.y + g_G0[gb +   Hh];
                        float gg = g.z + g_G0[gb + 2*Hh];
                        float go = g.w + g_G0[gb + 3*Hh];
                        int ci = b*Hh + h;
                        float si = 1.f/(1.f+expf(-gi));
                        float sf = 1.f/(1.f+expf(-gf));
                        float so = 1.f/(1.f+expf(-go));
                        float cn = sf * g_c0[ci] + si * tanhf(gg);
                        float hn = so * tanhf(cn);
                        g_c0[ci] = cn;
                        __nv_bfloat16 hh, ll;
                        bf_split(hn, hh, ll);
                        Ho[ci] = hh; Lo[ci] = ll;
                    }
                } else {
                    const int u = s - 2;
                    const float* pbuf = g_p1[u & 1];
                    __nv_bfloat16* Ho = g_h1b[(s & 1) ^ 1][0];
                    __nv_bfloat16* Lo = g_h1b[(s & 1) ^ 1][1];
                    for (int e = tid; e < Bc*16; e += 256) {
                        int b = e >> 4, hl = e & 15;
                        float4 g = *reinterpret_cast<const float4*>(&gsh[b*68 + hl*4]);
                        int h = hg + hl;
                        float4 p  = __ldcg(reinterpret_cast<const float4*>(&pbuf[(size_t)b*G4 + h*4]));
                        float4 bb = *reinterpret_cast<const float4*>(&g_bp1[h*4]);
                        float gi = g.x + p.x + bb.x;
                        float gf = g.y + p.y + bb.y;
                        float gg = g.z + p.z + bb.z;
                        float go = g.w + p.w + bb.w;
                        int ci = b*Hh + h;
                        float si = 1.f/(1.f+expf(-gi));
                        float sf = 1.f/(1.f+expf(-gf));
                        float so = 1.f/(1.f+expf(-go));
                        float cn = sf * g_c1[ci] + si * tanhf(gg);
                        float hn = so * tanhf(cn);
                        g_c1[ci] = cn;
                        __nv_bfloat16 hh, ll;
                        bf_split(hn, hh, ll);
                        Ho[ci] = hh; Lo[ci] = ll;
                        size_t yo = ((size_t)u*Bc + b)*Hh + h;
                        g_ysh[yo] = hh; g_ysl[yo] = ll;
                    }
                }
            }
        }

        // ---- grid barrier (skip after last slot) ----
        if (s + 1 < NSLOTS) {
            __syncthreads();
            if (tid == 0) {
                unsigned* bar = &g_bar;
                asm volatile("red.release.gpu.global.add.u32 [%0], 1;" :: "l"(bar) : "memory");
                unsigned target = (unsigned)GRID_STEP * (unsigned)(s + 1);
                unsigned v;
                do {
                    asm volatile("ld.acquire.gpu.global.u32 %0, [%1];" : "=r"(v) : "l"(bar) : "memory");
                    if (v >= target) break;
                    asm volatile("nanosleep.u32 64;");
                } while (true);
            }
            __syncthreads();
        }
    }
}

// ---------------- mma.sync bf16x2 output projection (3-stage pipeline) -------
#define PSTAGE   32768     // Ah 8K | Al 8K | Bh 8K | Bl 8K
#define PROJ_SMEM (3*PSTAGE)

__global__ void __launch_bounds__(256) proj_mma(const float* __restrict__ b_out,
                                                float* __restrict__ out) {
    extern __shared__ char dsm[];
    const uint32_t base = smem_u32(dsm);
    const int tid  = threadIdx.x;
    const int t    = blockIdx.x;
    const int m0   = t * 128;
    const int n0   = blockIdx.y * 128;
    const int lane = tid & 31;
    const int warp = tid >> 5;
    const int wm   = warp >> 2;
    const int wn   = warp & 3;
    const int lr   = lane & 15;
    const int lk   = lane >> 4;
    const int NS   = Hh/32;

    float acc[4][4][4];
    #pragma unroll
    for (int i = 0; i < 4; i++)
        #pragma unroll
        for (int j = 0; j < 4; j++)
            #pragma unroll
            for (int r = 0; r < 4; r++) acc[i][j][r] = 0.f;

    auto load_stage = [&](int buf, int k0) {
        const uint32_t sb = base + buf*PSTAGE;
        #pragma unroll
        for (int i = 0; i < 8; i++) {
            int id  = tid + i*256;
            int arr = id >> 9;
            int w   = id & 511;
            int row = w >> 2, ch = w & 3;
            uint32_t dst = sb + arr*8192 + row*64 + ((ch ^ (row & 3)) << 4);
            const __nv_bfloat16* src;
            if      (arr == 0) src = &g_ysh[(size_t)(m0 + row)*Hh + k0 + ch*8];
            else if (arr == 1) src = &g_ysl[(size_t)(m0 + row)*Hh + k0 + ch*8];
            else if (arr == 2) src = &g_Wh [(size_t)(n0 + row)*Hh + k0 + ch*8];
            else               src = &g_Wl [(size_t)(n0 + row)*Hh + k0 + ch*8];
            cp16(dst, src);
        }
        asm volatile("cp.async.commit_group;" ::: "memory");
    };

    load_stage(0, 0);
    load_stage(1, 32);

    for (int s = 0; s < NS; ++s) {
        if (s + 1 < NS) { asm volatile("cp.async.wait_group 1;" ::: "memory"); }
        else            { asm volatile("cp.async.wait_group 0;" ::: "memory"); }
        __syncthreads();
        if (s + 2 < NS) load_stage((s+2)%3, (s+2)*32);

        const uint32_t sb = base + (s%3)*PSTAGE;
        #pragma unroll
        for (int kk8 = 0; kk8 < 4; kk8 += 2) {
            uint32_t ah[4][4], al[4][4];
            #pragma unroll
            for (int mt = 0; mt < 4; mt++) {
                int row = wm*64 + mt*16 + lr;
                uint32_t off = row*64 + ((((kk8 + lk) ^ (row & 3))) << 4);
                LDSM4(ah[mt], sb + off);
                LDSM4(al[mt], sb + 8192 + off);
            }
            uint32_t bh[4][2], bl[4][2];
            #pragma unroll
            for (int np = 0; np < 2; np++) {
                int row = wn*32 + np*16 + lr;
                uint32_t off = row*64 + ((((kk8 + lk) ^ (row & 3))) << 4);
                uint32_t r[4];
                LDSM4(r, sb + 16384 + off);
                bh[np*2][0]=r[0]; bh[np*2+1][0]=r[1]; bh[np*2][1]=r[2]; bh[np*2+1][1]=r[3];
                LDSM4(r, sb + 24576 + off);
                bl[np*2][0]=r[0]; bl[np*2+1][0]=r[1]; bl[np*2][1]=r[2]; bl[np*2+1][1]=r[3];
            }
            #pragma unroll
            for (int mt = 0; mt < 4; mt++)
                #pragma unroll
                for (int nt = 0; nt < 4; nt++) {
                    mma_bf16(acc[mt][nt], ah[mt], bh[nt]);
                    mma_bf16(acc[mt][nt], ah[mt], bl[nt]);
                    mma_bf16(acc[mt][nt], al[mt], bh[nt]);
                }
        }
    }

    #pragma unroll
    for (int nt = 0; nt < 4; nt++) {
        int col = n0 + wn*32 + nt*8 + (lane & 3)*2;
        float bb0 = b_out[col], bb1 = b_out[col + 1];
        #pragma unroll
        for (int mt = 0; mt < 4; mt++) {
            int r0 = wm*64 + mt*16 + (lane >> 2);
            float2* p0 = reinterpret_cast<float2*>(&out[((size_t)r0*Tc + t)*Vc + col]);
            *p0 = make_float2(acc[mt][nt][0] + bb0, acc[mt][nt][1] + bb1);
            float2* p1 = reinterpret_cast<float2*>(&out[((size_t)(r0+8)*Tc + t)*Vc + col]);
            *p1 = make_float2(acc[mt][nt][2] + bb0, acc[mt][nt][3] + bb1);
        }
    }
}

// ---------------- launch ----------------------------------------------------
extern "C" void kernel_launch(void* const* d_in, const int* in_sizes, int n_in,
                              void* d_out, int out_size) {
    const int*   src   = (const int*)  d_in[0];
    const int*   trg   = (const int*)  d_in[1];
    const float* bert  = (const float*)d_in[2];
    const float* emb   = (const float*)d_in[3];
    const float* W_ih  = (const float*)d_in[4];
    const float* W_hh  = (const float*)d_in[5];
    const float* b_ih  = (const float*)d_in[6];
    const float* b_hh  = (const float*)d_in[7];
    const float* W_out = (const float*)d_in[8];
    const float* b_out = (const float*)d_in[9];
    float* out = (float*)d_out;

    cudaFuncSetAttribute(proj_mma,     cudaFuncAttributeMaxDynamicSharedMemorySize, PROJ_SMEM);
    cudaFuncSetAttribute(step_persist, cudaFuncAttributeMaxDynamicSharedMemorySize, STEP_SMEM);
    cudaFuncSetAttribute(gemm_mma,     cudaFuncAttributeMaxDynamicSharedMemorySize, GMMA_SMEM);

    // 1. gather embeddings (bf16-split xs) + init h/c + reset grid barrier
    init_kernel<<<(Tc*Bc*Hh + 255)/256, 256>>>(src, trg, bert, emb);

    // 1b. split W_out into bf16 hi/lo
    __nv_bfloat16 *wh, *wl;
    cudaGetSymbolAddress((void**)&wh, g_Wh);
    cudaGetSymbolAddress((void**)&wl, g_Wl);
    split_bf16<<<(Vc*Hh + 255)/256, 256>>>(W_out, wh, wl, Vc*Hh);

    // 1c. split (+permute) all LSTM weights + biases
    const float* Wih0 = W_ih;
    const float* Whh0 = W_hh;
    const float* Wih1 = W_ih + (size_t)G4 * Hh;
    const float* Whh1 = W_hh + (size_t)G4 * Hh;
    wsplit<<<(4*G4*Hh + 255)/256, 256>>>(Whh0, Wih1, Whh1, Wih0,
                                         b_ih, b_hh, b_ih + G4, b_hh + G4);

    // 2. hoisted layer-0 input GEMM on tensor cores (3-stage)
    gemm_mma<<<dim3(G4/128, (Tc*Bc)/128), 256, GMMA_SMEM>>>();

    // 3. persistent recurrence: ONE launch, internal grid barrier per slot
    step_persist<<<GRID_STEP, 256, STEP_SMEM>>>();

    // 4. output projection on tensor cores (bf16x2 split, 3 MMAs, 3-stage)
    proj_mma<<<dim3(Tc, Vc/128), 256, PROJ_SMEM>>>(b_out, out);
}

// round 8
// speedup vs baseline: 4.0027x; 1.2321x over previous
#include <cuda_runtime.h>
#include <cuda_fp16.h>
#include <math.h>
#include <stdint.h>

// Problem constants
#define Hh   768
#define Lc   2
#define Vc   32000
#define Bc   128
#define Tc   64
#define Sc   32
#define G4   (4*Hh)   // 3072

// ---------------- scratch (device globals; no allocations allowed) ----------
__device__ __align__(128) float g_G0[(size_t)Tc*Bc*G4]; // layer0 input gates (+biases), gate-major
__device__ __align__(128) float g_c0[Bc*Hh];
__device__ __align__(128) float g_c1[Bc*Hh];
__device__ __align__(128) float g_p1[2][Bc*G4];         // layer1 input-gate partials (permuted cols)
__device__ __align__(128) float g_bp1[G4];              // permuted (b_ih[1]+b_hh[1])
__device__ __align__(128) float g_b0[G4];               // b_ih[0]+b_hh[0] (gate-major)
__device__ unsigned g_bar;                              // grid barrier counter
// xs as fp16 hi/lo (written directly by init gather)
__device__ __align__(128) __half g_xsh[Tc*Bc*Hh];
__device__ __align__(128) __half g_xsl[Tc*Bc*Hh];
// h-state as fp16 hi/lo, ping-pong
__device__ __align__(128) __half g_h0b[2][2][Bc*Hh];
__device__ __align__(128) __half g_h1b[2][2][Bc*Hh];
// recurrence weights: [mat 0=Whh0,1=Wih1,2=Whh1][hi/lo], permuted rows p = h*4+gate
__device__ __align__(128) __half g_Wr[3][2][(size_t)G4*Hh];
// W_ih[0] split (gate-major rows, unpermuted)
__device__ __align__(128) __half g_Wi0[2][(size_t)G4*Hh];
// fp16 split buffers for tensor-core projection (W_out: hi only used by proj)
__device__ __align__(128) __half g_ysh[Tc*Bc*Hh];
__device__ __align__(128) __half g_ysl[Tc*Bc*Hh];
__device__ __align__(128) __half g_Wh[(size_t)Vc*Hh];

// ---------------- mma.sync helpers ------------------------------------------
__device__ __forceinline__ uint32_t smem_u32(const void* p) {
    uint32_t a;
    asm("{ .reg .u64 t; cvta.to.shared.u64 t, %1; cvt.u32.u64 %0, t; }" : "=r"(a) : "l"(p));
    return a;
}
#define LDSM4(r, a) \
    asm volatile("ldmatrix.sync.aligned.m8n8.x4.shared.b16 {%0,%1,%2,%3}, [%4];" \
        : "=r"((r)[0]), "=r"((r)[1]), "=r"((r)[2]), "=r"((r)[3]) : "r"(a))

__device__ __forceinline__ void mma_f16(float* c, const uint32_t* a, const uint32_t* b) {
    asm volatile("mma.sync.aligned.m16n8k16.row.col.f32.f16.f16.f32 "
        "{%0,%1,%2,%3}, {%4,%5,%6,%7}, {%8,%9}, {%0,%1,%2,%3};"
        : "+f"(c[0]), "+f"(c[1]), "+f"(c[2]), "+f"(c[3])
        : "r"(a[0]), "r"(a[1]), "r"(a[2]), "r"(a[3]), "r"(b[0]), "r"(b[1]));
}
__device__ __forceinline__ void cp16(uint32_t dst, const void* src) {       // L2-only (cg)
    asm volatile("cp.async.cg.shared.global [%0], [%1], 16;" :: "r"(dst), "l"(src));
}
__device__ __forceinline__ void cp16ca(uint32_t dst, const void* src) {     // L1-cacheable
    asm volatile("cp.async.ca.shared.global [%0], [%1], 16;" :: "r"(dst), "l"(src));
}
__device__ __forceinline__ void hf_split(float v, __half& h, __half& l) {
    h = __float2half_rz(v);
    l = __float2half_rz(v - __half2float(h));
}

// ---------------- init: gather embeddings (split), init h/c -----------------
__global__ void init_kernel(const int* __restrict__ src, const int* __restrict__ trg,
                            const float* __restrict__ bert, const float* __restrict__ emb) {
    int idx = blockIdx.x * blockDim.x + threadIdx.x;
    if (idx == 0) g_bar = 0;                       // reset grid barrier each run
    if (idx < Tc*Bc*Hh) {
        int h = idx % Hh;
        int m = idx / Hh;          // m = t*Bc + b
        int b = m % Bc;
        int t = m / Bc;
        float v = emb[(size_t)trg[b*Tc + t] * Hh + h];
        __half hh, ll;
        hf_split(v, hh, ll);
        g_xsh[idx] = hh; g_xsl[idx] = ll;
    }
    if (idx < Bc*Hh) {
        int b = idx / Hh;
        float v = bert[(size_t)src[b*Sc] * Hh + (idx % Hh)];
        __half h, l;
        hf_split(v, h, l);
        g_h0b[0][0][idx] = h; g_h0b[0][1][idx] = l;
        g_h1b[0][0][idx] = h; g_h1b[0][1][idx] = l;
        g_c0[idx] = 0.f;
        g_c1[idx] = 0.f;
    }
}

// ---------------- fp16 hi-only split for W_out -------------------------------
__global__ void split_wout(const float* __restrict__ x, __half* __restrict__ hi, int n) {
    int i = blockIdx.x * 256 + threadIdx.x;
    if (i < n) hi[i] = __float2half_rz(x[i]);
}

// ---------------- weight split(+permute) -------------------------------------
__global__ void wsplit(const float* __restrict__ Whh0, const float* __restrict__ Wih1,
                       const float* __restrict__ Whh1, const float* __restrict__ Wih0,
                       const float* __restrict__ bih0, const float* __restrict__ bhh0,
                       const float* __restrict__ bih1, const float* __restrict__ bhh1) {
    int i = blockIdx.x * 256 + threadIdx.x;
    const int per = G4 * Hh;
    if (i < 4*per) {
        int mat = i / per;
        int rem = i % per;
        int r = rem / Hh, k = rem % Hh;
        __half h, l;
        if (mat < 3) {
            const float* srcp = (mat == 0) ? Whh0 : (mat == 1 ? Wih1 : Whh1);
            hf_split(srcp[(size_t)r*Hh + k], h, l);
            int p = (r % Hh)*4 + (r / Hh);
            g_Wr[mat][0][(size_t)p*Hh + k] = h;
            g_Wr[mat][1][(size_t)p*Hh + k] = l;
        } else {
            hf_split(Wih0[(size_t)r*Hh + k], h, l);
            g_Wi0[0][(size_t)r*Hh + k] = h;
            g_Wi0[1][(size_t)r*Hh + k] = l;
        }
    }
    if (i < G4) {
        int p = (i % Hh)*4 + (i / Hh);
        g_bp1[p] = bih1[i] + bhh1[i];
        g_b0[i]  = bih0[i] + bhh0[i];
    }
}

// ---------------- mma hoisted layer0 input GEMM (fp16 3-mma) -----------------
#define GSTAGE   32768
#define GMMA_SMEM (3*GSTAGE)

__global__ void __launch_bounds__(256) gemm_mma() {
    extern __shared__ char dsm[];
    const uint32_t base = smem_u32(dsm);
    const int tid  = threadIdx.x;
    const int m0   = blockIdx.y * 128;
    const int n0   = blockIdx.x * 128;
    const int lane = tid & 31;
    const int warp = tid >> 5;
    const int wm   = warp >> 2;
    const int wn   = warp & 3;
    const int lr   = lane & 15;
    const int lk   = lane >> 4;
    const int NS   = Hh/32;

    float acc[4][4][4];
    #pragma unroll
    for (int i = 0; i < 4; i++)
        #pragma unroll
        for (int j = 0; j < 4; j++)
            #pragma unroll
            for (int r = 0; r < 4; r++) acc[i][j][r] = 0.f;

    auto load_stage = [&](int buf, int k0) {
        const uint32_t sb = base + buf*GSTAGE;
        #pragma unroll
        for (int i = 0; i < 8; i++) {
            int id  = tid + i*256;
            int arr = id >> 9;
            int w   = id & 511;
            int row = w >> 2, ch = w & 3;
            uint32_t dst = sb + arr*8192 + row*64 + ((ch ^ (row & 3)) << 4);
            const __half* src;
            if      (arr == 0) src = &g_xsh[(size_t)(m0 + row)*Hh + k0 + ch*8];
            else if (arr == 1) src = &g_xsl[(size_t)(m0 + row)*Hh + k0 + ch*8];
            else if (arr == 2) src = &g_Wi0[0][(size_t)(n0 + row)*Hh + k0 + ch*8];
            else               src = &g_Wi0[1][(size_t)(n0 + row)*Hh + k0 + ch*8];
            cp16(dst, src);
        }
        asm volatile("cp.async.commit_group;" ::: "memory");
    };

    load_stage(0, 0);
    load_stage(1, 32);

    for (int s = 0; s < NS; ++s) {
        if (s + 1 < NS) { asm volatile("cp.async.wait_group 1;" ::: "memory"); }
        else            { asm volatile("cp.async.wait_group 0;" ::: "memory"); }
        __syncthreads();
        if (s + 2 < NS) load_stage((s+2)%3, (s+2)*32);

        const uint32_t sb = base + (s%3)*GSTAGE;
        #pragma unroll
        for (int kk8 = 0; kk8 < 4; kk8 += 2) {
            uint32_t ah[4][4], al[4][4];
            #pragma unroll
            for (int mt = 0; mt < 4; mt++) {
                int row = wm*64 + mt*16 + lr;
                uint32_t off = row*64 + ((((kk8 + lk) ^ (row & 3))) << 4);
                LDSM4(ah[mt], sb + off);
                LDSM4(al[mt], sb + 8192 + off);
            }
            uint32_t bh[4][2], bl[4][2];
            #pragma unroll
            for (int np = 0; np < 2; np++) {
                int row = wn*32 + np*16 + lr;
                uint32_t off = row*64 + ((((kk8 + lk) ^ (row & 3))) << 4);
                uint32_t r[4];
                LDSM4(r, sb + 16384 + off);
                bh[np*2][0]=r[0]; bh[np*2+1][0]=r[1]; bh[np*2][1]=r[2]; bh[np*2+1][1]=r[3];
                LDSM4(r, sb + 24576 + off);
                bl[np*2][0]=r[0]; bl[np*2+1][0]=r[1]; bl[np*2][1]=r[2]; bl[np*2+1][1]=r[3];
            }
            #pragma unroll
            for (int mt = 0; mt < 4; mt++)
                #pragma unroll
                for (int nt = 0; nt < 4; nt++) {
                    mma_f16(acc[mt][nt], ah[mt], bh[nt]);
                    mma_f16(acc[mt][nt], ah[mt], bl[nt]);
                    mma_f16(acc[mt][nt], al[mt], bh[nt]);
                }
        }
    }

    #pragma unroll
    for (int nt = 0; nt < 4; nt++) {
        int col = n0 + wn*32 + nt*8 + (lane & 3)*2;
        float bb0 = g_b0[col], bb1 = g_b0[col + 1];
        #pragma unroll
        for (int mt = 0; mt < 4; mt++) {
            int r0 = m0 + wm*64 + mt*16 + (lane >> 2);
            *reinterpret_cast<float2*>(&g_G0[(size_t)r0*G4 + col]) =
                make_float2(acc[mt][nt][0] + bb0, acc[mt][nt][1] + bb1);
            *reinterpret_cast<float2*>(&g_G0[(size_t)(r0+8)*G4 + col]) =
                make_float2(acc[mt][nt][2] + bb0, acc[mt][nt][3] + bb1);
        }
    }
}

// ---------------- persistent mma recurrence (fp16 3-mma) ----------------------
#define SSTAGE 49152   // Ah 16K | Al 16K | Bh 8K | Bl 8K
#define STEP_SMEM (2*SSTAGE)
#define NSLOTS 66
#define GRID_STEP 144

__global__ __launch_bounds__(256) void step_persist() {
    extern __shared__ char dsm[];
    const uint32_t base = smem_u32(dsm);
    const int tid  = threadIdx.x;
    const int bx   = blockIdx.x;
    const int lane = tid & 31;
    const int warp = tid >> 5;
    const int wm   = warp >> 2;        // 0..1 (m 64 each)
    const int wn   = warp & 3;         // 0..3 (n 16 each)
    const int lr   = lane & 15;
    const int lk   = lane >> 4;

    int role, nb;
    const __half *Bh, *Bl;
    if (bx < 48)      { role = 0; nb = bx;      Bh = g_Wr[0][0]; Bl = g_Wr[0][1]; }
    else if (bx < 96) { role = 1; nb = bx - 48; Bh = g_Wr[1][0]; Bl = g_Wr[1][1]; }
    else              { role = 2; nb = bx - 96; Bh = g_Wr[2][0]; Bl = g_Wr[2][1]; }
    const int n0 = nb * 64;
    float* gsh = reinterpret_cast<float*>(dsm);

    for (int s = 0; s < NSLOTS; ++s) {
        bool active = (role == 0) ? (s < 64) : (role == 1) ? (s >= 1 && s <= 64) : (s >= 2);
        if (active) {
            const __half* Ah = (role == 2) ? g_h1b[s & 1][0] : g_h0b[s & 1][0];
            const __half* Al = (role == 2) ? g_h1b[s & 1][1] : g_h0b[s & 1][1];

            float acc[4][2][4];
            #pragma unroll
            for (int i = 0; i < 4; i++)
                #pragma unroll
                for (int j = 0; j < 2; j++)
                    #pragma unroll
                    for (int r = 0; r < 4; r++) acc[i][j][r] = 0.f;

            auto load_stage = [&](int buf, int k0) {
                const uint32_t sb = base + buf*SSTAGE;
                #pragma unroll
                for (int q = 0; q < 4; ++q) {            // A: cg (cross-CTA, L2-coherent)
                    int id  = tid + q*256;
                    int row = id >> 3, ch = id & 7;
                    uint32_t off = row*128 + ((ch ^ (row & 7)) << 4);
                    cp16(sb + off,         &Ah[row*Hh + k0 + ch*8]);
                    cp16(sb + 16384 + off, &Al[row*Hh + k0 + ch*8]);
                }
                #pragma unroll
                for (int q = 0; q < 2; ++q) {            // B: ca (read-only weights)
                    int id  = tid + q*256;
                    int row = id >> 3, ch = id & 7;
                    uint32_t off = row*128 + ((ch ^ (row & 7)) << 4);
                    cp16ca(sb + 32768 + off, &Bh[(size_t)(n0 + row)*Hh + k0 + ch*8]);
                    cp16ca(sb + 40960 + off, &Bl[(size_t)(n0 + row)*Hh + k0 + ch*8]);
                }
                asm volatile("cp.async.commit_group;" ::: "memory");
            };

            load_stage(0, 0);

            for (int st = 0; st < Hh/64; ++st) {
                if (st + 1 < Hh/64) {
                    load_stage((st+1) & 1, (st+1)*64);
                    asm volatile("cp.async.wait_group 1;" ::: "memory");
                } else {
                    asm volatile("cp.async.wait_group 0;" ::: "memory");
                }
                __syncthreads();

                const uint32_t sb = base + (st & 1)*SSTAGE;
                #pragma unroll
                for (int kk8 = 0; kk8 < 8; kk8 += 2) {
                    uint32_t ah[4][4], al[4][4];
                    #pragma unroll
                    for (int mt = 0; mt < 4; mt++) {
                        int row = wm*64 + mt*16 + lr;
                        uint32_t off = row*128 + ((((kk8 + lk) ^ (row & 7))) << 4);
                        LDSM4(ah[mt], sb + off);
                        LDSM4(al[mt], sb + 16384 + off);
                    }
                    uint32_t bh[2][2], bl[2][2];
                    {
                        int row = wn*16 + lr;
                        uint32_t off = row*128 + ((((kk8 + lk) ^ (row & 7))) << 4);
                        uint32_t r[4];
                        LDSM4(r, sb + 32768 + off);
                        bh[0][0]=r[0]; bh[1][0]=r[1]; bh[0][1]=r[2]; bh[1][1]=r[3];
                        LDSM4(r, sb + 40960 + off);
                        bl[0][0]=r[0]; bl[1][0]=r[1]; bl[0][1]=r[2]; bl[1][1]=r[3];
                    }
                    #pragma unroll
                    for (int mt = 0; mt < 4; mt++)
                        #pragma unroll
                        for (int nt = 0; nt < 2; nt++) {
                            mma_f16(acc[mt][nt], ah[mt], bh[nt]);
                            mma_f16(acc[mt][nt], ah[mt], bl[nt]);
                            mma_f16(acc[mt][nt], al[mt], bh[nt]);
                        }
                }
                __syncthreads();
            }

            if (role == 1) {
                float* pbuf = g_p1[(s-1) & 1];
                #pragma unroll
                for (int mt = 0; mt < 4; mt++)
                    #pragma unroll
                    for (int nt = 0; nt < 2; nt++) {
                        int r0  = wm*64 + mt*16 + (lane >> 2);
                        int col = n0 + wn*16 + nt*8 + (lane & 3)*2;
                        *reinterpret_cast<float2*>(&pbuf[(size_t)r0*G4 + col]) =
                            make_float2(acc[mt][nt][0], acc[mt][nt][1]);
                        *reinterpret_cast<float2*>(&pbuf[(size_t)(r0+8)*G4 + col]) =
                            make_float2(acc[mt][nt][2], acc[mt][nt][3]);
                    }
            } else {
                // stage gates to smem: gsh[128][68]
                #pragma unroll
                for (int mt = 0; mt < 4; mt++)
                    #pragma unroll
                    for (int nt = 0; nt < 2; nt++) {
                        int r0 = wm*64 + mt*16 + (lane >> 2);
                        int c  = wn*16 + nt*8 + (lane & 3)*2;
                        *reinterpret_cast<float2*>(&gsh[r0*68 + c]) =
                            make_float2(acc[mt][nt][0], acc[mt][nt][1]);
                        *reinterpret_cast<float2*>(&gsh[(r0+8)*68 + c]) =
                            make_float2(acc[mt][nt][2], acc[mt][nt][3]);
                    }
                __syncthreads();

                const int hg = nb * 16;
                if (role == 0) {
                    __half* Ho = g_h0b[(s & 1) ^ 1][0];
                    __half* Lo = g_h0b[(s & 1) ^ 1][1];
                    for (int e = tid; e < Bc*16; e += 256) {
                        int b = e >> 4, hl = e & 15;
                        float4 g = *reinterpret_cast<const float4*>(&gsh[b*68 + hl*4]);
                        int h = hg + hl;
                        size_t gb = ((size_t)(s*Bc + b))*G4 + h;
                        float gi = g.x + g_G0[gb];
                        float gf = g.y + g_G0[gb +   Hh];
                        float gg = g.z + g_G0[gb + 2*Hh];
                        float go = g.w + g_G0[gb + 3*Hh];
                        int ci = b*Hh + h;
                        float si = 1.f/(1.f+expf(-gi));
                        float sf = 1.f/(1.f+expf(-gf));
                        float so = 1.f/(1.f+expf(-go));
                        float cn = sf * g_c0[ci] + si * tanhf(gg);
                        float hn = so * tanhf(cn);
                        g_c0[ci] = cn;
                        __half hh, ll;
                        hf_split(hn, hh, ll);
                        Ho[ci] = hh; Lo[ci] = ll;
                    }
                } else {
                    const int u = s - 2;
                    const float* pbuf = g_p1[u & 1];
                    __half* Ho = g_h1b[(s & 1) ^ 1][0];
                    __half* Lo = g_h1b[(s & 1) ^ 1][1];
                    for (int e = tid; e < Bc*16; e += 256) {
                        int b = e >> 4, hl = e & 15;
                        float4 g = *reinterpret_cast<const float4*>(&gsh[b*68 + hl*4]);
                        int h = hg + hl;
                        float4 p  = __ldcg(reinterpret_cast<const float4*>(&pbuf[(size_t)b*G4 + h*4]));
                        float4 bb = *reinterpret_cast<const float4*>(&g_bp1[h*4]);
                        float gi = g.x + p.x + bb.x;
                        float gf = g.y + p.y + bb.y;
                        float gg = g.z + p.z + bb.z;
                        float go = g.w + p.w + bb.w;
                        int ci = b*Hh + h;
                        float si = 1.f/(1.f+expf(-gi));
                        float sf = 1.f/(1.f+expf(-gf));
                        float so = 1.f/(1.f+expf(-go));
                        float cn = sf * g_c1[ci] + si * tanhf(gg);
                        float hn = so * tanhf(cn);
                        g_c1[ci] = cn;
                        __half hh, ll;
                        hf_split(hn, hh, ll);
                        Ho[ci] = hh; Lo[ci] = ll;
                        size_t yo = ((size_t)u*Bc + b)*Hh + h;
                        g_ysh[yo] = hh; g_ysl[yo] = ll;
                    }
                }
            }
        }

        // ---- grid barrier (skip after last slot) ----
        if (s + 1 < NSLOTS) {
            __syncthreads();
            if (tid == 0) {
                unsigned* bar = &g_bar;
                asm volatile("red.release.gpu.global.add.u32 [%0], 1;" :: "l"(bar) : "memory");
                unsigned target = (unsigned)GRID_STEP * (unsigned)(s + 1);
                unsigned v;
                do {
                    asm volatile("ld.acquire.gpu.global.u32 %0, [%1];" : "=r"(v) : "l"(bar) : "memory");
                    if (v >= target) break;
                    asm volatile("nanosleep.u32 64;");
                } while (true);
            }
            __syncthreads();
        }
    }
}

// ---------------- fp16 2-mma output projection (A split, B hi only) ----------
#define PSTAGE   24576     // Ah 8K | Al 8K | Bh 8K
#define PROJ_SMEM (3*PSTAGE)

__global__ void __launch_bounds__(256) proj_mma(const float* __restrict__ b_out,
                                                float* __restrict__ out) {
    extern __shared__ char dsm[];
    const uint32_t base = smem_u32(dsm);
    const int tid  = threadIdx.x;
    const int t    = blockIdx.x;
    const int m0   = t * 128;
    const int n0   = blockIdx.y * 128;
    const int lane = tid & 31;
    const int warp = tid >> 5;
    const int wm   = warp >> 2;
    const int wn   = warp & 3;
    const int lr   = lane & 15;
    const int lk   = lane >> 4;
    const int NS   = Hh/32;

    float acc[4][4][4];
    #pragma unroll
    for (int i = 0; i < 4; i++)
        #pragma unroll
        for (int j = 0; j < 4; j++)
            #pragma unroll
            for (int r = 0; r < 4; r++) acc[i][j][r] = 0.f;

    auto load_stage = [&](int buf, int k0) {
        const uint32_t sb = base + buf*PSTAGE;
        #pragma unroll
        for (int i = 0; i < 6; i++) {
            int id  = tid + i*256;        // 0..1535
            int arr = id >> 9;            // 0..2
            int w   = id & 511;
            int row = w >> 2, ch = w & 3;
            uint32_t dst = sb + arr*8192 + row*64 + ((ch ^ (row & 3)) << 4);
            const __half* src;
            if      (arr == 0) src = &g_ysh[(size_t)(m0 + row)*Hh + k0 + ch*8];
            else if (arr == 1) src = &g_ysl[(size_t)(m0 + row)*Hh + k0 + ch*8];
            else               src = &g_Wh [(size_t)(n0 + row)*Hh + k0 + ch*8];
            cp16(dst, src);
        }
        asm volatile("cp.async.commit_group;" ::: "memory");
    };

    load_stage(0, 0);
    load_stage(1, 32);

    for (int s = 0; s < NS; ++s) {
        if (s + 1 < NS) { asm volatile("cp.async.wait_group 1;" ::: "memory"); }
        else            { asm volatile("cp.async.wait_group 0;" ::: "memory"); }
        __syncthreads();
        if (s + 2 < NS) load_stage((s+2)%3, (s+2)*32);

        const uint32_t sb = base + (s%3)*PSTAGE;
        #pragma unroll
        for (int kk8 = 0; kk8 < 4; kk8 += 2) {
            uint32_t ah[4][4], al[4][4];
            #pragma unroll
            for (int mt = 0; mt < 4; mt++) {
                int row = wm*64 + mt*16 + lr;
                uint32_t off = row*64 + ((((kk8 + lk) ^ (row & 3))) << 4);
                LDSM4(ah[mt], sb + off);
                LDSM4(al[mt], sb + 8192 + off);
            }
            uint32_t bh[4][2];
            #pragma unroll
            for (int np = 0; np < 2; np++) {
                int row = wn*32 + np*16 + lr;
                uint32_t off = row*64 + ((((kk8 + lk) ^ (row & 3))) << 4);
                uint32_t r[4];
                LDSM4(r, sb + 16384 + off);
                bh[np*2][0]=r[0]; bh[np*2+1][0]=r[1]; bh[np*2][1]=r[2]; bh[np*2+1][1]=r[3];
            }
            #pragma unroll
            for (int mt = 0; mt < 4; mt++)
                #pragma unroll
                for (int nt = 0; nt < 4; nt++) {
                    mma_f16(acc[mt][nt], ah[mt], bh[nt]);
                    mma_f16(acc[mt][nt], al[mt], bh[nt]);
                }
        }
    }

    #pragma unroll
    for (int nt = 0; nt < 4; nt++) {
        int col = n0 + wn*32 + nt*8 + (lane & 3)*2;
        float bb0 = b_out[col], bb1 = b_out[col + 1];
        #pragma unroll
        for (int mt = 0; mt < 4; mt++) {
            int r0 = wm*64 + mt*16 + (lane >> 2);
            float2* p0 = reinterpret_cast<float2*>(&out[((size_t)r0*Tc + t)*Vc + col]);
            *p0 = make_float2(acc[mt][nt][0] + bb0, acc[mt][nt][1] + bb1);
            float2* p1 = reinterpret_cast<float2*>(&out[((size_t)(r0+8)*Tc + t)*Vc + col]);
            *p1 = make_float2(acc[mt][nt][2] + bb0, acc[mt][nt][3] + bb1);
        }
    }
}

// ---------------- launch ----------------------------------------------------
extern "C" void kernel_launch(void* const* d_in, const int* in_sizes, int n_in,
                              void* d_out, int out_size) {
    const int*   src   = (const int*)  d_in[0];
    const int*   trg   = (const int*)  d_in[1];
    const float* bert  = (const float*)d_in[2];
    const float* emb   = (const float*)d_in[3];
    const float* W_ih  = (const float*)d_in[4];
    const float* W_hh  = (const float*)d_in[5];
    const float* b_ih  = (const float*)d_in[6];
    const float* b_hh  = (const float*)d_in[7];
    const float* W_out = (const float*)d_in[8];
    const float* b_out = (const float*)d_in[9];
    float* out = (float*)d_out;

    cudaFuncSetAttribute(proj_mma,     cudaFuncAttributeMaxDynamicSharedMemorySize, PROJ_SMEM);
    cudaFuncSetAttribute(step_persist, cudaFuncAttributeMaxDynamicSharedMemorySize, STEP_SMEM);
    cudaFuncSetAttribute(gemm_mma,     cudaFuncAttributeMaxDynamicSharedMemorySize, GMMA_SMEM);

    // 1. gather embeddings (fp16-split xs) + init h/c + reset grid barrier
    init_kernel<<<(Tc*Bc*Hh + 255)/256, 256>>>(src, trg, bert, emb);

    // 1b. W_out hi-only fp16
    __half* wh;
    cudaGetSymbolAddress((void**)&wh, g_Wh);
    split_wout<<<(Vc*Hh + 255)/256, 256>>>(W_out, wh, Vc*Hh);

    // 1c. split (+permute) all LSTM weights + biases (fp16 hi/lo)
    const float* Wih0 = W_ih;
    const float* Whh0 = W_hh;
    const float* Wih1 = W_ih + (size_t)G4 * Hh;
    const float* Whh1 = W_hh + (size_t)G4 * Hh;
    wsplit<<<(4*G4*Hh + 255)/256, 256>>>(Whh0, Wih1, Whh1, Wih0,
                                         b_ih, b_hh, b_ih + G4, b_hh + G4);

    // 2. hoisted layer-0 input GEMM on tensor cores (fp16 3-mma)
    gemm_mma<<<dim3(G4/128, (Tc*Bc)/128), 256, GMMA_SMEM>>>();

    // 3. persistent recurrence: ONE launch, internal grid barrier per slot
    step_persist<<<GRID_STEP, 256, STEP_SMEM>>>();

    // 4. output projection on tensor cores (fp16 2-mma)
    proj_mma<<<dim3(Tc, Vc/128), 256, PROJ_SMEM>>>(b_out, out);
}

// round 9
// speedup vs baseline: 4.2464x; 1.0609x over previous
#include <cuda_runtime.h>
#include <cuda_fp16.h>
#include <math.h>
#include <stdint.h>

// Problem constants
#define Hh   768
#define Lc   2
#define Vc   32000
#define Bc   128
#define Tc   64
#define Sc   32
#define G4   (4*Hh)   // 3072

// ---------------- scratch (device globals; no allocations allowed) ----------
__device__ __align__(128) float g_G0[(size_t)Tc*Bc*G4]; // layer0 input gates (+biases), gate-major
__device__ __align__(128) float g_c0[Bc*Hh];
__device__ __align__(128) float g_c1[Bc*Hh];
__device__ __align__(128) float g_p1[2][Bc*G4];         // layer1 input-gate partials (permuted cols)
__device__ __align__(128) float g_bp1[G4];              // permuted (b_ih[1]+b_hh[1])
__device__ __align__(128) float g_b0[G4];               // b_ih[0]+b_hh[0] (gate-major)
__device__ unsigned g_bar;                              // grid barrier counter
// xs as fp16 hi/lo (written directly by init gather)
__device__ __align__(128) __half g_xsh[Tc*Bc*Hh];
__device__ __align__(128) __half g_xsl[Tc*Bc*Hh];
// h-state as fp16 hi/lo, ping-pong
__device__ __align__(128) __half g_h0b[2][2][Bc*Hh];
__device__ __align__(128) __half g_h1b[2][2][Bc*Hh];
// recurrence weights: [mat 0=Whh0,1=Wih1,2=Whh1][hi/lo], permuted rows p = h*4+gate
__device__ __align__(128) __half g_Wr[3][2][(size_t)G4*Hh];
// W_ih[0] split (gate-major rows, unpermuted)
__device__ __align__(128) __half g_Wi0[2][(size_t)G4*Hh];
// fp16 split buffers for tensor-core projection (W_out: hi only used by proj)
__device__ __align__(128) __half g_ysh[Tc*Bc*Hh];
__device__ __align__(128) __half g_ysl[Tc*Bc*Hh];
__device__ __align__(128) __half g_Wh[(size_t)Vc*Hh];

// ---------------- mma.sync helpers ------------------------------------------
__device__ __forceinline__ uint32_t smem_u32(const void* p) {
    uint32_t a;
    asm("{ .reg .u64 t; cvta.to.shared.u64 t, %1; cvt.u32.u64 %0, t; }" : "=r"(a) : "l"(p));
    return a;
}
#define LDSM4(r, a) \
    asm volatile("ldmatrix.sync.aligned.m8n8.x4.shared.b16 {%0,%1,%2,%3}, [%4];" \
        : "=r"((r)[0]), "=r"((r)[1]), "=r"((r)[2]), "=r"((r)[3]) : "r"(a))

__device__ __forceinline__ void mma_f16(float* c, const uint32_t* a, const uint32_t* b) {
    asm volatile("mma.sync.aligned.m16n8k16.row.col.f32.f16.f16.f32 "
        "{%0,%1,%2,%3}, {%4,%5,%6,%7}, {%8,%9}, {%0,%1,%2,%3};"
        : "+f"(c[0]), "+f"(c[1]), "+f"(c[2]), "+f"(c[3])
        : "r"(a[0]), "r"(a[1]), "r"(a[2]), "r"(a[3]), "r"(b[0]), "r"(b[1]));
}
__device__ __forceinline__ void cp16(uint32_t dst, const void* src) {       // L2-only (cg)
    asm volatile("cp.async.cg.shared.global [%0], [%1], 16;" :: "r"(dst), "l"(src));
}
__device__ __forceinline__ void cp16ca(uint32_t dst, const void* src) {     // L1-cacheable
    asm volatile("cp.async.ca.shared.global [%0], [%1], 16;" :: "r"(dst), "l"(src));
}
__device__ __forceinline__ void hf_split(float v, __half& h, __half& l) {
    h = __float2half_rz(v);
    l = __float2half_rz(v - __half2float(h));
}

// ---------------- init: gather embeddings (split), init h/c -----------------
__global__ void init_kernel(const int* __restrict__ src, const int* __restrict__ trg,
                            const float* __restrict__ bert, const float* __restrict__ emb) {
    int idx = blockIdx.x * blockDim.x + threadIdx.x;
    if (idx == 0) g_bar = 0;                       // reset grid barrier each run
    if (idx < Tc*Bc*Hh) {
        int h = idx % Hh;
        int m = idx / Hh;          // m = t*Bc + b
        int b = m % Bc;
        int t = m / Bc;
        float v = emb[(size_t)trg[b*Tc + t] * Hh + h];
        __half hh, ll;
        hf_split(v, hh, ll);
        g_xsh[idx] = hh; g_xsl[idx] = ll;
    }
    if (idx < Bc*Hh) {
        int b = idx / Hh;
        float v = bert[(size_t)src[b*Sc] * Hh + (idx % Hh)];
        __half h, l;
        hf_split(v, h, l);
        g_h0b[0][0][idx] = h; g_h0b[0][1][idx] = l;
        g_h1b[0][0][idx] = h; g_h1b[0][1][idx] = l;
        g_c0[idx] = 0.f;
        g_c1[idx] = 0.f;
    }
}

// ---------------- fp16 hi-only split for W_out -------------------------------
__global__ void split_wout(const float* __restrict__ x, __half* __restrict__ hi, int n) {
    int i = blockIdx.x * 256 + threadIdx.x;
    if (i < n) hi[i] = __float2half_rz(x[i]);
}

// ---------------- weight split(+permute) -------------------------------------
__global__ void wsplit(const float* __restrict__ Whh0, const float* __restrict__ Wih1,
                       const float* __restrict__ Whh1, const float* __restrict__ Wih0,
                       const float* __restrict__ bih0, const float* __restrict__ bhh0,
                       const float* __restrict__ bih1, const float* __restrict__ bhh1) {
    int i = blockIdx.x * 256 + threadIdx.x;
    const int per = G4 * Hh;
    if (i < 4*per) {
        int mat = i / per;
        int rem = i % per;
        int r = rem / Hh, k = rem % Hh;
        __half h, l;
        if (mat < 3) {
            const float* srcp = (mat == 0) ? Whh0 : (mat == 1 ? Wih1 : Whh1);
            hf_split(srcp[(size_t)r*Hh + k], h, l);
            int p = (r % Hh)*4 + (r / Hh);
            g_Wr[mat][0][(size_t)p*Hh + k] = h;
            g_Wr[mat][1][(size_t)p*Hh + k] = l;
        } else {
            hf_split(Wih0[(size_t)r*Hh + k], h, l);
            g_Wi0[0][(size_t)r*Hh + k] = h;
            g_Wi0[1][(size_t)r*Hh + k] = l;
        }
    }
    if (i < G4) {
        int p = (i % Hh)*4 + (i / Hh);
        g_bp1[p] = bih1[i] + bhh1[i];
        g_b0[i]  = bih0[i] + bhh0[i];
    }
}

// ---------------- mma hoisted layer0 input GEMM (fp16 3-mma) -----------------
#define GSTAGE   32768
#define GMMA_SMEM (3*GSTAGE)

__global__ void __launch_bounds__(256) gemm_mma() {
    extern __shared__ char dsm[];
    const uint32_t base = smem_u32(dsm);
    const int tid  = threadIdx.x;
    const int m0   = blockIdx.y * 128;
    const int n0   = blockIdx.x * 128;
    const int lane = tid & 31;
    const int warp = tid >> 5;
    const int wm   = warp >> 2;
    const int wn   = warp & 3;
    const int lr   = lane & 15;
    const int lk   = lane >> 4;
    const int NS   = Hh/32;

    float acc[4][4][4];
    #pragma unroll
    for (int i = 0; i < 4; i++)
        #pragma unroll
        for (int j = 0; j < 4; j++)
            #pragma unroll
            for (int r = 0; r < 4; r++) acc[i][j][r] = 0.f;

    auto load_stage = [&](int buf, int k0) {
        const uint32_t sb = base + buf*GSTAGE;
        #pragma unroll
        for (int i = 0; i < 8; i++) {
            int id  = tid + i*256;
            int arr = id >> 9;
            int w   = id & 511;
            int row = w >> 2, ch = w & 3;
            uint32_t dst = sb + arr*8192 + row*64 + ((ch ^ (row & 3)) << 4);
            const __half* src;
            if      (arr == 0) src = &g_xsh[(size_t)(m0 + row)*Hh + k0 + ch*8];
            else if (arr == 1) src = &g_xsl[(size_t)(m0 + row)*Hh + k0 + ch*8];
            else if (arr == 2) src = &g_Wi0[0][(size_t)(n0 + row)*Hh + k0 + ch*8];
            else               src = &g_Wi0[1][(size_t)(n0 + row)*Hh + k0 + ch*8];
            cp16(dst, src);
        }
        asm volatile("cp.async.commit_group;" ::: "memory");
    };

    load_stage(0, 0);
    load_stage(1, 32);

    for (int s = 0; s < NS; ++s) {
        if (s + 1 < NS) { asm volatile("cp.async.wait_group 1;" ::: "memory"); }
        else            { asm volatile("cp.async.wait_group 0;" ::: "memory"); }
        __syncthreads();
        if (s + 2 < NS) load_stage((s+2)%3, (s+2)*32);

        const uint32_t sb = base + (s%3)*GSTAGE;
        #pragma unroll
        for (int kk8 = 0; kk8 < 4; kk8 += 2) {
            uint32_t ah[4][4], al[4][4];
            #pragma unroll
            for (int mt = 0; mt < 4; mt++) {
                int row = wm*64 + mt*16 + lr;
                uint32_t off = row*64 + ((((kk8 + lk) ^ (row & 3))) << 4);
                LDSM4(ah[mt], sb + off);
                LDSM4(al[mt], sb + 8192 + off);
            }
            uint32_t bh[4][2], bl[4][2];
            #pragma unroll
            for (int np = 0; np < 2; np++) {
                int row = wn*32 + np*16 + lr;
                uint32_t off = row*64 + ((((kk8 + lk) ^ (row & 3))) << 4);
                uint32_t r[4];
                LDSM4(r, sb + 16384 + off);
                bh[np*2][0]=r[0]; bh[np*2+1][0]=r[1]; bh[np*2][1]=r[2]; bh[np*2+1][1]=r[3];
                LDSM4(r, sb + 24576 + off);
                bl[np*2][0]=r[0]; bl[np*2+1][0]=r[1]; bl[np*2][1]=r[2]; bl[np*2+1][1]=r[3];
            }
            #pragma unroll
            for (int mt = 0; mt < 4; mt++)
                #pragma unroll
                for (int nt = 0; nt < 4; nt++) {
                    mma_f16(acc[mt][nt], ah[mt], bh[nt]);
                    mma_f16(acc[mt][nt], ah[mt], bl[nt]);
                    mma_f16(acc[mt][nt], al[mt], bh[nt]);
                }
        }
    }

    #pragma unroll
    for (int nt = 0; nt < 4; nt++) {
        int col = n0 + wn*32 + nt*8 + (lane & 3)*2;
        float bb0 = g_b0[col], bb1 = g_b0[col + 1];
        #pragma unroll
        for (int mt = 0; mt < 4; mt++) {
            int r0 = m0 + wm*64 + mt*16 + (lane >> 2);
            *reinterpret_cast<float2*>(&g_G0[(size_t)r0*G4 + col]) =
                make_float2(acc[mt][nt][0] + bb0, acc[mt][nt][1] + bb1);
            *reinterpret_cast<float2*>(&g_G0[(size_t)(r0+8)*G4 + col]) =
                make_float2(acc[mt][nt][2] + bb0, acc[mt][nt][3] + bb1);
        }
    }
}

// ---------------- persistent mma recurrence (fp16 3-mma, 2 CTAs/SM) ----------
// ONE launch, 288 CTAs (2 per SM), 66 slots, gpu-scope grid barrier per slot.
// Each CTA: M=64 (batch half) x N=64 (16 h-quads) x K=768.
//   bx   0.. 95: role0 layer0 gates  (B = permWhh0, A = h0b[s&1])   s in [0,63]
//   bx  96..191: role1 layer1 input  (B = permWih1, A = h0b[s&1])   s in [1,64] -> g_p1[(s-1)&1]
//   bx 192..287: role2 layer1 gates  (B = permWhh1, A = h1b[s&1])   s in [2,65], u = s-2
//   within role: nb = (bx - roleBase) >> 1 (n-tile), mh = bx & 1 (batch half)
#define SSTAGE 32768   // Ah 8K | Al 8K | Bh 8K | Bl 8K
#define STEP_SMEM (2*SSTAGE)
#define NSLOTS 66
#define GRID_STEP 288

__global__ void __launch_bounds__(256, 2) step_persist() {
    extern __shared__ char dsm[];
    const uint32_t base = smem_u32(dsm);
    const int tid  = threadIdx.x;
    const int bx   = blockIdx.x;
    const int lane = tid & 31;
    const int warp = tid >> 5;
    const int wm   = warp >> 2;        // 0..1 (m 32 each)
    const int wn   = warp & 3;         // 0..3 (n 16 each)
    const int lr   = lane & 15;
    const int lk   = lane >> 4;

    int role, nb, mh;
    const __half *Bh, *Bl;
    if (bx < 96)       { role = 0; nb = bx >> 1;        Bh = g_Wr[0][0]; Bl = g_Wr[0][1]; }
    else if (bx < 192) { role = 1; nb = (bx - 96) >> 1; Bh = g_Wr[1][0]; Bl = g_Wr[1][1]; }
    else               { role = 2; nb = (bx - 192) >> 1; Bh = g_Wr[2][0]; Bl = g_Wr[2][1]; }
    mh = bx & 1;
    const int n0  = nb * 64;
    const int am0 = mh * 64;           // batch-half row offset
    float* gsh = reinterpret_cast<float*>(dsm);   // [64][68] epilogue staging

    for (int s = 0; s < NSLOTS; ++s) {
        bool active = (role == 0) ? (s < 64) : (role == 1) ? (s >= 1 && s <= 64) : (s >= 2);
        if (active) {
            const __half* Ah = (role == 2) ? g_h1b[s & 1][0] : g_h0b[s & 1][0];
            const __half* Al = (role == 2) ? g_h1b[s & 1][1] : g_h0b[s & 1][1];

            float acc[2][2][4];
            #pragma unroll
            for (int i = 0; i < 2; i++)
                #pragma unroll
                for (int j = 0; j < 2; j++)
                    #pragma unroll
                    for (int r = 0; r < 4; r++) acc[i][j][r] = 0.f;

            auto load_stage = [&](int buf, int k0) {
                const uint32_t sb = base + buf*SSTAGE;
                #pragma unroll
                for (int q = 0; q < 2; ++q) {            // 64 rows x 8 chunks each matrix
                    int id  = tid + q*256;
                    int row = id >> 3, ch = id & 7;
                    uint32_t off = row*128 + ((ch ^ (row & 7)) << 4);
                    cp16(sb + off,          &Ah[(size_t)(am0 + row)*Hh + k0 + ch*8]);
                    cp16(sb + 8192  + off,  &Al[(size_t)(am0 + row)*Hh + k0 + ch*8]);
                    cp16ca(sb + 16384 + off, &Bh[(size_t)(n0 + row)*Hh + k0 + ch*8]);
                    cp16ca(sb + 24576 + off, &Bl[(size_t)(n0 + row)*Hh + k0 + ch*8]);
                }
                asm volatile("cp.async.commit_group;" ::: "memory");
            };

            load_stage(0, 0);

            for (int st = 0; st < Hh/64; ++st) {
                if (st + 1 < Hh/64) {
                    load_stage((st+1) & 1, (st+1)*64);
                    asm volatile("cp.async.wait_group 1;" ::: "memory");
                } else {
                    asm volatile("cp.async.wait_group 0;" ::: "memory");
                }
                __syncthreads();

                const uint32_t sb = base + (st & 1)*SSTAGE;
                #pragma unroll
                for (int kk8 = 0; kk8 < 8; kk8 += 2) {
                    uint32_t ah[2][4], al[2][4];
                    #pragma unroll
                    for (int mt = 0; mt < 2; mt++) {
                        int row = wm*32 + mt*16 + lr;
                        uint32_t off = row*128 + ((((kk8 + lk) ^ (row & 7))) << 4);
                        LDSM4(ah[mt], sb + off);
                        LDSM4(al[mt], sb + 8192 + off);
                    }
                    uint32_t bh[2][2], bl[2][2];
                    {
                        int row = wn*16 + lr;
                        uint32_t off = row*128 + ((((kk8 + lk) ^ (row & 7))) << 4);
                        uint32_t r[4];
                        LDSM4(r, sb + 16384 + off);
                        bh[0][0]=r[0]; bh[1][0]=r[1]; bh[0][1]=r[2]; bh[1][1]=r[3];
                        LDSM4(r, sb + 24576 + off);
                        bl[0][0]=r[0]; bl[1][0]=r[1]; bl[0][1]=r[2]; bl[1][1]=r[3];
                    }
                    #pragma unroll
                    for (int mt = 0; mt < 2; mt++)
                        #pragma unroll
                        for (int nt = 0; nt < 2; nt++) {
                            mma_f16(acc[mt][nt], ah[mt], bh[nt]);
                            mma_f16(acc[mt][nt], ah[mt], bl[nt]);
                            mma_f16(acc[mt][nt], al[mt], bh[nt]);
                        }
                }
                __syncthreads();
            }

            if (role == 1) {
                float* pbuf = g_p1[(s-1) & 1];
                #pragma unroll
                for (int mt = 0; mt < 2; mt++)
                    #pragma unroll
                    for (int nt = 0; nt < 2; nt++) {
                        int r0  = am0 + wm*32 + mt*16 + (lane >> 2);
                        int col = n0 + wn*16 + nt*8 + (lane & 3)*2;
                        *reinterpret_cast<float2*>(&pbuf[(size_t)r0*G4 + col]) =
                            make_float2(acc[mt][nt][0], acc[mt][nt][1]);
                        *reinterpret_cast<float2*>(&pbuf[(size_t)(r0+8)*G4 + col]) =
                            make_float2(acc[mt][nt][2], acc[mt][nt][3]);
                    }
            } else {
                // stage gates to smem: gsh[64][68]
                #pragma unroll
                for (int mt = 0; mt < 2; mt++)
                    #pragma unroll
                    for (int nt = 0; nt < 2; nt++) {
                        int r0 = wm*32 + mt*16 + (lane >> 2);
                        int c  = wn*16 + nt*8 + (lane & 3)*2;
                        *reinterpret_cast<float2*>(&gsh[r0*68 + c]) =
                            make_float2(acc[mt][nt][0], acc[mt][nt][1]);
                        *reinterpret_cast<float2*>(&gsh[(r0+8)*68 + c]) =
                            make_float2(acc[mt][nt][2], acc[mt][nt][3]);
                    }
                __syncthreads();

                const int hg = nb * 16;
                if (role == 0) {
                    __half* Ho = g_h0b[(s & 1) ^ 1][0];
                    __half* Lo = g_h0b[(s & 1) ^ 1][1];
                    for (int e = tid; e < 64*16; e += 256) {
                        int br = e >> 4, hl = e & 15;
                        int b = am0 + br;
                        float4 g = *reinterpret_cast<const float4*>(&gsh[br*68 + hl*4]);
                        int h = hg + hl;
                        size_t gb = ((size_t)(s*Bc + b))*G4 + h;
                        float gi = g.x + g_G0[gb];
                        float gf = g.y + g_G0[gb +   Hh];
                        float gg = g.z + g_G0[gb + 2*Hh];
                        float go = g.w + g_G0[gb + 3*Hh];
                        int ci = b*Hh + h;
                        float si = 1.f/(1.f+expf(-gi));
                        float sf = 1.f/(1.f+expf(-gf));
                        float so = 1.f/(1.f+expf(-go));
                        float cn = sf * g_c0[ci] + si * tanhf(gg);
                        float hn = so * tanhf(cn);
                        g_c0[ci] = cn;
                        __half hh, ll;
                        hf_split(hn, hh, ll);
                        Ho[ci] = hh; Lo[ci] = ll;
                    }
                } else {
                    const int u = s - 2;
                    const float* pbuf = g_p1[u & 1];
                    __half* Ho = g_h1b[(s & 1) ^ 1][0];
                    __half* Lo = g_h1b[(s & 1) ^ 1][1];
                    for (int e = tid; e < 64*16; e += 256) {
                        int br = e >> 4, hl = e & 15;
                        int b = am0 + br;
                        float4 g = *reinterpret_cast<const float4*>(&gsh[br*68 + hl*4]);
                        int h = hg + hl;
                        float4 p  = __ldcg(reinterpret_cast<const float4*>(&pbuf[(size_t)b*G4 + h*4]));
                        float4 bb = *reinterpret_cast<const float4*>(&g_bp1[h*4]);
                        float gi = g.x + p.x + bb.x;
                        float gf = g.y + p.y + bb.y;
                        float gg = g.z + p.z + bb.z;
                        float go = g.w + p.w + bb.w;
                        int ci = b*Hh + h;
                        float si = 1.f/(1.f+expf(-gi));
                        float sf = 1.f/(1.f+expf(-gf));
                        float so = 1.f/(1.f+expf(-go));
                        float cn = sf * g_c1[ci] + si * tanhf(gg);
                        float hn = so * tanhf(cn);
                        g_c1[ci] = cn;
                        __half hh, ll;
                        hf_split(hn, hh, ll);
                        Ho[ci] = hh; Lo[ci] = ll;
                        size_t yo = ((size_t)u*Bc + b)*Hh + h;
                        g_ysh[yo] = hh; g_ysl[yo] = ll;
                    }
                }
            }
        }

        // ---- grid barrier (skip after last slot) ----
        if (s + 1 < NSLOTS) {
            __syncthreads();
            if (tid == 0) {
                unsigned* bar = &g_bar;
                asm volatile("red.release.gpu.global.add.u32 [%0], 1;" :: "l"(bar) : "memory");
                unsigned target = (unsigned)GRID_STEP * (unsigned)(s + 1);
                unsigned v;
                do {
                    asm volatile("ld.acquire.gpu.global.u32 %0, [%1];" : "=r"(v) : "l"(bar) : "memory");
                    if (v >= target) break;
                    asm volatile("nanosleep.u32 64;");
                } while (true);
            }
            __syncthreads();
        }
    }
}

// ---------------- fp16 2-mma output projection (A split, B hi only) ----------
#define PSTAGE   24576     // Ah 8K | Al 8K | Bh 8K
#define PROJ_SMEM (3*PSTAGE)

__global__ void __launch_bounds__(256) proj_mma(const float* __restrict__ b_out,
                                                float* __restrict__ out) {
    extern __shared__ char dsm[];
    const uint32_t base = smem_u32(dsm);
    const int tid  = threadIdx.x;
    const int t    = blockIdx.x;
    const int m0   = t * 128;
    const int n0   = blockIdx.y * 128;
    const int lane = tid & 31;
    const int warp = tid >> 5;
    const int wm   = warp >> 2;
    const int wn   = warp & 3;
    const int lr   = lane & 15;
    const int lk   = lane >> 4;
    const int NS   = Hh/32;

    float acc[4][4][4];
    #pragma unroll
    for (int i = 0; i < 4; i++)
        #pragma unroll
        for (int j = 0; j < 4; j++)
            #pragma unroll
            for (int r = 0; r < 4; r++) acc[i][j][r] = 0.f;

    auto load_stage = [&](int buf, int k0) {
        const uint32_t sb = base + buf*PSTAGE;
        #pragma unroll
        for (int i = 0; i < 6; i++) {
            int id  = tid + i*256;        // 0..1535
            int arr = id >> 9;            // 0..2
            int w   = id & 511;
            int row = w >> 2, ch = w & 3;
            uint32_t dst = sb + arr*8192 + row*64 + ((ch ^ (row & 3)) << 4);
            const __half* src;
            if      (arr == 0) src = &g_ysh[(size_t)(m0 + row)*Hh + k0 + ch*8];
            else if (arr == 1) src = &g_ysl[(size_t)(m0 + row)*Hh + k0 + ch*8];
            else               src = &g_Wh [(size_t)(n0 + row)*Hh + k0 + ch*8];
            cp16(dst, src);
        }
        asm volatile("cp.async.commit_group;" ::: "memory");
    };

    load_stage(0, 0);
    load_stage(1, 32);

    for (int s = 0; s < NS; ++s) {
        if (s + 1 < NS) { asm volatile("cp.async.wait_group 1;" ::: "memory"); }
        else            { asm volatile("cp.async.wait_group 0;" ::: "memory"); }
        __syncthreads();
        if (s + 2 < NS) load_stage((s+2)%3, (s+2)*32);

        const uint32_t sb = base + (s%3)*PSTAGE;
        #pragma unroll
        for (int kk8 = 0; kk8 < 4; kk8 += 2) {
            uint32_t ah[4][4], al[4][4];
            #pragma unroll
            for (int mt = 0; mt < 4; mt++) {
                int row = wm*64 + mt*16 + lr;
                uint32_t off = row*64 + ((((kk8 + lk) ^ (row & 3))) << 4);
                LDSM4(ah[mt], sb + off);
                LDSM4(al[mt], sb + 8192 + off);
            }
            uint32_t bh[4][2];
            #pragma unroll
            for (int np = 0; np < 2; np++) {
                int row = wn*32 + np*16 + lr;
                uint32_t off = row*64 + ((((kk8 + lk) ^ (row & 3))) << 4);
                uint32_t r[4];
                LDSM4(r, sb + 16384 + off);
                bh[np*2][0]=r[0]; bh[np*2+1][0]=r[1]; bh[np*2][1]=r[2]; bh[np*2+1][1]=r[3];
            }
            #pragma unroll
            for (int mt = 0; mt < 4; mt++)
                #pragma unroll
                for (int nt = 0; nt < 4; nt++) {
                    mma_f16(acc[mt][nt], ah[mt], bh[nt]);
                    mma_f16(acc[mt][nt], al[mt], bh[nt]);
                }
        }
    }

    #pragma unroll
    for (int nt = 0; nt < 4; nt++) {
        int col = n0 + wn*32 + nt*8 + (lane & 3)*2;
        float bb0 = b_out[col], bb1 = b_out[col + 1];
        #pragma unroll
        for (int mt = 0; mt < 4; mt++) {
            int r0 = wm*64 + mt*16 + (lane >> 2);
            float2* p0 = reinterpret_cast<float2*>(&out[((size_t)r0*Tc + t)*Vc + col]);
            *p0 = make_float2(acc[mt][nt][0] + bb0, acc[mt][nt][1] + bb1);
            float2* p1 = reinterpret_cast<float2*>(&out[((size_t)(r0+8)*Tc + t)*Vc + col]);
            *p1 = make_float2(acc[mt][nt][2] + bb0, acc[mt][nt][3] + bb1);
        }
    }
}

// ---------------- launch ----------------------------------------------------
extern "C" void kernel_launch(void* const* d_in, const int* in_sizes, int n_in,
                              void* d_out, int out_size) {
    const int*   src   = (const int*)  d_in[0];
    const int*   trg   = (const int*)  d_in[1];
    const float* bert  = (const float*)d_in[2];
    const float* emb   = (const float*)d_in[3];
    const float* W_ih  = (const float*)d_in[4];
    const float* W_hh  = (const float*)d_in[5];
    const float* b_ih  = (const float*)d_in[6];
    const float* b_hh  = (const float*)d_in[7];
    const float* W_out = (const float*)d_in[8];
    const float* b_out = (const float*)d_in[9];
    float* out = (float*)d_out;

    cudaFuncSetAttribute(proj_mma,     cudaFuncAttributeMaxDynamicSharedMemorySize, PROJ_SMEM);
    cudaFuncSetAttribute(step_persist, cudaFuncAttributeMaxDynamicSharedMemorySize, STEP_SMEM);
    cudaFuncSetAttribute(gemm_mma,     cudaFuncAttributeMaxDynamicSharedMemorySize, GMMA_SMEM);

    // 1. gather embeddings (fp16-split xs) + init h/c + reset grid barrier
    init_kernel<<<(Tc*Bc*Hh + 255)/256, 256>>>(src, trg, bert, emb);

    // 1b. W_out hi-only fp16
    __half* wh;
    cudaGetSymbolAddress((void**)&wh, g_Wh);
    split_wout<<<(Vc*Hh + 255)/256, 256>>>(W_out, wh, Vc*Hh);

    // 1c. split (+permute) all LSTM weights + biases (fp16 hi/lo)
    const float* Wih0 = W_ih;
    const float* Whh0 = W_hh;
    const float* Wih1 = W_ih + (size_t)G4 * Hh;
    const float* Whh1 = W_hh + (size_t)G4 * Hh;
    wsplit<<<(4*G4*Hh + 255)/256, 256>>>(Whh0, Wih1, Whh1, Wih0,
                                         b_ih, b_hh, b_ih + G4, b_hh + G4);

    // 2. hoisted layer-0 input GEMM on tensor cores (fp16 3-mma)
    gemm_mma<<<dim3(G4/128, (Tc*Bc)/128), 256, GMMA_SMEM>>>();

    // 3. persistent recurrence: ONE launch, 288 CTAs (2/SM), grid barrier per slot
    step_persist<<<GRID_STEP, 256, STEP_SMEM>>>();

    // 4. output projection on tensor cores (fp16 2-mma)
    proj_mma<<<dim3(Tc, Vc/128), 256, PROJ_SMEM>>>(b_out, out);
}

// round 10
// speedup vs baseline: 4.4907x; 1.0575x over previous
#include <cuda_runtime.h>
#include <cuda_fp16.h>
#include <math.h>
#include <stdint.h>

// Problem constants
#define Hh   768
#define Lc   2
#define Vc   32000
#define Bc   128
#define Tc   64
#define Sc   32
#define G4   (4*Hh)   // 3072

// ---------------- scratch (device globals; no allocations allowed) ----------
__device__ __align__(128) float g_G0[(size_t)Tc*Bc*G4]; // layer0 input gates (+biases), gate-major
__device__ __align__(128) float g_c0[Bc*Hh];
__device__ __align__(128) float g_c1[Bc*Hh];
__device__ __align__(128) float g_p1[2][Bc*G4];         // layer1 input-gate partials (permuted cols)
__device__ __align__(128) float g_bp1[G4];              // permuted (b_ih[1]+b_hh[1])
__device__ __align__(128) float g_b0[G4];               // b_ih[0]+b_hh[0] (gate-major)
__device__ unsigned g_bar;                              // grid barrier counter
// xs as fp16 hi/lo (written directly by init gather)
__device__ __align__(128) __half g_xsh[Tc*Bc*Hh];
__device__ __align__(128) __half g_xsl[Tc*Bc*Hh];
// h-state as fp16 hi/lo, ping-pong
__device__ __align__(128) __half g_h0b[2][2][Bc*Hh];
__device__ __align__(128) __half g_h1b[2][2][Bc*Hh];
// recurrence weights: [mat 0=Whh0,1=Wih1,2=Whh1][hi/lo], permuted rows p = h*4+gate
__device__ __align__(128) __half g_Wr[3][2][(size_t)G4*Hh];
// W_ih[0] split (gate-major rows, unpermuted)
__device__ __align__(128) __half g_Wi0[2][(size_t)G4*Hh];
// fp16 split buffers for tensor-core projection (W_out: hi only used by proj)
__device__ __align__(128) __half g_ysh[Tc*Bc*Hh];
__device__ __align__(128) __half g_ysl[Tc*Bc*Hh];
__device__ __align__(128) __half g_Wh[(size_t)Vc*Hh];

// ---------------- mma.sync helpers ------------------------------------------
__device__ __forceinline__ uint32_t smem_u32(const void* p) {
    uint32_t a;
    asm("{ .reg .u64 t; cvta.to.shared.u64 t, %1; cvt.u32.u64 %0, t; }" : "=r"(a) : "l"(p));
    return a;
}
#define LDSM4(r, a) \
    asm volatile("ldmatrix.sync.aligned.m8n8.x4.shared.b16 {%0,%1,%2,%3}, [%4];" \
        : "=r"((r)[0]), "=r"((r)[1]), "=r"((r)[2]), "=r"((r)[3]) : "r"(a))

__device__ __forceinline__ void mma_f16(float* c, const uint32_t* a, const uint32_t* b) {
    asm volatile("mma.sync.aligned.m16n8k16.row.col.f32.f16.f16.f32 "
        "{%0,%1,%2,%3}, {%4,%5,%6,%7}, {%8,%9}, {%0,%1,%2,%3};"
        : "+f"(c[0]), "+f"(c[1]), "+f"(c[2]), "+f"(c[3])
        : "r"(a[0]), "r"(a[1]), "r"(a[2]), "r"(a[3]), "r"(b[0]), "r"(b[1]));
}
__device__ __forceinline__ void cp16(uint32_t dst, const void* src) {       // L2-only (cg)
    asm volatile("cp.async.cg.shared.global [%0], [%1], 16;" :: "r"(dst), "l"(src));
}
__device__ __forceinline__ void cp16ca(uint32_t dst, const void* src) {     // L1-cacheable
    asm volatile("cp.async.ca.shared.global [%0], [%1], 16;" :: "r"(dst), "l"(src));
}
__device__ __forceinline__ void hf_split(float v, __half& h, __half& l) {
    h = __float2half_rz(v);
    l = __float2half_rz(v - __half2float(h));
}

// ---------------- init: gather embeddings (split), init h/c -----------------
__global__ void init_kernel(const int* __restrict__ src, const int* __restrict__ trg,
                            const float* __restrict__ bert, const float* __restrict__ emb) {
    int idx = blockIdx.x * blockDim.x + threadIdx.x;
    if (idx == 0) g_bar = 0;                       // reset grid barrier each run
    if (idx < Tc*Bc*Hh) {
        int h = idx % Hh;
        int m = idx / Hh;          // m = t*Bc + b
        int b = m % Bc;
        int t = m / Bc;
        float v = emb[(size_t)trg[b*Tc + t] * Hh + h];
        __half hh, ll;
        hf_split(v, hh, ll);
        g_xsh[idx] = hh; g_xsl[idx] = ll;
    }
    if (idx < Bc*Hh) {
        int b = idx / Hh;
        float v = bert[(size_t)src[b*Sc] * Hh + (idx % Hh)];
        __half h, l;
        hf_split(v, h, l);
        g_h0b[0][0][idx] = h; g_h0b[0][1][idx] = l;
        g_h1b[0][0][idx] = h; g_h1b[0][1][idx] = l;
        g_c0[idx] = 0.f;
        g_c1[idx] = 0.f;
    }
}

// ---------------- fp16 hi-only split for W_out -------------------------------
__global__ void split_wout(const float* __restrict__ x, __half* __restrict__ hi, int n) {
    int i = blockIdx.x * 256 + threadIdx.x;
    if (i < n) hi[i] = __float2half_rz(x[i]);
}

// ---------------- weight split(+permute) -------------------------------------
__global__ void wsplit(const float* __restrict__ Whh0, const float* __restrict__ Wih1,
                       const float* __restrict__ Whh1, const float* __restrict__ Wih0,
                       const float* __restrict__ bih0, const float* __restrict__ bhh0,
                       const float* __restrict__ bih1, const float* __restrict__ bhh1) {
    int i = blockIdx.x * 256 + threadIdx.x;
    const int per = G4 * Hh;
    if (i < 4*per) {
        int mat = i / per;
        int rem = i % per;
        int r = rem / Hh, k = rem % Hh;
        __half h, l;
        if (mat < 3) {
            const float* srcp = (mat == 0) ? Whh0 : (mat == 1 ? Wih1 : Whh1);
            hf_split(srcp[(size_t)r*Hh + k], h, l);
            int p = (r % Hh)*4 + (r / Hh);
            g_Wr[mat][0][(size_t)p*Hh + k] = h;
            g_Wr[mat][1][(size_t)p*Hh + k] = l;
        } else {
            hf_split(Wih0[(size_t)r*Hh + k], h, l);
            g_Wi0[0][(size_t)r*Hh + k] = h;
            g_Wi0[1][(size_t)r*Hh + k] = l;
        }
    }
    if (i < G4) {
        int p = (i % Hh)*4 + (i / Hh);
        g_bp1[p] = bih1[i] + bhh1[i];
        g_b0[i]  = bih0[i] + bhh0[i];
    }
}

// ---------------- mma hoisted layer0 input GEMM (fp16 3-mma, unchanged) ------
#define GSTAGE   32768
#define GMMA_SMEM (3*GSTAGE)

__global__ void __launch_bounds__(256) gemm_mma() {
    extern __shared__ char dsm[];
    const uint32_t base = smem_u32(dsm);
    const int tid  = threadIdx.x;
    const int m0   = blockIdx.y * 128;
    const int n0   = blockIdx.x * 128;
    const int lane = tid & 31;
    const int warp = tid >> 5;
    const int wm   = warp >> 2;
    const int wn   = warp & 3;
    const int lr   = lane & 15;
    const int lk   = lane >> 4;
    const int NS   = Hh/32;

    float acc[4][4][4];
    #pragma unroll
    for (int i = 0; i < 4; i++)
        #pragma unroll
        for (int j = 0; j < 4; j++)
            #pragma unroll
            for (int r = 0; r < 4; r++) acc[i][j][r] = 0.f;

    auto load_stage = [&](int buf, int k0) {
        const uint32_t sb = base + buf*GSTAGE;
        #pragma unroll
        for (int i = 0; i < 8; i++) {
            int id  = tid + i*256;
            int arr = id >> 9;
            int w   = id & 511;
            int row = w >> 2, ch = w & 3;
            uint32_t dst = sb + arr*8192 + row*64 + ((ch ^ (row & 3)) << 4);
            const __half* src;
            if      (arr == 0) src = &g_xsh[(size_t)(m0 + row)*Hh + k0 + ch*8];
            else if (arr == 1) src = &g_xsl[(size_t)(m0 + row)*Hh + k0 + ch*8];
            else if (arr == 2) src = &g_Wi0[0][(size_t)(n0 + row)*Hh + k0 + ch*8];
            else               src = &g_Wi0[1][(size_t)(n0 + row)*Hh + k0 + ch*8];
            cp16(dst, src);
        }
        asm volatile("cp.async.commit_group;" ::: "memory");
    };

    load_stage(0, 0);
    load_stage(1, 32);

    for (int s = 0; s < NS; ++s) {
        if (s + 1 < NS) { asm volatile("cp.async.wait_group 1;" ::: "memory"); }
        else            { asm volatile("cp.async.wait_group 0;" ::: "memory"); }
        __syncthreads();
        if (s + 2 < NS) load_stage((s+2)%3, (s+2)*32);

        const uint32_t sb = base + (s%3)*GSTAGE;
        #pragma unroll
        for (int kk8 = 0; kk8 < 4; kk8 += 2) {
            uint32_t ah[4][4], al[4][4];
            #pragma unroll
            for (int mt = 0; mt < 4; mt++) {
                int row = wm*64 + mt*16 + lr;
                uint32_t off = row*64 + ((((kk8 + lk) ^ (row & 3))) << 4);
                LDSM4(ah[mt], sb + off);
                LDSM4(al[mt], sb + 8192 + off);
            }
            uint32_t bh[4][2], bl[4][2];
            #pragma unroll
            for (int np = 0; np < 2; np++) {
                int row = wn*32 + np*16 + lr;
                uint32_t off = row*64 + ((((kk8 + lk) ^ (row & 3))) << 4);
                uint32_t r[4];
                LDSM4(r, sb + 16384 + off);
                bh[np*2][0]=r[0]; bh[np*2+1][0]=r[1]; bh[np*2][1]=r[2]; bh[np*2+1][1]=r[3];
                LDSM4(r, sb + 24576 + off);
                bl[np*2][0]=r[0]; bl[np*2+1][0]=r[1]; bl[np*2][1]=r[2]; bl[np*2+1][1]=r[3];
            }
            #pragma unroll
            for (int mt = 0; mt < 4; mt++)
                #pragma unroll
                for (int nt = 0; nt < 4; nt++) {
                    mma_f16(acc[mt][nt], ah[mt], bh[nt]);
                    mma_f16(acc[mt][nt], ah[mt], bl[nt]);
                    mma_f16(acc[mt][nt], al[mt], bh[nt]);
                }
        }
    }

    #pragma unroll
    for (int nt = 0; nt < 4; nt++) {
        int col = n0 + wn*32 + nt*8 + (lane & 3)*2;
        float bb0 = g_b0[col], bb1 = g_b0[col + 1];
        #pragma unroll
        for (int mt = 0; mt < 4; mt++) {
            int r0 = m0 + wm*64 + mt*16 + (lane >> 2);
            *reinterpret_cast<float2*>(&g_G0[(size_t)r0*G4 + col]) =
                make_float2(acc[mt][nt][0] + bb0, acc[mt][nt][1] + bb1);
            *reinterpret_cast<float2*>(&g_G0[(size_t)(r0+8)*G4 + col]) =
                make_float2(acc[mt][nt][2] + bb0, acc[mt][nt][3] + bb1);
        }
    }
}

// ---------------- persistent mma recurrence (fp16 3-mma, 2 CTAs/SM) ----------
// 288 CTAs, 66 slots. 3-stage one-sync k-loop; B tile prefetched before barrier.
#define SSTAGE 32768   // Ah 8K | Al 8K | Bh 8K | Bl 8K
#define STEP_SMEM (3*SSTAGE)
#define NSLOTS 66
#define GRID_STEP 288
#define SNK (Hh/64)    // 12 k-chunks

__global__ void __launch_bounds__(256, 2) step_persist() {
    extern __shared__ char dsm[];
    const uint32_t base = smem_u32(dsm);
    const int tid  = threadIdx.x;
    const int bx   = blockIdx.x;
    const int lane = tid & 31;
    const int warp = tid >> 5;
    const int wm   = warp >> 2;        // 0..1 (m 32 each)
    const int wn   = warp & 3;         // 0..3 (n 16 each)
    const int lr   = lane & 15;
    const int lk   = lane >> 4;

    int role, nb, mh;
    const __half *Bh, *Bl;
    if (bx < 96)       { role = 0; nb = bx >> 1;         Bh = g_Wr[0][0]; Bl = g_Wr[0][1]; }
    else if (bx < 192) { role = 1; nb = (bx - 96) >> 1;  Bh = g_Wr[1][0]; Bl = g_Wr[1][1]; }
    else               { role = 2; nb = (bx - 192) >> 1; Bh = g_Wr[2][0]; Bl = g_Wr[2][1]; }
    mh = bx & 1;
    const int n0  = nb * 64;
    const int am0 = mh * 64;           // batch-half row offset
    // epilogue staging lives in buffer 1 (disjoint from buffer-0 B prefetch region)
    float* gsh = reinterpret_cast<float*>(dsm + SSTAGE);   // [64][68]

    // prefetch this CTA's B tile, chunk 0, into buffer 0 (uncommitted)
    auto prefetch_B0 = [&]() {
        #pragma unroll
        for (int q = 0; q < 2; ++q) {
            int id  = tid + q*256;
            int row = id >> 3, ch = id & 7;
            uint32_t off = row*128 + ((ch ^ (row & 7)) << 4);
            cp16ca(base + 16384 + off, &Bh[(size_t)(n0 + row)*Hh + ch*8]);
            cp16ca(base + 24576 + off, &Bl[(size_t)(n0 + row)*Hh + ch*8]);
        }
    };

    if (role == 0) prefetch_B0();      // only role0 is active at slot 0

    for (int s = 0; s < NSLOTS; ++s) {
        bool active = (role == 0) ? (s < 64) : (role == 1) ? (s >= 1 && s <= 64) : (s >= 2);
        if (active) {
            const __half* Ah = (role == 2) ? g_h1b[s & 1][0] : g_h0b[s & 1][0];
            const __half* Al = (role == 2) ? g_h1b[s & 1][1] : g_h0b[s & 1][1];

            float acc[2][2][4];
            #pragma unroll
            for (int i = 0; i < 2; i++)
                #pragma unroll
                for (int j = 0; j < 2; j++)
                    #pragma unroll
                    for (int r = 0; r < 4; r++) acc[i][j][r] = 0.f;

            auto load_full = [&](int buf, int k0) {
                const uint32_t sb = base + buf*SSTAGE;
                #pragma unroll
                for (int q = 0; q < 2; ++q) {
                    int id  = tid + q*256;
                    int row = id >> 3, ch = id & 7;
                    uint32_t off = row*128 + ((ch ^ (row & 7)) << 4);
                    cp16(sb + off,           &Ah[(size_t)(am0 + row)*Hh + k0 + ch*8]);
                    cp16(sb + 8192  + off,   &Al[(size_t)(am0 + row)*Hh + k0 + ch*8]);
                    cp16ca(sb + 16384 + off, &Bh[(size_t)(n0 + row)*Hh + k0 + ch*8]);
                    cp16ca(sb + 24576 + off, &Bl[(size_t)(n0 + row)*Hh + k0 + ch*8]);
                }
                asm volatile("cp.async.commit_group;" ::: "memory");
            };

            // stage 0: A only (B was prefetched); commit closes B too
            {
                #pragma unroll
                for (int q = 0; q < 2; ++q) {
                    int id  = tid + q*256;
                    int row = id >> 3, ch = id & 7;
                    uint32_t off = row*128 + ((ch ^ (row & 7)) << 4);
                    cp16(base + off,          &Ah[(size_t)(am0 + row)*Hh + ch*8]);
                    cp16(base + 8192  + off,  &Al[(size_t)(am0 + row)*Hh + ch*8]);
                }
                asm volatile("cp.async.commit_group;" ::: "memory");
            }
            load_full(1, 64);

            for (int st = 0; st < SNK; ++st) {
                if (st == SNK-1) { asm volatile("cp.async.wait_group 0;" ::: "memory"); }
                else             { asm volatile("cp.async.wait_group 1;" ::: "memory"); }
                __syncthreads();
                if (st + 2 < SNK) load_full((st+2)%3, (st+2)*64);

                const uint32_t sb = base + (st%3)*SSTAGE;
                #pragma unroll
                for (int kk8 = 0; kk8 < 8; kk8 += 2) {
                    uint32_t ah[2][4], al[2][4];
                    #pragma unroll
                    for (int mt = 0; mt < 2; mt++) {
                        int row = wm*32 + mt*16 + lr;
                        uint32_t off = row*128 + ((((kk8 + lk) ^ (row & 7))) << 4);
                        LDSM4(ah[mt], sb + off);
                        LDSM4(al[mt], sb + 8192 + off);
                    }
                    uint32_t bh[2][2], bl[2][2];
                    {
                        int row = wn*16 + lr;
                        uint32_t off = row*128 + ((((kk8 + lk) ^ (row & 7))) << 4);
                        uint32_t r[4];
                        LDSM4(r, sb + 16384 + off);
                        bh[0][0]=r[0]; bh[1][0]=r[1]; bh[0][1]=r[2]; bh[1][1]=r[3];
                        LDSM4(r, sb + 24576 + off);
                        bl[0][0]=r[0]; bl[1][0]=r[1]; bl[0][1]=r[2]; bl[1][1]=r[3];
                    }
                    #pragma unroll
                    for (int mt = 0; mt < 2; mt++)
                        #pragma unroll
                        for (int nt = 0; nt < 2; nt++) {
                            mma_f16(acc[mt][nt], ah[mt], bh[nt]);
                            mma_f16(acc[mt][nt], ah[mt], bl[nt]);
                            mma_f16(acc[mt][nt], al[mt], bh[nt]);
                        }
                }
            }
            __syncthreads();     // all warps past the k-loop (smem stages free)

            if (role == 1) {
                float* pbuf = g_p1[(s-1) & 1];
                #pragma unroll
                for (int mt = 0; mt < 2; mt++)
                    #pragma unroll
                    for (int nt = 0; nt < 2; nt++) {
                        int r0  = am0 + wm*32 + mt*16 + (lane >> 2);
                        int col = n0 + wn*16 + nt*8 + (lane & 3)*2;
                        *reinterpret_cast<float2*>(&pbuf[(size_t)r0*G4 + col]) =
                            make_float2(acc[mt][nt][0], acc[mt][nt][1]);
                        *reinterpret_cast<float2*>(&pbuf[(size_t)(r0+8)*G4 + col]) =
                            make_float2(acc[mt][nt][2], acc[mt][nt][3]);
                    }
            } else {
                // stage gates to smem (buffer 1): gsh[64][68]
                #pragma unroll
                for (int mt = 0; mt < 2; mt++)
                    #pragma unroll
                    for (int nt = 0; nt < 2; nt++) {
                        int r0 = wm*32 + mt*16 + (lane >> 2);
                        int c  = wn*16 + nt*8 + (lane & 3)*2;
                        *reinterpret_cast<float2*>(&gsh[r0*68 + c]) =
                            make_float2(acc[mt][nt][0], acc[mt][nt][1]);
                        *reinterpret_cast<float2*>(&gsh[(r0+8)*68 + c]) =
                            make_float2(acc[mt][nt][2], acc[mt][nt][3]);
                    }
                __syncthreads();

                const int hg = nb * 16;
                if (role == 0) {
                    __half* Ho = g_h0b[(s & 1) ^ 1][0];
                    __half* Lo = g_h0b[(s & 1) ^ 1][1];
                    for (int e = tid; e < 64*16; e += 256) {
                        int br = e >> 4, hl = e & 15;
                        int b = am0 + br;
                        float4 g = *reinterpret_cast<const float4*>(&gsh[br*68 + hl*4]);
                        int h = hg + hl;
                        size_t gb = ((size_t)(s*Bc + b))*G4 + h;
                        float gi = g.x + g_G0[gb];
                        float gf = g.y + g_G0[gb +   Hh];
                        float gg = g.z + g_G0[gb + 2*Hh];
                        float go = g.w + g_G0[gb + 3*Hh];
                        int ci = b*Hh + h;
                        float si = 1.f/(1.f+expf(-gi));
                        float sf = 1.f/(1.f+expf(-gf));
                        float so = 1.f/(1.f+expf(-go));
                        float cn = sf * g_c0[ci] + si * tanhf(gg);
                        float hn = so * tanhf(cn);
                        g_c0[ci] = cn;
                        __half hh, ll;
                        hf_split(hn, hh, ll);
                        Ho[ci] = hh; Lo[ci] = ll;
                    }
                } else {
                    const int u = s - 2;
                    const float* pbuf = g_p1[u & 1];
                    __half* Ho = g_h1b[(s & 1) ^ 1][0];
                    __half* Lo = g_h1b[(s & 1) ^ 1][1];
                    for (int e = tid; e < 64*16; e += 256) {
                        int br = e >> 4, hl = e & 15;
                        int b = am0 + br;
                        float4 g = *reinterpret_cast<const float4*>(&gsh[br*68 + hl*4]);
                        int h = hg + hl;
                        float4 p  = __ldcg(reinterpret_cast<const float4*>(&pbuf[(size_t)b*G4 + h*4]));
                        float4 bb = *reinterpret_cast<const float4*>(&g_bp1[h*4]);
                        float gi = g.x + p.x + bb.x;
                        float gf = g.y + p.y + bb.y;
                        float gg = g.z + p.z + bb.z;
                        float go = g.w + p.w + bb.w;
                        int ci = b*Hh + h;
                        float si = 1.f/(1.f+expf(-gi));
                        float sf = 1.f/(1.f+expf(-gf));
                        float so = 1.f/(1.f+expf(-go));
                        float cn = sf * g_c1[ci] + si * tanhf(gg);
                        float hn = so * tanhf(cn);
                        g_c1[ci] = cn;
                        __half hh, ll;
                        hf_split(hn, hh, ll);
                        Ho[ci] = hh; Lo[ci] = ll;
                        size_t yo = ((size_t)u*Bc + b)*Hh + h;
                        g_ysh[yo] = hh; g_ysl[yo] = ll;
                    }
                }
            }
        }

        // ---- prefetch next slot's B (barrier-independent), then grid barrier ----
        if (s + 1 < NSLOTS) {
            bool active_next = (role == 0) ? (s+1 < 64)
                             : (role == 1) ? (s+1 >= 1 && s+1 <= 64)
                             : (s+1 >= 2);
            if (active) __syncthreads();   // ensure no warp still reads smem stages
            if (active_next) prefetch_B0();
            __syncthreads();
            if (tid == 0) {
                unsigned* bar = &g_bar;
                asm volatile("red.release.gpu.global.add.u32 [%0], 1;" :: "l"(bar) : "memory");
                unsigned target = (unsigned)GRID_STEP * (unsigned)(s + 1);
                unsigned v;
                do {
                    asm volatile("ld.acquire.gpu.global.u32 %0, [%1];" : "=r"(v) : "l"(bar) : "memory");
                    if (v >= target) break;
                    asm volatile("nanosleep.u32 64;");
                } while (true);
            }
            __syncthreads();
        }
    }
}

// ---------------- fp16 2-mma output projection (k-chunk 64, 2 stages) --------
#define PSTAGE   49152     // Ah 16K | Al 16K | Bh 16K
#define PROJ_SMEM (2*PSTAGE)
#define PNK (Hh/64)        // 12 k-chunks

__global__ void __launch_bounds__(256) proj_mma(const float* __restrict__ b_out,
                                                float* __restrict__ out) {
    extern __shared__ char dsm[];
    const uint32_t base = smem_u32(dsm);
    const int tid  = threadIdx.x;
    const int t    = blockIdx.x;
    const int m0   = t * 128;
    const int n0   = blockIdx.y * 128;
    const int lane = tid & 31;
    const int warp = tid >> 5;
    const int wm   = warp >> 2;
    const int wn   = warp & 3;
    const int lr   = lane & 15;
    const int lk   = lane >> 4;

    float acc[4][4][4];
    #pragma unroll
    for (int i = 0; i < 4; i++)
        #pragma unroll
        for (int j = 0; j < 4; j++)
            #pragma unroll
            for (int r = 0; r < 4; r++) acc[i][j][r] = 0.f;

    auto load_stage = [&](int buf, int k0) {
        const uint32_t sb = base + buf*PSTAGE;
        #pragma unroll
        for (int i = 0; i < 12; i++) {
            int id  = tid + i*256;        // 0..3071
            int arr = id >> 10;           // 0..2
            int w   = id & 1023;
            int row = w >> 3, ch = w & 7;
            uint32_t dst = sb + arr*16384 + row*128 + ((ch ^ (row & 7)) << 4);
            const __half* src;
            if      (arr == 0) src = &g_ysh[(size_t)(m0 + row)*Hh + k0 + ch*8];
            else if (arr == 1) src = &g_ysl[(size_t)(m0 + row)*Hh + k0 + ch*8];
            else               src = &g_Wh [(size_t)(n0 + row)*Hh + k0 + ch*8];
            cp16(dst, src);
        }
        asm volatile("cp.async.commit_group;" ::: "memory");
    };

    load_stage(0, 0);

    for (int s = 0; s < PNK; ++s) {
        asm volatile("cp.async.wait_group 0;" ::: "memory");
        __syncthreads();
        if (s + 1 < PNK) load_stage((s+1) & 1, (s+1)*64);

        const uint32_t sb = base + (s & 1)*PSTAGE;
        #pragma unroll
        for (int kk8 = 0; kk8 < 8; kk8 += 2) {
            uint32_t ah[4][4], al[4][4];
            #pragma unroll
            for (int mt = 0; mt < 4; mt++) {
                int row = wm*64 + mt*16 + lr;
                uint32_t off = row*128 + ((((kk8 + lk) ^ (row & 7))) << 4);
                LDSM4(ah[mt], sb + off);
                LDSM4(al[mt], sb + 16384 + off);
            }
            uint32_t bh[4][2];
            #pragma unroll
            for (int np = 0; np < 2; np++) {
                int row = wn*32 + np*16 + lr;
                uint32_t off = row*128 + ((((kk8 + lk) ^ (row & 7))) << 4);
                uint32_t r[4];
                LDSM4(r, sb + 32768 + off);
                bh[np*2][0]=r[0]; bh[np*2+1][0]=r[1]; bh[np*2][1]=r[2]; bh[np*2+1][1]=r[3];
            }
            #pragma unroll
            for (int mt = 0; mt < 4; mt++)
                #pragma unroll
                for (int nt = 0; nt < 4; nt++) {
                    mma_f16(acc[mt][nt], ah[mt], bh[nt]);
                    mma_f16(acc[mt][nt], al[mt], bh[nt]);
                }
        }
    }

    #pragma unroll
    for (int nt = 0; nt < 4; nt++) {
        int col = n0 + wn*32 + nt*8 + (lane & 3)*2;
        float bb0 = b_out[col], bb1 = b_out[col + 1];
        #pragma unroll
        for (int mt = 0; mt < 4; mt++) {
            int r0 = wm*64 + mt*16 + (lane >> 2);
            float2* p0 = reinterpret_cast<float2*>(&out[((size_t)r0*Tc + t)*Vc + col]);
            *p0 = make_float2(acc[mt][nt][0] + bb0, acc[mt][nt][1] + bb1);
            float2* p1 = reinterpret_cast<float2*>(&out[((size_t)(r0+8)*Tc + t)*Vc + col]);
            *p1 = make_float2(acc[mt][nt][2] + bb0, acc[mt][nt][3] + bb1);
        }
    }
}

// ---------------- launch ----------------------------------------------------
extern "C" void kernel_launch(void* const* d_in, const int* in_sizes, int n_in,
                              void* d_out, int out_size) {
    const int*   src   = (const int*)  d_in[0];
    const int*   trg   = (const int*)  d_in[1];
    const float* bert  = (const float*)d_in[2];
    const float* emb   = (const float*)d_in[3];
    const float* W_ih  = (const float*)d_in[4];
    const float* W_hh  = (const float*)d_in[5];
    const float* b_ih  = (const float*)d_in[6];
    const float* b_hh  = (const float*)d_in[7];
    const float* W_out = (const float*)d_in[8];
    const float* b_out = (const float*)d_in[9];
    float* out = (float*)d_out;

    cudaFuncSetAttribute(proj_mma,     cudaFuncAttributeMaxDynamicSharedMemorySize, PROJ_SMEM);
    cudaFuncSetAttribute(step_persist, cudaFuncAttributeMaxDynamicSharedMemorySize, STEP_SMEM);
    cudaFuncSetAttribute(gemm_mma,     cudaFuncAttributeMaxDynamicSharedMemorySize, GMMA_SMEM);

    // 1. gather embeddings (fp16-split xs) + init h/c + reset grid barrier
    init_kernel<<<(Tc*Bc*Hh + 255)/256, 256>>>(src, trg, bert, emb);

    // 1b. W_out hi-only fp16
    __half* wh;
    cudaGetSymbolAddress((void**)&wh, g_Wh);
    split_wout<<<(Vc*Hh + 255)/256, 256>>>(W_out, wh, Vc*Hh);

    // 1c. split (+permute) all LSTM weights + biases (fp16 hi/lo)
    const float* Wih0 = W_ih;
    const float* Whh0 = W_hh;
    const float* Wih1 = W_ih + (size_t)G4 * Hh;
    const float* Whh1 = W_hh + (size_t)G4 * Hh;
    wsplit<<<(4*G4*Hh + 255)/256, 256>>>(Whh0, Wih1, Whh1, Wih0,
                                         b_ih, b_hh, b_ih + G4, b_hh + G4);

    // 2. hoisted layer-0 input GEMM on tensor cores (fp16 3-mma)
    gemm_mma<<<dim3(G4/128, (Tc*Bc)/128), 256, GMMA_SMEM>>>();

    // 3. persistent recurrence: ONE launch, 288 CTAs (2/SM), grid barrier per slot
    step_persist<<<GRID_STEP, 256, STEP_SMEM>>>();

    // 4. output projection on tensor cores (fp16 2-mma, k-chunk 64)
    proj_mma<<<dim3(Tc, Vc/128), 256, PROJ_SMEM>>>(b_out, out);
}